// round 3
// baseline (speedup 1.0000x reference)
#include <cuda_runtime.h>
#include <cuda_bf16.h>
#include <cstdint>

#define V_  262144
#define E_  524288
#define NG  8192
#define H_  128

// ---------------- tcgen05 feature gate ---------------------------------------------
// tcgen05 is arch-SPECIFIC (sm_103a). The harness also builds family-level
// compute_103 PTX, where tcgen05 is illegal. Gate on the feature macros; the
// non-feature pass gets a correct naive fallback (never executed on device,
// since the fatbin carries sm_103a SASS).
#if defined(__CUDA_ARCH_FEAT_SM103_ALL) || defined(__CUDA_ARCH_FEAT_SM100_ALL) || defined(__CUDA_ARCH_FEAT_SM101_ALL)
#define HAS_TC 1
#endif
#if !defined(HAS_TC) && defined(__CUDA_ARCH_HAS_FEATURE__)
#if __CUDA_ARCH_HAS_FEATURE__(SM103_ALL)
#define HAS_TC 1
#endif
#endif
#ifndef HAS_TC
#define HAS_TC 0
#endif

// ---------------- scratch globals ------------------------------------------------
__device__ float    g_x[(size_t)V_ * H_];
__device__ float    g_e[(size_t)E_ * H_];
__device__ float    g_agg[(size_t)V_ * H_];   // stays zero between launches
__device__ float    g_h[(size_t)V_ * H_];
__device__ float    g_logit[V_];
__device__ unsigned g_menc[NG];
__device__ float    g_den[NG];
// transposed + tf32-split weights: emb(128x384) | W1[4](128x128) | W2[4](128x128) | mlp1(128x192)
#define WT_TOTAL 204800
__device__ float    g_wthi[WT_TOTAL];
__device__ float    g_wtlo[WT_TOTAL];

// ---------------- PTX helpers -----------------------------------------------------
__device__ __forceinline__ uint32_t smem_u32(const void* p) {
    uint32_t a;
    asm("{ .reg .u64 t; cvta.to.shared.u64 t, %1; cvt.u32.u64 %0, t; }" : "=r"(a) : "l"(p));
    return a;
}
__device__ __forceinline__ uint32_t f2tf32(float v) {
    uint32_t r; asm("cvt.rna.tf32.f32 %0, %1;" : "=r"(r) : "f"(v)); return r;
}
__device__ __forceinline__ void mbar_init(uint32_t mbar, uint32_t cnt) {
    asm volatile("mbarrier.init.shared.b64 [%0], %1;" :: "r"(mbar), "r"(cnt) : "memory");
}
__device__ __forceinline__ void mbar_wait(uint32_t mbar, uint32_t parity) {
    asm volatile(
        "{\n\t.reg .pred P;\n\tWL_%=:\n\t"
        "mbarrier.try_wait.parity.acquire.cta.shared::cta.b64 P, [%0], %1, 0x989680;\n\t"
        "@!P bra WL_%=;\n\t}" :: "r"(mbar), "r"(parity) : "memory");
}
__device__ __forceinline__ void fence_async_shared() {
    asm volatile("fence.proxy.async.shared::cta;" ::: "memory");
}

#if HAS_TC
__device__ __forceinline__ void mma_tf32(uint32_t d, uint64_t a, uint64_t b,
                                         uint32_t idesc, int acc) {
    asm volatile(
        "{\n\t.reg .pred p;\n\tsetp.ne.b32 p, %4, 0;\n\t"
        "tcgen05.mma.cta_group::1.kind::tf32 [%0], %1, %2, %3, p;\n\t}"
        :: "r"(d), "l"(a), "l"(b), "r"(idesc), "r"(acc) : "memory");
}
__device__ __forceinline__ void tc_commit(uint32_t mbar) {
    asm volatile(
        "tcgen05.commit.cta_group::1.mbarrier::arrive::one.shared::cluster.b64 [%0];"
        :: "r"(mbar) : "memory");
}
__device__ __forceinline__ void tc_alloc(uint32_t smem_dst, uint32_t ncols) {
    asm volatile("tcgen05.alloc.cta_group::1.sync.aligned.shared::cta.b32 [%0], %1;"
                 :: "r"(smem_dst), "r"(ncols) : "memory");
}
__device__ __forceinline__ void tc_dealloc(uint32_t tmem, uint32_t ncols) {
    asm volatile("tcgen05.dealloc.cta_group::1.sync.aligned.b32 %0, %1;"
                 :: "r"(tmem), "r"(ncols));
}
__device__ __forceinline__ void tc_relinquish() {
    asm volatile("tcgen05.relinquish_alloc_permit.cta_group::1.sync.aligned;");
}
__device__ __forceinline__ void tc_fence_after() {
    asm volatile("tcgen05.fence::after_thread_sync;" ::: "memory");
}
__device__ __forceinline__ void tc_wait_ld() {
    asm volatile("tcgen05.wait::ld.sync.aligned;" ::: "memory");
}
__device__ __forceinline__ void ldtm32(uint32_t* r, uint32_t addr) {
    asm volatile(
        "tcgen05.ld.sync.aligned.32x32b.x32.b32 "
        "{%0, %1, %2, %3, %4, %5, %6, %7, %8, %9, %10, %11, %12, %13, %14, %15, "
        " %16, %17, %18, %19, %20, %21, %22, %23, %24, %25, %26, %27, %28, %29, %30, %31}, [%32];"
        : "=r"(r[0]), "=r"(r[1]), "=r"(r[2]), "=r"(r[3]), "=r"(r[4]), "=r"(r[5]),
          "=r"(r[6]), "=r"(r[7]), "=r"(r[8]), "=r"(r[9]), "=r"(r[10]), "=r"(r[11]),
          "=r"(r[12]), "=r"(r[13]), "=r"(r[14]), "=r"(r[15]), "=r"(r[16]), "=r"(r[17]),
          "=r"(r[18]), "=r"(r[19]), "=r"(r[20]), "=r"(r[21]), "=r"(r[22]), "=r"(r[23]),
          "=r"(r[24]), "=r"(r[25]), "=r"(r[26]), "=r"(r[27]), "=r"(r[28]), "=r"(r[29]),
          "=r"(r[30]), "=r"(r[31])
        : "r"(addr));
}
#endif  // HAS_TC

__device__ __forceinline__ unsigned encf(float f) {
    unsigned u = __float_as_uint(f);
    return (u & 0x80000000u) ? ~u : (u | 0x80000000u);
}
__device__ __forceinline__ float decf(unsigned u) {
    return (u & 0x80000000u) ? __uint_as_float(u & 0x7fffffffu) : __uint_as_float(~u);
}

// SMEM descriptor base: SW128, version=1, SBO=64 (1024B 8-row-group stride), LBO=1
static __device__ __forceinline__ uint64_t make_desc(uint32_t addr) {
    const uint64_t base =
        (uint64_t(2) << 61) | (uint64_t(1) << 46) | (uint64_t(64) << 32) | (uint64_t(1) << 16);
    return base | ((uint64_t)(addr >> 4) & 0x3FFF);
}

// idesc: cF32(1<<4) | aTF32(2<<7) | bTF32(2<<10) | N=128 (16<<17) | M=128 (8<<24)
#define IDESC_TF32 0x08200910u

// ---------------- weight transpose + tf32 split ----------------------------------
__global__ void split_w_k(const float* __restrict__ We, const float* __restrict__ W1,
                          const float* __restrict__ W2, const float* __restrict__ Wm)
{
    int i = blockIdx.x * 256 + threadIdx.x;
    if (i >= WT_TOTAL) return;
    float v;
    if (i < 49152) {                       // emb: (n,k) n<128, k<384, src W[k*128+n]
        int n = i / 384, k = i % 384;
        v = We[k * 128 + n];
    } else if (i < 114688) {               // W1 layers
        int j = i - 49152; int l = j >> 14; int q = j & 16383;
        int n = q >> 7, k = q & 127;
        v = W1[l * 16384 + k * 128 + n];
    } else if (i < 180224) {               // W2 layers
        int j = i - 114688; int l = j >> 14; int q = j & 16383;
        int n = q >> 7, k = q & 127;
        v = W2[l * 16384 + k * 128 + n];
    } else {                               // mlp1: k<192
        int j = i - 180224; int n = j / 192, k = j % 192;
        v = Wm[k * 128 + n];
    }
    uint32_t h = f2tf32(v);
    float lo = v - __uint_as_float(h);
    g_wthi[i] = __uint_as_float(h);
    g_wtlo[i] = __uint_as_float(f2tf32(lo));
}

// ---------------- edge embedding -------------------------------------------------
__global__ __launch_bounds__(128) void edge_embed_k(
    const float* __restrict__ attr, const float* __restrict__ Wedge,
    const float* __restrict__ bedge)
{
    __shared__ float Ws[16 * 128];
    __shared__ float Ae[128 * 16];
    __shared__ float bs[128];
    const int tid = threadIdx.x;
    const int e0 = blockIdx.x * 128;
    for (int i = tid; i < 16 * 128; i += 128) Ws[i] = Wedge[i];
    bs[tid] = bedge[tid];
    for (int i = tid; i < 128 * 16; i += 128) Ae[i] = attr[(size_t)e0 * 16 + i];
    __syncthreads();
    for (int ee = 0; ee < 128; ee++) {
        float s = bs[tid];
        #pragma unroll
        for (int k = 0; k < 16; k++) s = fmaf(Ae[ee * 16 + k], Ws[k * 128 + tid], s);
        g_e[(size_t)(e0 + ee) * 128 + tid] = fmaxf(s, 0.f);
    }
}

// ---------------- scatter --------------------------------------------------------
__global__ __launch_bounds__(256) void scatter_k(
    const int* __restrict__ src, const int* __restrict__ dst)
{
    const int warp = (blockIdx.x * blockDim.x + threadIdx.x) >> 5;
    const int lane = threadIdx.x & 31;
    if (warp >= E_) return;
    const int s = src[warp];
    const int d = dst[warp];
    float4 xv = *(const float4*)(g_x + (size_t)s * 128 + lane * 4);
    float4 ev = *(const float4*)(g_e + (size_t)warp * 128 + lane * 4);
    float4 m;
    m.x = fmaxf(xv.x + ev.x, 0.f);
    m.y = fmaxf(xv.y + ev.y, 0.f);
    m.z = fmaxf(xv.z + ev.z, 0.f);
    m.w = fmaxf(xv.w + ev.w, 0.f);
    atomicAdd((float4*)(g_agg + (size_t)d * 128 + lane * 4), m);
}

// ---------------- tcgen05 tf32 GEMM (3xTF32 split) --------------------------------
// MODE 0 (EMB):  A = [x_upd | Zc[g] | Zb[g]], out = relu -> g_x
// MODE 1 (L1):   A = g_x + g_agg (zeroes g_agg), out = relu -> g_h
// MODE 2 (L2):   A = g_h, g_x += relu(acc + b)
// MODE 3 (HEAD): A = [g_x | x_inp], relu, dot w2 -> g_logit
#define OFF_AHI 1024
#define OFF_ALO (1024 + 16384)
#define OFF_BHI (1024 + 32768)
#define OFF_BLO (1024 + 49152)
#define SMEM_BYTES (1024 + 65536)

template <int K, int MODE>
__global__ __launch_bounds__(128) void tc_gemm_k(
    const float* __restrict__ A0, const float* __restrict__ A1,
    const float* __restrict__ A2, const int* __restrict__ n2g,
    const float* __restrict__ bias, const float* __restrict__ w2,
    const float* __restrict__ b2s, int woff)
{
#if HAS_TC
    extern __shared__ __align__(1024) char smem[];
    const uint32_t smem_base = smem_u32(smem);
    const uint32_t mbar = smem_base + 8;
    const int tid = threadIdx.x;
    const int wid = tid >> 5;
    const int lane = tid & 31;
    const int rowBase = blockIdx.x * 128;

    if (wid == 0) tc_alloc(smem_base, 128);
    if (tid == 0) mbar_init(mbar, 1);
    __syncthreads();
    uint32_t tmem;
    asm volatile("ld.shared.b32 %0, [%1];" : "=r"(tmem) : "r"(smem_base));
    if (wid == 0) tc_relinquish();

    const uint64_t dAhi = make_desc(smem_base + OFF_AHI);
    const uint64_t dAlo = make_desc(smem_base + OFF_ALO);
    const uint64_t dBhi = make_desc(smem_base + OFF_BHI);
    const uint64_t dBlo = make_desc(smem_base + OFF_BLO);

    const int NCH = K / 32;
    for (int c = 0; c < NCH; c++) {
        const int k0 = c * 32;
        #pragma unroll
        for (int it = 0; it < 8; it++) {
            int i = it * 128 + tid;
            int m = i >> 3;
            int j = i & 7;
            int kk = k0 + j * 4;
            int r = rowBase + m;
            float4 v;
            if (MODE == 0) {
                if (kk < 128) {
                    v = *(const float4*)(A0 + (size_t)r * 128 + kk);
                } else {
                    int gg = __ldg(n2g + r);
                    if (kk < 256) v = *(const float4*)(A1 + (size_t)gg * 128 + (kk - 128));
                    else          v = *(const float4*)(A2 + (size_t)gg * 128 + (kk - 256));
                }
            } else if (MODE == 1) {
                size_t off = (size_t)r * 128 + kk;
                float4 a = *(const float4*)(g_x + off);
                float4 b = *(const float4*)(g_agg + off);
                v = make_float4(a.x + b.x, a.y + b.y, a.z + b.z, a.w + b.w);
                *(float4*)(g_agg + off) = make_float4(0.f, 0.f, 0.f, 0.f);
            } else if (MODE == 2) {
                v = *(const float4*)(g_h + (size_t)r * 128 + kk);
            } else {
                if (kk < 128) v = *(const float4*)(g_x + (size_t)r * 128 + kk);
                else          v = *(const float4*)(A0 + (size_t)r * 64 + (kk - 128));
            }
            uint4 hi, lo;
            hi.x = f2tf32(v.x); lo.x = f2tf32(v.x - __uint_as_float(hi.x));
            hi.y = f2tf32(v.y); lo.y = f2tf32(v.y - __uint_as_float(hi.y));
            hi.z = f2tf32(v.z); lo.z = f2tf32(v.z - __uint_as_float(hi.z));
            hi.w = f2tf32(v.w); lo.w = f2tf32(v.w - __uint_as_float(hi.w));
            uint32_t off = (uint32_t)(m >> 3) * 1024u + (uint32_t)((m & 7) * 128) + j * 16;
            off ^= ((m & 7) << 4);   // SW128 swizzle
            *(uint4*)(smem + OFF_AHI + off) = hi;
            *(uint4*)(smem + OFF_ALO + off) = lo;
            // B tile: pre-split transposed weights (row n == m)
            const size_t bidx = (size_t)woff + (size_t)m * K + kk;
            *(uint4*)(smem + OFF_BHI + off) = *(const uint4*)(g_wthi + bidx);
            *(uint4*)(smem + OFF_BLO + off) = *(const uint4*)(g_wtlo + bidx);
        }
        fence_async_shared();
        __syncthreads();
        if (tid == 0) {
            #pragma unroll
            for (int s = 0; s < 4; s++) {
                int first = (c == 0 && s == 0);
                mma_tf32(tmem, dAhi + s * 2, dBhi + s * 2, IDESC_TF32, first ? 0 : 1);
                mma_tf32(tmem, dAhi + s * 2, dBlo + s * 2, IDESC_TF32, 1);
                mma_tf32(tmem, dAlo + s * 2, dBhi + s * 2, IDESC_TF32, 1);
            }
            tc_commit(mbar);
        }
        mbar_wait(mbar, (uint32_t)(c & 1));
    }
    tc_fence_after();

    // ---------------- epilogue ----------------
    const int r = rowBase + wid * 32 + lane;
    if (MODE == 3) {
        float p = 0.f;
        #pragma unroll
        for (int s = 0; s < 4; s++) {
            uint32_t regs[32];
            ldtm32(regs, tmem + s * 32);
            tc_wait_ld();
            #pragma unroll
            for (int j = 0; j < 32; j++) {
                float t = fmaxf(__uint_as_float(regs[j]) + __ldg(bias + s * 32 + j), 0.f);
                p = fmaf(t, __ldg(w2 + s * 32 + j), p);
            }
        }
        g_logit[r] = p + b2s[0];
    } else {
        float* dstp = (MODE == 1) ? g_h : g_x;
        #pragma unroll
        for (int s = 0; s < 4; s++) {
            uint32_t regs[32];
            ldtm32(regs, tmem + s * 32);
            tc_wait_ld();
            size_t base = (size_t)r * 128 + s * 32;
            #pragma unroll
            for (int j = 0; j < 32; j += 4) {
                float4 o;
                o.x = fmaxf(__uint_as_float(regs[j + 0]) + __ldg(bias + s * 32 + j + 0), 0.f);
                o.y = fmaxf(__uint_as_float(regs[j + 1]) + __ldg(bias + s * 32 + j + 1), 0.f);
                o.z = fmaxf(__uint_as_float(regs[j + 2]) + __ldg(bias + s * 32 + j + 2), 0.f);
                o.w = fmaxf(__uint_as_float(regs[j + 3]) + __ldg(bias + s * 32 + j + 3), 0.f);
                if (MODE == 2) {
                    float4 x0 = *(const float4*)(g_x + base + j);
                    o.x += x0.x; o.y += x0.y; o.z += x0.z; o.w += x0.w;
                }
                *(float4*)(dstp + base + j) = o;
            }
        }
    }
    __syncthreads();
    if (wid == 0) tc_dealloc(tmem, 128);

#else  // ---------- naive fallback (family-PTX pass only; never runs on device) ----
    const int tid = threadIdx.x;
    const int rowBase = blockIdx.x * 128;
    __shared__ float col[128];
    for (int m = 0; m < 128; m++) {
        const int r = rowBase + m;
        float acc = 0.f;
        for (int k = 0; k < K; k++) {
            float a;
            if (MODE == 0) {
                if (k < 128) a = A0[(size_t)r * 128 + k];
                else {
                    int gg = n2g[r];
                    a = (k < 256) ? A1[(size_t)gg * 128 + (k - 128)]
                                  : A2[(size_t)gg * 128 + (k - 256)];
                }
            } else if (MODE == 1) {
                a = g_x[(size_t)r * 128 + k] + g_agg[(size_t)r * 128 + k];
            } else if (MODE == 2) {
                a = g_h[(size_t)r * 128 + k];
            } else {
                a = (k < 128) ? g_x[(size_t)r * 128 + k] : A0[(size_t)r * 64 + (k - 128)];
            }
            float w = g_wthi[(size_t)woff + (size_t)tid * K + k] +
                      g_wtlo[(size_t)woff + (size_t)tid * K + k];
            acc = fmaf(a, w, acc);
        }
        if (MODE == 3) {
            col[tid] = fmaxf(acc + bias[tid], 0.f) * w2[tid];
            __syncthreads();
            if (tid == 0) {
                float p = 0.f;
                for (int j = 0; j < 128; j++) p += col[j];
                g_logit[r] = p + b2s[0];
            }
            __syncthreads();
        } else if (MODE == 1) {
            g_h[(size_t)r * 128 + tid] = fmaxf(acc + bias[tid], 0.f);
        } else if (MODE == 2) {
            g_x[(size_t)r * 128 + tid] += fmaxf(acc + bias[tid], 0.f);
        } else {
            g_x[(size_t)r * 128 + tid] = fmaxf(acc + bias[tid], 0.f);
        }
    }
    if (MODE == 1) {
        __syncthreads();
        for (int i = tid; i < 128 * 128; i += 128)
            g_agg[(size_t)rowBase * 128 + i] = 0.f;
    }
#endif
}

// ---------------- segment softmax -------------------------------------------------
__global__ void zero_small_k() {
    int i = blockIdx.x * blockDim.x + threadIdx.x;
    if (i < NG) { g_menc[i] = 0u; g_den[i] = 0.f; }
}
__global__ void seg_max_k(const int* __restrict__ n2g) {
    int i = blockIdx.x * blockDim.x + threadIdx.x;
    if (i >= V_) return;
    atomicMax(&g_menc[n2g[i]], encf(g_logit[i]));
}
__global__ void seg_exp_k(const int* __restrict__ n2g, float* __restrict__ out) {
    int i = blockIdx.x * blockDim.x + threadIdx.x;
    if (i >= V_) return;
    int gg = n2g[i];
    float m = decf(g_menc[gg]);
    float ex = expf(g_logit[i] - m);
    out[i] = ex;
    atomicAdd(&g_den[gg], ex);
}
__global__ void seg_div_k(const int* __restrict__ n2g, float* __restrict__ out) {
    int i = blockIdx.x * blockDim.x + threadIdx.x;
    if (i >= V_) return;
    out[i] = out[i] / g_den[n2g[i]];
}

// ---------------- launch -----------------------------------------------------------
extern "C" void kernel_launch(void* const* d_in, const int* in_sizes, int n_in,
                              void* d_out, int out_size)
{
    const float* x_inp   = (const float*)d_in[0];
    const int*   eidx    = (const int*)  d_in[1];
    const float* eattr   = (const float*)d_in[2];
    const float* x_upd   = (const float*)d_in[3];
    const float* Zc      = (const float*)d_in[4];
    const float* Zb      = (const float*)d_in[5];
    const int*   n2g     = (const int*)  d_in[6];
    const float* W_emb   = (const float*)d_in[7];
    const float* b_emb   = (const float*)d_in[8];
    const float* W_edge  = (const float*)d_in[9];
    const float* b_edge  = (const float*)d_in[10];
    const float* W1      = (const float*)d_in[11];
    const float* b1      = (const float*)d_in[12];
    const float* W2      = (const float*)d_in[13];
    const float* b2      = (const float*)d_in[14];
    const float* W_mlp1  = (const float*)d_in[15];
    const float* b_mlp1  = (const float*)d_in[16];
    const float* W_mlp2  = (const float*)d_in[17];
    const float* b_mlp2  = (const float*)d_in[18];
    float* out = (float*)d_out;

    cudaFuncSetAttribute(tc_gemm_k<384, 0>, cudaFuncAttributeMaxDynamicSharedMemorySize, SMEM_BYTES);
    cudaFuncSetAttribute(tc_gemm_k<128, 1>, cudaFuncAttributeMaxDynamicSharedMemorySize, SMEM_BYTES);
    cudaFuncSetAttribute(tc_gemm_k<128, 2>, cudaFuncAttributeMaxDynamicSharedMemorySize, SMEM_BYTES);
    cudaFuncSetAttribute(tc_gemm_k<192, 3>, cudaFuncAttributeMaxDynamicSharedMemorySize, SMEM_BYTES);

    const int GB = V_ / 128;   // 2048 tiles

    split_w_k<<<(WT_TOTAL + 255) / 256, 256>>>(W_emb, W1, W2, W_mlp1);
    zero_small_k<<<(NG + 255) / 256, 256>>>();
    edge_embed_k<<<E_ / 128, 128>>>(eattr, W_edge, b_edge);

    tc_gemm_k<384, 0><<<GB, 128, SMEM_BYTES>>>(x_upd, Zc, Zb, n2g, b_emb,
                                               nullptr, nullptr, 0);
    for (int l = 0; l < 4; l++) {
        scatter_k<<<E_ / 8, 256>>>(eidx, eidx + E_);
        tc_gemm_k<128, 1><<<GB, 128, SMEM_BYTES>>>(nullptr, nullptr, nullptr, nullptr,
                                                   b1 + (size_t)l * 128, nullptr, nullptr,
                                                   49152 + l * 16384);
        tc_gemm_k<128, 2><<<GB, 128, SMEM_BYTES>>>(nullptr, nullptr, nullptr, nullptr,
                                                   b2 + (size_t)l * 128, nullptr, nullptr,
                                                   114688 + l * 16384);
    }
    tc_gemm_k<192, 3><<<GB, 128, SMEM_BYTES>>>(x_inp, nullptr, nullptr, nullptr,
                                               b_mlp1, W_mlp2, b_mlp2, 180224);

    seg_max_k<<<V_ / 256, 256>>>(n2g);
    seg_exp_k<<<V_ / 256, 256>>>(n2g, out);
    seg_div_k<<<V_ / 256, 256>>>(n2g, out);
}

// round 4
// speedup vs baseline: 1.4732x; 1.4732x over previous
#include <cuda_runtime.h>
#include <cuda_bf16.h>
#include <cstdint>

#define V_  262144
#define E_  524288
#define NG  8192
#define H_  128

// ---------------- tcgen05 feature gate ---------------------------------------------
#if defined(__CUDA_ARCH_FEAT_SM103_ALL) || defined(__CUDA_ARCH_FEAT_SM100_ALL) || defined(__CUDA_ARCH_FEAT_SM101_ALL)
#define HAS_TC 1
#endif
#if !defined(HAS_TC) && defined(__CUDA_ARCH_HAS_FEATURE__)
#if __CUDA_ARCH_HAS_FEATURE__(SM103_ALL)
#define HAS_TC 1
#endif
#endif
#ifndef HAS_TC
#define HAS_TC 0
#endif

// ---------------- scratch globals ------------------------------------------------
__device__ float    g_x[(size_t)V_ * H_];
__device__ float    g_e[(size_t)E_ * H_];
__device__ float    g_agg[(size_t)V_ * H_];   // stays zero between launches
__device__ float    g_h[(size_t)V_ * H_];
__device__ float    g_logit[V_];
__device__ unsigned g_menc[NG];
__device__ float    g_den[NG];
// weights, transposed + tf32 hi/lo split, PRE-SWIZZLED (SW64) chunk-contiguous:
// each 16-K chunk = 2048 floats = 8KB, laid out exactly as the smem tile image.
// bases (floats): emb 0 (24 ch) | W1 l: 49152+l*16384 (8 ch) | W2 l: 114688+l*16384 | mlp1 180224 (12 ch)
#define WT_TOTAL 204800
__device__ float    g_wthi[WT_TOTAL];
__device__ float    g_wtlo[WT_TOTAL];

// ---------------- PTX helpers -----------------------------------------------------
__device__ __forceinline__ uint32_t smem_u32(const void* p) {
    uint32_t a;
    asm("{ .reg .u64 t; cvta.to.shared.u64 t, %1; cvt.u32.u64 %0, t; }" : "=r"(a) : "l"(p));
    return a;
}
__device__ __forceinline__ uint32_t f2tf32(float v) {
    uint32_t r; asm("cvt.rna.tf32.f32 %0, %1;" : "=r"(r) : "f"(v)); return r;
}
__device__ __forceinline__ void mbar_init(uint32_t mbar, uint32_t cnt) {
    asm volatile("mbarrier.init.shared.b64 [%0], %1;" :: "r"(mbar), "r"(cnt) : "memory");
}
__device__ __forceinline__ void mbar_arrive(uint32_t mbar) {
    asm volatile("mbarrier.arrive.shared.b64 _, [%0];" :: "r"(mbar) : "memory");
}
__device__ __forceinline__ void mbar_wait(uint32_t mbar, uint32_t parity) {
    asm volatile(
        "{\n\t.reg .pred P;\n\tWL_%=:\n\t"
        "mbarrier.try_wait.parity.acquire.cta.shared::cta.b64 P, [%0], %1, 0x989680;\n\t"
        "@!P bra WL_%=;\n\t}" :: "r"(mbar), "r"(parity) : "memory");
}
__device__ __forceinline__ void fence_async_shared() {
    asm volatile("fence.proxy.async.shared::cta;" ::: "memory");
}

#if HAS_TC
__device__ __forceinline__ void mma_tf32(uint32_t d, uint64_t a, uint64_t b,
                                         uint32_t idesc, int acc) {
    asm volatile(
        "{\n\t.reg .pred p;\n\tsetp.ne.b32 p, %4, 0;\n\t"
        "tcgen05.mma.cta_group::1.kind::tf32 [%0], %1, %2, %3, p;\n\t}"
        :: "r"(d), "l"(a), "l"(b), "r"(idesc), "r"(acc) : "memory");
}
__device__ __forceinline__ void tc_commit(uint32_t mbar) {
    asm volatile(
        "tcgen05.commit.cta_group::1.mbarrier::arrive::one.shared::cluster.b64 [%0];"
        :: "r"(mbar) : "memory");
}
__device__ __forceinline__ void tc_alloc(uint32_t smem_dst, uint32_t ncols) {
    asm volatile("tcgen05.alloc.cta_group::1.sync.aligned.shared::cta.b32 [%0], %1;"
                 :: "r"(smem_dst), "r"(ncols) : "memory");
}
__device__ __forceinline__ void tc_dealloc(uint32_t tmem, uint32_t ncols) {
    asm volatile("tcgen05.dealloc.cta_group::1.sync.aligned.b32 %0, %1;"
                 :: "r"(tmem), "r"(ncols));
}
__device__ __forceinline__ void tc_relinquish() {
    asm volatile("tcgen05.relinquish_alloc_permit.cta_group::1.sync.aligned;");
}
__device__ __forceinline__ void tc_fence_after() {
    asm volatile("tcgen05.fence::after_thread_sync;" ::: "memory");
}
__device__ __forceinline__ void tc_wait_ld() {
    asm volatile("tcgen05.wait::ld.sync.aligned;" ::: "memory");
}
__device__ __forceinline__ void ldtm32(uint32_t* r, uint32_t addr) {
    asm volatile(
        "tcgen05.ld.sync.aligned.32x32b.x32.b32 "
        "{%0, %1, %2, %3, %4, %5, %6, %7, %8, %9, %10, %11, %12, %13, %14, %15, "
        " %16, %17, %18, %19, %20, %21, %22, %23, %24, %25, %26, %27, %28, %29, %30, %31}, [%32];"
        : "=r"(r[0]), "=r"(r[1]), "=r"(r[2]), "=r"(r[3]), "=r"(r[4]), "=r"(r[5]),
          "=r"(r[6]), "=r"(r[7]), "=r"(r[8]), "=r"(r[9]), "=r"(r[10]), "=r"(r[11]),
          "=r"(r[12]), "=r"(r[13]), "=r"(r[14]), "=r"(r[15]), "=r"(r[16]), "=r"(r[17]),
          "=r"(r[18]), "=r"(r[19]), "=r"(r[20]), "=r"(r[21]), "=r"(r[22]), "=r"(r[23]),
          "=r"(r[24]), "=r"(r[25]), "=r"(r[26]), "=r"(r[27]), "=r"(r[28]), "=r"(r[29]),
          "=r"(r[30]), "=r"(r[31])
        : "r"(addr));
}
#endif  // HAS_TC

__device__ __forceinline__ unsigned encf(float f) {
    unsigned u = __float_as_uint(f);
    return (u & 0x80000000u) ? ~u : (u | 0x80000000u);
}
__device__ __forceinline__ float decf(unsigned u) {
    return (u & 0x80000000u) ? __uint_as_float(u & 0x7fffffffu) : __uint_as_float(~u);
}

// SW64 K-major descriptor: layout=4, version=1, SBO=32 (512B 8-row-group), LBO=1
static __device__ __forceinline__ uint64_t make_desc64(uint32_t addr) {
    const uint64_t base =
        (uint64_t(4) << 61) | (uint64_t(1) << 46) | (uint64_t(32) << 32) | (uint64_t(1) << 16);
    return base | ((uint64_t)(addr >> 4) & 0x3FFF);
}

// idesc: cF32(1<<4) | aTF32(2<<7) | bTF32(2<<10) | N=128 (16<<17) | M=128 (8<<24)
#define IDESC_TF32 0x08200910u

// smem layout (bytes)
#define SM_TMEMP 0
#define SM_FULL0 16
#define SM_FULL1 24
#define SM_EMPT0 32
#define SM_EMPT1 40
#define SM_PART  256          // 1KB epilogue partials (MODE 3)
#define SM_AHI   2048         // + s*8192   (2 stages)
#define SM_ALO   (2048 + 16384)
#define SM_BHI   (2048 + 32768)
#define SM_BLO   (2048 + 49152)
#define SMEM_BYTES (2048 + 65536)

// ---------------- weight transpose + tf32 split + SW64 pre-swizzle ----------------
__global__ void split_w_k(const float* __restrict__ We, const float* __restrict__ W1,
                          const float* __restrict__ W2, const float* __restrict__ Wm)
{
    int i = blockIdx.x * 256 + threadIdx.x;
    if (i >= WT_TOTAL) return;
    // decode (gemm base, n, k) from flat transposed index (same bases as before)
    int base, n, k, K;
    if (i < 49152)       { base = 0;      int j = i;          K = 384; n = j / K; k = j % K; }
    else if (i < 114688) { int j = i - 49152;  int l = j >> 14; base = 49152 + l*16384;  j &= 16383; K = 128; n = j >> 7; k = j & 127; }
    else if (i < 180224) { int j = i - 114688; int l = j >> 14; base = 114688 + l*16384; j &= 16383; K = 128; n = j >> 7; k = j & 127; }
    else                 { base = 180224; int j = i - 180224;  K = 192; n = j / K; k = j % K; }
    float v;
    if (base == 0)           v = We[k * 128 + n];
    else if (base < 114688)  v = W1[(base - 49152) / 16384 * 16384 + k * 128 + n];
    else if (base < 180224)  v = W2[(base - 114688) / 16384 * 16384 + k * 128 + n];
    else                     v = Wm[k * 128 + n];

    uint32_t h = f2tf32(v);
    float lo = v - __uint_as_float(h);
    // destination: chunk-contiguous SW64 tile image
    int chunk = k >> 4;
    int kk = k & 15;
    uint32_t off = (uint32_t)n * 64u + (uint32_t)kk * 4u;
    off ^= ((off >> 3) & 0x30);               // SW64 swizzle
    int di = base + chunk * 2048 + (int)(off >> 2);
    g_wthi[di] = __uint_as_float(h);
    g_wtlo[di] = __uint_as_float(f2tf32(lo));
}

// ---------------- edge embedding -------------------------------------------------
__global__ __launch_bounds__(128) void edge_embed_k(
    const float* __restrict__ attr, const float* __restrict__ Wedge,
    const float* __restrict__ bedge)
{
    __shared__ float Ws[16 * 128];
    __shared__ float Ae[128 * 16];
    __shared__ float bs[128];
    const int tid = threadIdx.x;
    const int e0 = blockIdx.x * 128;
    for (int i = tid; i < 16 * 128; i += 128) Ws[i] = Wedge[i];
    bs[tid] = bedge[tid];
    for (int i = tid; i < 128 * 16; i += 128) Ae[i] = attr[(size_t)e0 * 16 + i];
    __syncthreads();
    for (int ee = 0; ee < 128; ee++) {
        float s = bs[tid];
        #pragma unroll
        for (int k = 0; k < 16; k++) s = fmaf(Ae[ee * 16 + k], Ws[k * 128 + tid], s);
        g_e[(size_t)(e0 + ee) * 128 + tid] = fmaxf(s, 0.f);
    }
}

// ---------------- scatter --------------------------------------------------------
__global__ __launch_bounds__(256) void scatter_k(
    const int* __restrict__ src, const int* __restrict__ dst)
{
    const int warp = (blockIdx.x * blockDim.x + threadIdx.x) >> 5;
    const int lane = threadIdx.x & 31;
    if (warp >= E_) return;
    const int s = src[warp];
    const int d = dst[warp];
    float4 xv = *(const float4*)(g_x + (size_t)s * 128 + lane * 4);
    float4 ev = *(const float4*)(g_e + (size_t)warp * 128 + lane * 4);
    float4 m;
    m.x = fmaxf(xv.x + ev.x, 0.f);
    m.y = fmaxf(xv.y + ev.y, 0.f);
    m.z = fmaxf(xv.z + ev.z, 0.f);
    m.w = fmaxf(xv.w + ev.w, 0.f);
    atomicAdd((float4*)(g_agg + (size_t)d * 128 + lane * 4), m);
}

// ---------------- pipelined tcgen05 tf32 GEMM (3xTF32) ----------------------------
// 288 threads: warps 0-7 = producers + epilogue, warp 8 lane 0 = MMA issuer.
// 2-stage smem pipeline, chunk = 16 K-elems, SW64 K-major tiles.
// MODE 0 (EMB):  A = [x_upd | Zc[g] | Zb[g]], out = relu -> g_x
// MODE 1 (L1):   A = g_x + g_agg (zeroes g_agg), out = relu -> g_h
// MODE 2 (L2):   A = g_h, g_x += relu(acc + b)
// MODE 3 (HEAD): A = [g_x | x_inp], relu, dot w2 -> g_logit
template <int K, int MODE>
__global__ __launch_bounds__(288, 2) void tc_gemm_k(
    const float* __restrict__ A0, const float* __restrict__ A1,
    const float* __restrict__ A2, const int* __restrict__ n2g,
    const float* __restrict__ bias, const float* __restrict__ w2,
    const float* __restrict__ b2s, int woff)
{
#if HAS_TC
    extern __shared__ __align__(1024) char smem[];
    const uint32_t sb = smem_u32(smem);
    const int tid  = threadIdx.x;
    const int wid  = tid >> 5;
    const int lane = tid & 31;
    const int rowBase = blockIdx.x * 128;
    const int NCH = K / 16;

    if (wid == 0) { tc_alloc(sb + SM_TMEMP, 128); tc_relinquish(); }
    if (tid == 0) {
        mbar_init(sb + SM_FULL0, 256); mbar_init(sb + SM_FULL1, 256);
        mbar_init(sb + SM_EMPT0, 1);   mbar_init(sb + SM_EMPT1, 1);
    }
    __syncthreads();
    uint32_t tmem;
    asm volatile("ld.shared.b32 %0, [%1];" : "=r"(tmem) : "r"(sb + SM_TMEMP));

    if (tid < 256) {
        // -------------------- producer --------------------
        const int row  = tid >> 1;
        const int r    = rowBase + row;
        const int f4c0 = (tid & 1) * 2;                 // 0 or 2  (float4 column)
        uint32_t bo = (uint32_t)row * 64u + (uint32_t)f4c0 * 16u;
        const uint32_t sw0 = bo ^ ((bo >> 3) & 0x30);
        bo += 16u;
        const uint32_t sw1 = bo ^ ((bo >> 3) & 0x30);
        int gg = 0;
        if (MODE == 0) gg = __ldg(n2g + r);

        for (int c = 0; c < NCH; c++) {
            const int s = c & 1;
            const int kb = c * 16 + f4c0 * 4;
            // ---- prefetch global loads BEFORE buffer wait ----
            float4 av0, av1;
            if (MODE == 0) {
                if (kb < 128) {
                    av0 = *(const float4*)(A0 + (size_t)r * 128 + kb);
                    av1 = *(const float4*)(A0 + (size_t)r * 128 + kb + 4);
                } else if (kb < 256) {
                    av0 = *(const float4*)(A1 + (size_t)gg * 128 + (kb - 128));
                    av1 = *(const float4*)(A1 + (size_t)gg * 128 + (kb - 124));
                } else {
                    av0 = *(const float4*)(A2 + (size_t)gg * 128 + (kb - 256));
                    av1 = *(const float4*)(A2 + (size_t)gg * 128 + (kb - 252));
                }
            } else if (MODE == 1) {
                size_t off = (size_t)r * 128 + kb;
                float4 a0 = *(const float4*)(g_x + off);
                float4 g0 = *(const float4*)(g_agg + off);
                float4 a1 = *(const float4*)(g_x + off + 4);
                float4 g1 = *(const float4*)(g_agg + off + 4);
                av0 = make_float4(a0.x + g0.x, a0.y + g0.y, a0.z + g0.z, a0.w + g0.w);
                av1 = make_float4(a1.x + g1.x, a1.y + g1.y, a1.z + g1.z, a1.w + g1.w);
                *(float4*)(g_agg + off)     = make_float4(0.f, 0.f, 0.f, 0.f);
                *(float4*)(g_agg + off + 4) = make_float4(0.f, 0.f, 0.f, 0.f);
            } else if (MODE == 2) {
                av0 = *(const float4*)(g_h + (size_t)r * 128 + kb);
                av1 = *(const float4*)(g_h + (size_t)r * 128 + kb + 4);
            } else {
                if (kb < 128) {
                    av0 = *(const float4*)(g_x + (size_t)r * 128 + kb);
                    av1 = *(const float4*)(g_x + (size_t)r * 128 + kb + 4);
                } else {
                    av0 = *(const float4*)(A0 + (size_t)r * 64 + (kb - 128));
                    av1 = *(const float4*)(A0 + (size_t)r * 64 + (kb - 124));
                }
            }
            const float4* bsh = (const float4*)(g_wthi + woff + c * 2048);
            const float4* bsl = (const float4*)(g_wtlo + woff + c * 2048);
            float4 b0h = bsh[tid], b1h = bsh[tid + 256];
            float4 b0l = bsl[tid], b1l = bsl[tid + 256];

            // ---- wait for buffer free (chunk c-2's MMAs complete) ----
            if (c >= 2) mbar_wait(sb + SM_EMPT0 + s * 8, ((c >> 1) + 1) & 1);

            // ---- A: tf32 hi/lo split, swizzled store ----
            uint4 hi0, lo0, hi1, lo1;
            hi0.x = f2tf32(av0.x); lo0.x = f2tf32(av0.x - __uint_as_float(hi0.x));
            hi0.y = f2tf32(av0.y); lo0.y = f2tf32(av0.y - __uint_as_float(hi0.y));
            hi0.z = f2tf32(av0.z); lo0.z = f2tf32(av0.z - __uint_as_float(hi0.z));
            hi0.w = f2tf32(av0.w); lo0.w = f2tf32(av0.w - __uint_as_float(hi0.w));
            hi1.x = f2tf32(av1.x); lo1.x = f2tf32(av1.x - __uint_as_float(hi1.x));
            hi1.y = f2tf32(av1.y); lo1.y = f2tf32(av1.y - __uint_as_float(hi1.y));
            hi1.z = f2tf32(av1.z); lo1.z = f2tf32(av1.z - __uint_as_float(hi1.z));
            hi1.w = f2tf32(av1.w); lo1.w = f2tf32(av1.w - __uint_as_float(hi1.w));
            char* stg = smem + s * 8192;
            *(uint4*)(stg + SM_AHI + sw0) = hi0;
            *(uint4*)(stg + SM_AHI + sw1) = hi1;
            *(uint4*)(stg + SM_ALO + sw0) = lo0;
            *(uint4*)(stg + SM_ALO + sw1) = lo1;
            // ---- B: straight copy (pre-swizzled) ----
            *(float4*)(stg + SM_BHI + tid * 16)         = b0h;
            *(float4*)(stg + SM_BHI + (tid + 256) * 16) = b1h;
            *(float4*)(stg + SM_BLO + tid * 16)         = b0l;
            *(float4*)(stg + SM_BLO + (tid + 256) * 16) = b1l;

            fence_async_shared();
            mbar_arrive(sb + SM_FULL0 + s * 8);
        }
    } else if (tid == 256) {
        // -------------------- MMA issuer --------------------
        uint64_t dAhi[2], dAlo[2], dBhi[2], dBlo[2];
        #pragma unroll
        for (int s = 0; s < 2; s++) {
            dAhi[s] = make_desc64(sb + SM_AHI + s * 8192);
            dAlo[s] = make_desc64(sb + SM_ALO + s * 8192);
            dBhi[s] = make_desc64(sb + SM_BHI + s * 8192);
            dBlo[s] = make_desc64(sb + SM_BLO + s * 8192);
        }
        for (int c = 0; c < NCH; c++) {
            const int s = c & 1;
            mbar_wait(sb + SM_FULL0 + s * 8, (c >> 1) & 1);
            #pragma unroll
            for (int ks = 0; ks < 2; ks++) {
                const uint64_t oA = ks * 2;
                int first = (c == 0 && ks == 0);
                mma_tf32(tmem, dAhi[s] + oA, dBhi[s] + oA, IDESC_TF32, first ? 0 : 1);
                mma_tf32(tmem, dAhi[s] + oA, dBlo[s] + oA, IDESC_TF32, 1);
                mma_tf32(tmem, dAlo[s] + oA, dBhi[s] + oA, IDESC_TF32, 1);
            }
            tc_commit(sb + SM_EMPT0 + s * 8);
        }
    }

    // -------------------- epilogue --------------------
    {
        const int L = NCH - 1;
        mbar_wait(sb + SM_EMPT0 + (L & 1) * 8, (L >> 1) & 1);
        tc_fence_after();
    }
    if (tid < 256) {
        const int sp = wid & 3;           // TMEM subpartition (rows sp*32..+31)
        const int h  = wid >> 2;          // column half: 0 -> cols 0-63, 1 -> 64-127
        const int r  = rowBase + sp * 32 + lane;
        const int cb = h * 64;
        uint32_t regs[64];
        ldtm32(regs,      tmem + cb);
        ldtm32(regs + 32, tmem + cb + 32);
        tc_wait_ld();

        if (MODE == 3) {
            float p = 0.f;
            #pragma unroll
            for (int j = 0; j < 64; j++) {
                float t = fmaxf(__uint_as_float(regs[j]) + __ldg(bias + cb + j), 0.f);
                p = fmaf(t, __ldg(w2 + cb + j), p);
            }
            ((float*)(smem + SM_PART))[h * 128 + sp * 32 + lane] = p;
        } else {
            float* dstp = (MODE == 1) ? g_h : g_x;
            size_t base = (size_t)r * 128 + cb;
            #pragma unroll
            for (int j = 0; j < 64; j += 4) {
                float4 o;
                o.x = fmaxf(__uint_as_float(regs[j + 0]) + __ldg(bias + cb + j + 0), 0.f);
                o.y = fmaxf(__uint_as_float(regs[j + 1]) + __ldg(bias + cb + j + 1), 0.f);
                o.z = fmaxf(__uint_as_float(regs[j + 2]) + __ldg(bias + cb + j + 2), 0.f);
                o.w = fmaxf(__uint_as_float(regs[j + 3]) + __ldg(bias + cb + j + 3), 0.f);
                if (MODE == 2) {
                    float4 x0 = *(const float4*)(g_x + base + j);
                    o.x += x0.x; o.y += x0.y; o.z += x0.z; o.w += x0.w;
                }
                *(float4*)(dstp + base + j) = o;
            }
        }
    }
    __syncthreads();
    if (MODE == 3 && tid < 128) {
        const float* part = (const float*)(smem + SM_PART);
        g_logit[rowBase + tid] = part[tid] + part[128 + tid] + b2s[0];
    }
    if (wid == 0) tc_dealloc(tmem, 128);

#else  // ---------- naive fallback (family-PTX pass only; never executes) ----------
    const int tid = threadIdx.x;
    const int rowBase = blockIdx.x * 128;
    if (tid >= 128) return;
    __shared__ float col[128];
    for (int m = 0; m < 128; m++) {
        const int r = rowBase + m;
        float acc = 0.f;
        for (int k = 0; k < K; k++) {
            float a;
            if (MODE == 0) {
                if (k < 128) a = A0[(size_t)r * 128 + k];
                else {
                    int gg = n2g[r];
                    a = (k < 256) ? A1[(size_t)gg * 128 + (k - 128)]
                                  : A2[(size_t)gg * 128 + (k - 256)];
                }
            } else if (MODE == 1) {
                a = g_x[(size_t)r * 128 + k] + g_agg[(size_t)r * 128 + k];
            } else if (MODE == 2) {
                a = g_h[(size_t)r * 128 + k];
            } else {
                a = (k < 128) ? g_x[(size_t)r * 128 + k] : A0[(size_t)r * 64 + (k - 128)];
            }
            int chunk = k >> 4, kk = k & 15;
            uint32_t off = (uint32_t)tid * 64u + (uint32_t)kk * 4u;
            off ^= ((off >> 3) & 0x30);
            int di = woff + chunk * 2048 + (int)(off >> 2);
            acc = fmaf(a, g_wthi[di] + g_wtlo[di], acc);
        }
        if (MODE == 3) {
            col[tid] = fmaxf(acc + bias[tid], 0.f) * w2[tid];
            __syncthreads();
            if (tid == 0) {
                float p = 0.f;
                for (int j = 0; j < 128; j++) p += col[j];
                g_logit[r] = p + b2s[0];
            }
            __syncthreads();
        } else if (MODE == 1) {
            g_h[(size_t)r * 128 + tid] = fmaxf(acc + bias[tid], 0.f);
        } else if (MODE == 2) {
            g_x[(size_t)r * 128 + tid] += fmaxf(acc + bias[tid], 0.f);
        } else {
            g_x[(size_t)r * 128 + tid] = fmaxf(acc + bias[tid], 0.f);
        }
    }
    if (MODE == 1) {
        __syncthreads();
        for (int i = tid; i < 128 * 128; i += 128)
            g_agg[(size_t)rowBase * 128 + i] = 0.f;
    }
#endif
}

// ---------------- segment softmax -------------------------------------------------
__global__ void zero_small_k() {
    int i = blockIdx.x * blockDim.x + threadIdx.x;
    if (i < NG) { g_menc[i] = 0u; g_den[i] = 0.f; }
}
__global__ void seg_max_k(const int* __restrict__ n2g) {
    int i = blockIdx.x * blockDim.x + threadIdx.x;
    if (i >= V_) return;
    atomicMax(&g_menc[n2g[i]], encf(g_logit[i]));
}
__global__ void seg_exp_k(const int* __restrict__ n2g, float* __restrict__ out) {
    int i = blockIdx.x * blockDim.x + threadIdx.x;
    if (i >= V_) return;
    int gg = n2g[i];
    float m = decf(g_menc[gg]);
    float ex = expf(g_logit[i] - m);
    out[i] = ex;
    atomicAdd(&g_den[gg], ex);
}
__global__ void seg_div_k(const int* __restrict__ n2g, float* __restrict__ out) {
    int i = blockIdx.x * blockDim.x + threadIdx.x;
    if (i >= V_) return;
    out[i] = out[i] / g_den[n2g[i]];
}

// ---------------- launch -----------------------------------------------------------
extern "C" void kernel_launch(void* const* d_in, const int* in_sizes, int n_in,
                              void* d_out, int out_size)
{
    const float* x_inp   = (const float*)d_in[0];
    const int*   eidx    = (const int*)  d_in[1];
    const float* eattr   = (const float*)d_in[2];
    const float* x_upd   = (const float*)d_in[3];
    const float* Zc      = (const float*)d_in[4];
    const float* Zb      = (const float*)d_in[5];
    const int*   n2g     = (const int*)  d_in[6];
    const float* W_emb   = (const float*)d_in[7];
    const float* b_emb   = (const float*)d_in[8];
    const float* W_edge  = (const float*)d_in[9];
    const float* b_edge  = (const float*)d_in[10];
    const float* W1      = (const float*)d_in[11];
    const float* b1      = (const float*)d_in[12];
    const float* W2      = (const float*)d_in[13];
    const float* b2      = (const float*)d_in[14];
    const float* W_mlp1  = (const float*)d_in[15];
    const float* b_mlp1  = (const float*)d_in[16];
    const float* W_mlp2  = (const float*)d_in[17];
    const float* b_mlp2  = (const float*)d_in[18];
    float* out = (float*)d_out;

    cudaFuncSetAttribute(tc_gemm_k<384, 0>, cudaFuncAttributeMaxDynamicSharedMemorySize, SMEM_BYTES);
    cudaFuncSetAttribute(tc_gemm_k<128, 1>, cudaFuncAttributeMaxDynamicSharedMemorySize, SMEM_BYTES);
    cudaFuncSetAttribute(tc_gemm_k<128, 2>, cudaFuncAttributeMaxDynamicSharedMemorySize, SMEM_BYTES);
    cudaFuncSetAttribute(tc_gemm_k<192, 3>, cudaFuncAttributeMaxDynamicSharedMemorySize, SMEM_BYTES);

    const int GB = V_ / 128;   // 2048 tiles

    split_w_k<<<(WT_TOTAL + 255) / 256, 256>>>(W_emb, W1, W2, W_mlp1);
    zero_small_k<<<(NG + 255) / 256, 256>>>();
    edge_embed_k<<<E_ / 128, 128>>>(eattr, W_edge, b_edge);

    tc_gemm_k<384, 0><<<GB, 288, SMEM_BYTES>>>(x_upd, Zc, Zb, n2g, b_emb,
                                               nullptr, nullptr, 0);
    for (int l = 0; l < 4; l++) {
        scatter_k<<<E_ / 8, 256>>>(eidx, eidx + E_);
        tc_gemm_k<128, 1><<<GB, 288, SMEM_BYTES>>>(nullptr, nullptr, nullptr, nullptr,
                                                   b1 + (size_t)l * 128, nullptr, nullptr,
                                                   49152 + l * 16384);
        tc_gemm_k<128, 2><<<GB, 288, SMEM_BYTES>>>(nullptr, nullptr, nullptr, nullptr,
                                                   b2 + (size_t)l * 128, nullptr, nullptr,
                                                   114688 + l * 16384);
    }
    tc_gemm_k<192, 3><<<GB, 288, SMEM_BYTES>>>(x_inp, nullptr, nullptr, nullptr,
                                               b_mlp1, W_mlp2, b_mlp2, 180224);

    seg_max_k<<<V_ / 256, 256>>>(n2g);
    seg_exp_k<<<V_ / 256, 256>>>(n2g, out);
    seg_div_k<<<V_ / 256, 256>>>(n2g, out);
}

// round 5
// speedup vs baseline: 2.0835x; 1.4143x over previous
#include <cuda_runtime.h>
#include <cuda_bf16.h>
#include <cstdint>

#define V_  262144
#define E_  524288
#define NG  8192
#define H_  128

// ---------------- tcgen05 feature gate ---------------------------------------------
#if defined(__CUDA_ARCH_FEAT_SM103_ALL) || defined(__CUDA_ARCH_FEAT_SM100_ALL) || defined(__CUDA_ARCH_FEAT_SM101_ALL)
#define HAS_TC 1
#endif
#if !defined(HAS_TC) && defined(__CUDA_ARCH_HAS_FEATURE__)
#if __CUDA_ARCH_HAS_FEATURE__(SM103_ALL)
#define HAS_TC 1
#endif
#endif
#ifndef HAS_TC
#define HAS_TC 0
#endif

// ---------------- scratch globals ------------------------------------------------
__device__ float    g_x[(size_t)V_ * H_];
__device__ float    g_e[(size_t)E_ * H_];
__device__ float    g_agg[(size_t)V_ * H_];   // stays zero between launches
__device__ float    g_h[(size_t)V_ * H_];
__device__ float    g_logit[V_];
__device__ unsigned g_menc[NG];
__device__ float    g_den[NG];
// weights: transposed, bf16 hi/lo split, PRE-SWIZZLED (SW64) 32-K-chunk-contiguous
// images (each chunk = 128 rows x 32 bf16 = 4096 elems = 8KB, exact smem tile image).
// bases (elements): emb 0 | W1 l: 49152+l*16384 | W2 l: 114688+l*16384 | mlp1 180224
#define WT_TOTAL 204800
__device__ __align__(16) __nv_bfloat16 g_wbhi[WT_TOTAL];
__device__ __align__(16) __nv_bfloat16 g_wblo[WT_TOTAL];

// ---------------- PTX helpers -----------------------------------------------------
__device__ __forceinline__ uint32_t smem_u32(const void* p) {
    uint32_t a;
    asm("{ .reg .u64 t; cvta.to.shared.u64 t, %1; cvt.u32.u64 %0, t; }" : "=r"(a) : "l"(p));
    return a;
}
__device__ __forceinline__ void mbar_init(uint32_t mbar, uint32_t cnt) {
    asm volatile("mbarrier.init.shared.b64 [%0], %1;" :: "r"(mbar), "r"(cnt) : "memory");
}
__device__ __forceinline__ void mbar_arrive(uint32_t mbar) {
    asm volatile("mbarrier.arrive.shared.b64 _, [%0];" :: "r"(mbar) : "memory");
}
__device__ __forceinline__ void mbar_arrive_tx(uint32_t mbar, uint32_t tx) {
    asm volatile("mbarrier.arrive.expect_tx.shared.b64 _, [%0], %1;"
                 :: "r"(mbar), "r"(tx) : "memory");
}
__device__ __forceinline__ void mbar_wait(uint32_t mbar, uint32_t parity) {
    asm volatile(
        "{\n\t.reg .pred P;\n\tWL_%=:\n\t"
        "mbarrier.try_wait.parity.acquire.cta.shared::cta.b64 P, [%0], %1, 0x989680;\n\t"
        "@!P bra WL_%=;\n\t}" :: "r"(mbar), "r"(parity) : "memory");
}
__device__ __forceinline__ void fence_async_shared() {
    asm volatile("fence.proxy.async.shared::cta;" ::: "memory");
}
__device__ __forceinline__ void bulk_g2s(uint32_t dst, const void* src, uint32_t bytes,
                                         uint32_t mbar) {
    uint64_t gsrc;
    asm("cvta.to.global.u64 %0, %1;" : "=l"(gsrc) : "l"(src));
    asm volatile(
        "cp.async.bulk.shared::cta.global.mbarrier::complete_tx::bytes [%0], [%1], %2, [%3];"
        :: "r"(dst), "l"(gsrc), "r"(bytes), "r"(mbar) : "memory");
}

#if HAS_TC
__device__ __forceinline__ void mma_bf16(uint32_t d, uint64_t a, uint64_t b,
                                         uint32_t idesc, int acc) {
    asm volatile(
        "{\n\t.reg .pred p;\n\tsetp.ne.b32 p, %4, 0;\n\t"
        "tcgen05.mma.cta_group::1.kind::f16 [%0], %1, %2, %3, p;\n\t}"
        :: "r"(d), "l"(a), "l"(b), "r"(idesc), "r"(acc) : "memory");
}
__device__ __forceinline__ void tc_commit(uint32_t mbar) {
    asm volatile(
        "tcgen05.commit.cta_group::1.mbarrier::arrive::one.shared::cluster.b64 [%0];"
        :: "r"(mbar) : "memory");
}
__device__ __forceinline__ void tc_alloc(uint32_t smem_dst, uint32_t ncols) {
    asm volatile("tcgen05.alloc.cta_group::1.sync.aligned.shared::cta.b32 [%0], %1;"
                 :: "r"(smem_dst), "r"(ncols) : "memory");
}
__device__ __forceinline__ void tc_dealloc(uint32_t tmem, uint32_t ncols) {
    asm volatile("tcgen05.dealloc.cta_group::1.sync.aligned.b32 %0, %1;"
                 :: "r"(tmem), "r"(ncols));
}
__device__ __forceinline__ void tc_relinquish() {
    asm volatile("tcgen05.relinquish_alloc_permit.cta_group::1.sync.aligned;");
}
__device__ __forceinline__ void tc_fence_after() {
    asm volatile("tcgen05.fence::after_thread_sync;" ::: "memory");
}
__device__ __forceinline__ void tc_wait_ld() {
    asm volatile("tcgen05.wait::ld.sync.aligned;" ::: "memory");
}
__device__ __forceinline__ void ldtm32(uint32_t* r, uint32_t addr) {
    asm volatile(
        "tcgen05.ld.sync.aligned.32x32b.x32.b32 "
        "{%0, %1, %2, %3, %4, %5, %6, %7, %8, %9, %10, %11, %12, %13, %14, %15, "
        " %16, %17, %18, %19, %20, %21, %22, %23, %24, %25, %26, %27, %28, %29, %30, %31}, [%32];"
        : "=r"(r[0]), "=r"(r[1]), "=r"(r[2]), "=r"(r[3]), "=r"(r[4]), "=r"(r[5]),
          "=r"(r[6]), "=r"(r[7]), "=r"(r[8]), "=r"(r[9]), "=r"(r[10]), "=r"(r[11]),
          "=r"(r[12]), "=r"(r[13]), "=r"(r[14]), "=r"(r[15]), "=r"(r[16]), "=r"(r[17]),
          "=r"(r[18]), "=r"(r[19]), "=r"(r[20]), "=r"(r[21]), "=r"(r[22]), "=r"(r[23]),
          "=r"(r[24]), "=r"(r[25]), "=r"(r[26]), "=r"(r[27]), "=r"(r[28]), "=r"(r[29]),
          "=r"(r[30]), "=r"(r[31])
        : "r"(addr));
}
#endif  // HAS_TC

__device__ __forceinline__ unsigned encf(float f) {
    unsigned u = __float_as_uint(f);
    return (u & 0x80000000u) ? ~u : (u | 0x80000000u);
}
__device__ __forceinline__ float decf(unsigned u) {
    return (u & 0x80000000u) ? __uint_as_float(u & 0x7fffffffu) : __uint_as_float(~u);
}

// SW64 K-major descriptor: layout=4, version=1, SBO=32 (512B 8-row group), LBO=1
static __device__ __forceinline__ uint64_t make_desc64(uint32_t addr) {
    const uint64_t base =
        (uint64_t(4) << 61) | (uint64_t(1) << 46) | (uint64_t(32) << 32) | (uint64_t(1) << 16);
    return base | ((uint64_t)(addr >> 4) & 0x3FFF);
}

// idesc kind::f16: cF32(1<<4) | aBF16(1<<7) | bBF16(1<<10) | N=128 (16<<17) | M=128 (8<<24)
#define IDESC_BF16 0x08200490u

// smem layout (bytes): header | 2 stages x [Ahi 8K | Alo 8K | Bhi 8K | Blo 8K]
#define SM_TMEMP 0
#define SM_FULL0 16
#define SM_FULL1 24
#define SM_EMPT0 32
#define SM_EMPT1 40
#define SM_PART  256
#define SM_TILES 2048
#define STG_SZ   32768
#define OFF_AHI  0
#define OFF_ALO  8192
#define OFF_BHI  16384
#define OFF_BLO  24576
#define SMEM_BYTES (SM_TILES + 2 * STG_SZ)

// pack two floats -> bf16x2 (lo index in low half)
__device__ __forceinline__ uint32_t pack_bf2(float a, float b) {
    __nv_bfloat162 h = __float22bfloat162_rn(make_float2(a, b));
    return *(uint32_t*)&h;
}

// ---------------- weight transpose + bf16 split + SW64 pre-swizzle ----------------
__global__ void split_w_k(const float* __restrict__ We, const float* __restrict__ W1,
                          const float* __restrict__ W2, const float* __restrict__ Wm)
{
    int i = blockIdx.x * 256 + threadIdx.x;
    if (i >= WT_TOTAL) return;
    int base, n, k, K;
    if (i < 49152)       { base = 0;      int j = i;          K = 384; n = j / K; k = j % K; }
    else if (i < 114688) { int j = i - 49152;  int l = j >> 14; base = 49152 + l*16384;  j &= 16383; K = 128; n = j >> 7; k = j & 127; }
    else if (i < 180224) { int j = i - 114688; int l = j >> 14; base = 114688 + l*16384; j &= 16383; K = 128; n = j >> 7; k = j & 127; }
    else                 { base = 180224; int j = i - 180224;  K = 192; n = j / K; k = j % K; }
    float v;
    if (base == 0)           v = We[k * 128 + n];
    else if (base < 114688)  v = W1[(base - 49152) / 16384 * 16384 + k * 128 + n];
    else if (base < 180224)  v = W2[(base - 114688) / 16384 * 16384 + k * 128 + n];
    else                     v = Wm[k * 128 + n];

    __nv_bfloat16 hi = __float2bfloat16_rn(v);
    __nv_bfloat16 lo = __float2bfloat16_rn(v - __bfloat162float(hi));
    int chunk = k >> 5, kk = k & 31;
    uint32_t off = (uint32_t)n * 64u + (uint32_t)kk * 2u;
    off ^= ((off >> 3) & 0x30);               // SW64 swizzle
    int di = base + chunk * 4096 + (int)(off >> 1);
    g_wbhi[di] = hi;
    g_wblo[di] = lo;
}

// ---------------- edge embedding -------------------------------------------------
__global__ __launch_bounds__(128) void edge_embed_k(
    const float* __restrict__ attr, const float* __restrict__ Wedge,
    const float* __restrict__ bedge)
{
    __shared__ float Ws[16 * 128];
    __shared__ float Ae[128 * 16];
    __shared__ float bs[128];
    const int tid = threadIdx.x;
    const int e0 = blockIdx.x * 128;
    for (int i = tid; i < 16 * 128; i += 128) Ws[i] = Wedge[i];
    bs[tid] = bedge[tid];
    for (int i = tid; i < 128 * 16; i += 128) Ae[i] = attr[(size_t)e0 * 16 + i];
    __syncthreads();
    for (int ee = 0; ee < 128; ee++) {
        float s = bs[tid];
        #pragma unroll
        for (int k = 0; k < 16; k++) s = fmaf(Ae[ee * 16 + k], Ws[k * 128 + tid], s);
        g_e[(size_t)(e0 + ee) * 128 + tid] = fmaxf(s, 0.f);
    }
}

// ---------------- scatter --------------------------------------------------------
__global__ __launch_bounds__(256) void scatter_k(
    const int* __restrict__ src, const int* __restrict__ dst)
{
    const int warp = (blockIdx.x * blockDim.x + threadIdx.x) >> 5;
    const int lane = threadIdx.x & 31;
    if (warp >= E_) return;
    const int s = src[warp];
    const int d = dst[warp];
    float4 xv = *(const float4*)(g_x + (size_t)s * 128 + lane * 4);
    float4 ev = *(const float4*)(g_e + (size_t)warp * 128 + lane * 4);
    float4 m;
    m.x = fmaxf(xv.x + ev.x, 0.f);
    m.y = fmaxf(xv.y + ev.y, 0.f);
    m.z = fmaxf(xv.z + ev.z, 0.f);
    m.w = fmaxf(xv.w + ev.w, 0.f);
    atomicAdd((float4*)(g_agg + (size_t)d * 128 + lane * 4), m);
}

// ---------------- pipelined tcgen05 bf16 GEMM (3xBF16 split) ----------------------
// 288 threads: warps 0-7 produce A tiles; tid 256 fetches B via cp.async.bulk and
// issues MMAs. 2-stage pipeline, chunk = 32 K-elems, SW64 K-major bf16 tiles.
// full barrier: 256 producer arrivals + issuer arrive.expect_tx(16KB) -> count 257.
template <int K, int MODE>
__global__ __launch_bounds__(288, 2) void tc_gemm_k(
    const float* __restrict__ A0, const float* __restrict__ A1,
    const float* __restrict__ A2, const int* __restrict__ n2g,
    const float* __restrict__ bias, const float* __restrict__ w2,
    const float* __restrict__ b2s, int woff)
{
#if HAS_TC
    extern __shared__ __align__(1024) char smem[];
    const uint32_t sb = smem_u32(smem);
    const int tid  = threadIdx.x;
    const int wid  = tid >> 5;
    const int lane = tid & 31;
    const int rowBase = blockIdx.x * 128;
    const int NCH = K / 32;

    if (wid == 0) { tc_alloc(sb + SM_TMEMP, 128); tc_relinquish(); }
    if (tid == 0) {
        mbar_init(sb + SM_FULL0, 257); mbar_init(sb + SM_FULL1, 257);
        mbar_init(sb + SM_EMPT0, 1);   mbar_init(sb + SM_EMPT1, 1);
    }
    __syncthreads();
    uint32_t tmem;
    asm volatile("ld.shared.b32 %0, [%1];" : "=r"(tmem) : "r"(sb + SM_TMEMP));

    if (tid < 256) {
        // -------------------- A producers --------------------
        const int row  = tid >> 1;
        const int r    = rowBase + row;
        const int half = tid & 1;                    // which 16-K half of the chunk
        uint32_t bo = (uint32_t)row * 64u + (uint32_t)half * 32u;
        const uint32_t sw0 = bo ^ ((bo >> 3) & 0x30);
        bo += 16u;
        const uint32_t sw1 = bo ^ ((bo >> 3) & 0x30);
        int gg = 0;
        if (MODE == 0) gg = __ldg(n2g + r);

        for (int c = 0; c < NCH; c++) {
            const int s = c & 1;
            const int kb = c * 32 + half * 16;
            // ---- prefetch 16 floats BEFORE buffer wait ----
            float4 av[4];
            if (MODE == 0) {
                const float* p = (kb < 128) ? A0 + (size_t)r * 128 + kb
                               : (kb < 256) ? A1 + (size_t)gg * 128 + (kb - 128)
                                            : A2 + (size_t)gg * 128 + (kb - 256);
                #pragma unroll
                for (int q = 0; q < 4; q++) av[q] = *(const float4*)(p + q * 4);
            } else if (MODE == 1) {
                size_t off = (size_t)r * 128 + kb;
                #pragma unroll
                for (int q = 0; q < 4; q++) {
                    float4 a = *(const float4*)(g_x + off + q * 4);
                    float4 g = *(const float4*)(g_agg + off + q * 4);
                    av[q] = make_float4(a.x + g.x, a.y + g.y, a.z + g.z, a.w + g.w);
                }
                #pragma unroll
                for (int q = 0; q < 4; q++)
                    *(float4*)(g_agg + off + q * 4) = make_float4(0.f, 0.f, 0.f, 0.f);
            } else if (MODE == 2) {
                const float* p = g_h + (size_t)r * 128 + kb;
                #pragma unroll
                for (int q = 0; q < 4; q++) av[q] = *(const float4*)(p + q * 4);
            } else {
                const float* p = (kb < 128) ? g_x + (size_t)r * 128 + kb
                                            : A0 + (size_t)r * 64 + (kb - 128);
                #pragma unroll
                for (int q = 0; q < 4; q++) av[q] = *(const float4*)(p + q * 4);
            }

            if (c >= 2) mbar_wait(sb + SM_EMPT0 + s * 8, ((c >> 1) + 1) & 1);

            // ---- bf16 hi/lo split ----
            const float* f = (const float*)av;
            uint32_t hi[8], lo[8];
            #pragma unroll
            for (int q = 0; q < 8; q++) {
                float a = f[2 * q], b = f[2 * q + 1];
                __nv_bfloat162 h = __float22bfloat162_rn(make_float2(a, b));
                hi[q] = *(uint32_t*)&h;
                float la = a - __bfloat162float(h.x);
                float lb = b - __bfloat162float(h.y);
                lo[q] = pack_bf2(la, lb);
            }
            char* stg = smem + SM_TILES + s * STG_SZ;
            *(uint4*)(stg + OFF_AHI + sw0) = *(uint4*)&hi[0];
            *(uint4*)(stg + OFF_AHI + sw1) = *(uint4*)&hi[4];
            *(uint4*)(stg + OFF_ALO + sw0) = *(uint4*)&lo[0];
            *(uint4*)(stg + OFF_ALO + sw1) = *(uint4*)&lo[4];

            fence_async_shared();
            mbar_arrive(sb + SM_FULL0 + s * 8);
        }
    } else if (tid == 256) {
        // ---------------- B fetch (bulk) + MMA issuer ----------------
        uint64_t dAhi[2], dAlo[2], dBhi[2], dBlo[2];
        #pragma unroll
        for (int s = 0; s < 2; s++) {
            uint32_t st = sb + SM_TILES + s * STG_SZ;
            dAhi[s] = make_desc64(st + OFF_AHI);
            dAlo[s] = make_desc64(st + OFF_ALO);
            dBhi[s] = make_desc64(st + OFF_BHI);
            dBlo[s] = make_desc64(st + OFF_BLO);
        }
        for (int c = 0; c < NCH; c++) {
            const int s = c & 1;
            if (c >= 2) mbar_wait(sb + SM_EMPT0 + s * 8, ((c >> 1) + 1) & 1);
            const uint32_t full = sb + SM_FULL0 + s * 8;
            mbar_arrive_tx(full, 16384);
            const uint32_t st = sb + SM_TILES + s * STG_SZ;
            bulk_g2s(st + OFF_BHI, g_wbhi + woff + c * 4096, 8192, full);
            bulk_g2s(st + OFF_BLO, g_wblo + woff + c * 4096, 8192, full);
            mbar_wait(full, (c >> 1) & 1);
            #pragma unroll
            for (int ks = 0; ks < 2; ks++) {
                const uint64_t o = ks * 2;
                int first = (c == 0 && ks == 0);
                mma_bf16(tmem, dAhi[s] + o, dBhi[s] + o, IDESC_BF16, first ? 0 : 1);
                mma_bf16(tmem, dAhi[s] + o, dBlo[s] + o, IDESC_BF16, 1);
                mma_bf16(tmem, dAlo[s] + o, dBhi[s] + o, IDESC_BF16, 1);
            }
            tc_commit(sb + SM_EMPT0 + s * 8);
        }
    }

    // -------------------- epilogue --------------------
    {
        const int L = NCH - 1;
        mbar_wait(sb + SM_EMPT0 + (L & 1) * 8, (L >> 1) & 1);
        tc_fence_after();
    }
    if (tid < 256) {
        const int sp = wid & 3;           // TMEM subpartition
        const int h  = wid >> 2;          // column half
        const int r  = rowBase + sp * 32 + lane;
        const int cb = h * 64;
        uint32_t regs[64];
        ldtm32(regs,      tmem + cb);
        ldtm32(regs + 32, tmem + cb + 32);
        tc_wait_ld();

        if (MODE == 3) {
            float p = 0.f;
            #pragma unroll
            for (int j = 0; j < 64; j++) {
                float t = fmaxf(__uint_as_float(regs[j]) + __ldg(bias + cb + j), 0.f);
                p = fmaf(t, __ldg(w2 + cb + j), p);
            }
            ((float*)(smem + SM_PART))[h * 128 + sp * 32 + lane] = p;
        } else {
            float* dstp = (MODE == 1) ? g_h : g_x;
            size_t base = (size_t)r * 128 + cb;
            #pragma unroll
            for (int j = 0; j < 64; j += 4) {
                float4 o;
                o.x = fmaxf(__uint_as_float(regs[j + 0]) + __ldg(bias + cb + j + 0), 0.f);
                o.y = fmaxf(__uint_as_float(regs[j + 1]) + __ldg(bias + cb + j + 1), 0.f);
                o.z = fmaxf(__uint_as_float(regs[j + 2]) + __ldg(bias + cb + j + 2), 0.f);
                o.w = fmaxf(__uint_as_float(regs[j + 3]) + __ldg(bias + cb + j + 3), 0.f);
                if (MODE == 2) {
                    float4 x0 = *(const float4*)(g_x + base + j);
                    o.x += x0.x; o.y += x0.y; o.z += x0.z; o.w += x0.w;
                }
                *(float4*)(dstp + base + j) = o;
            }
        }
    }
    __syncthreads();
    if (MODE == 3 && tid < 128) {
        const float* part = (const float*)(smem + SM_PART);
        g_logit[rowBase + tid] = part[tid] + part[128 + tid] + b2s[0];
    }
    if (wid == 0) tc_dealloc(tmem, 128);

#else  // ---------- naive fallback (family-PTX pass only; never executes) ----------
    const int tid = threadIdx.x;
    const int rowBase = blockIdx.x * 128;
    if (tid >= 128) return;
    __shared__ float col[128];
    for (int m = 0; m < 128; m++) {
        const int r = rowBase + m;
        float acc = 0.f;
        for (int k = 0; k < K; k++) {
            float a;
            if (MODE == 0) {
                if (k < 128) a = A0[(size_t)r * 128 + k];
                else {
                    int gg = n2g[r];
                    a = (k < 256) ? A1[(size_t)gg * 128 + (k - 128)]
                                  : A2[(size_t)gg * 128 + (k - 256)];
                }
            } else if (MODE == 1) {
                a = g_x[(size_t)r * 128 + k] + g_agg[(size_t)r * 128 + k];
            } else if (MODE == 2) {
                a = g_h[(size_t)r * 128 + k];
            } else {
                a = (k < 128) ? g_x[(size_t)r * 128 + k] : A0[(size_t)r * 64 + (k - 128)];
            }
            int chunk = k >> 5, kk = k & 31;
            uint32_t off = (uint32_t)tid * 64u + (uint32_t)kk * 2u;
            off ^= ((off >> 3) & 0x30);
            int di = woff + chunk * 4096 + (int)(off >> 1);
            float w = __bfloat162float(g_wbhi[di]) + __bfloat162float(g_wblo[di]);
            acc = fmaf(a, w, acc);
        }
        if (MODE == 3) {
            col[tid] = fmaxf(acc + bias[tid], 0.f) * w2[tid];
            __syncthreads();
            if (tid == 0) {
                float p = 0.f;
                for (int j = 0; j < 128; j++) p += col[j];
                g_logit[r] = p + b2s[0];
            }
            __syncthreads();
        } else if (MODE == 1) {
            g_h[(size_t)r * 128 + tid] = fmaxf(acc + bias[tid], 0.f);
        } else if (MODE == 2) {
            g_x[(size_t)r * 128 + tid] += fmaxf(acc + bias[tid], 0.f);
        } else {
            g_x[(size_t)r * 128 + tid] = fmaxf(acc + bias[tid], 0.f);
        }
    }
    if (MODE == 1) {
        __syncthreads();
        for (int i = tid; i < 128 * 128; i += 128)
            g_agg[(size_t)rowBase * 128 + i] = 0.f;
    }
#endif
}

// ---------------- segment softmax -------------------------------------------------
__global__ void zero_small_k() {
    int i = blockIdx.x * blockDim.x + threadIdx.x;
    if (i < NG) { g_menc[i] = 0u; g_den[i] = 0.f; }
}
__global__ void seg_max_k(const int* __restrict__ n2g) {
    int i = blockIdx.x * blockDim.x + threadIdx.x;
    if (i >= V_) return;
    atomicMax(&g_menc[n2g[i]], encf(g_logit[i]));
}
__global__ void seg_exp_k(const int* __restrict__ n2g, float* __restrict__ out) {
    int i = blockIdx.x * blockDim.x + threadIdx.x;
    if (i >= V_) return;
    int gg = n2g[i];
    float m = decf(g_menc[gg]);
    float ex = expf(g_logit[i] - m);
    out[i] = ex;
    atomicAdd(&g_den[gg], ex);
}
__global__ void seg_div_k(const int* __restrict__ n2g, float* __restrict__ out) {
    int i = blockIdx.x * blockDim.x + threadIdx.x;
    if (i >= V_) return;
    out[i] = out[i] / g_den[n2g[i]];
}

// ---------------- launch -----------------------------------------------------------
extern "C" void kernel_launch(void* const* d_in, const int* in_sizes, int n_in,
                              void* d_out, int out_size)
{
    const float* x_inp   = (const float*)d_in[0];
    const int*   eidx    = (const int*)  d_in[1];
    const float* eattr   = (const float*)d_in[2];
    const float* x_upd   = (const float*)d_in[3];
    const float* Zc      = (const float*)d_in[4];
    const float* Zb      = (const float*)d_in[5];
    const int*   n2g     = (const int*)  d_in[6];
    const float* W_emb   = (const float*)d_in[7];
    const float* b_emb   = (const float*)d_in[8];
    const float* W_edge  = (const float*)d_in[9];
    const float* b_edge  = (const float*)d_in[10];
    const float* W1      = (const float*)d_in[11];
    const float* b1      = (const float*)d_in[12];
    const float* W2      = (const float*)d_in[13];
    const float* b2      = (const float*)d_in[14];
    const float* W_mlp1  = (const float*)d_in[15];
    const float* b_mlp1  = (const float*)d_in[16];
    const float* W_mlp2  = (const float*)d_in[17];
    const float* b_mlp2  = (const float*)d_in[18];
    float* out = (float*)d_out;

    cudaFuncSetAttribute(tc_gemm_k<384, 0>, cudaFuncAttributeMaxDynamicSharedMemorySize, SMEM_BYTES);
    cudaFuncSetAttribute(tc_gemm_k<128, 1>, cudaFuncAttributeMaxDynamicSharedMemorySize, SMEM_BYTES);
    cudaFuncSetAttribute(tc_gemm_k<128, 2>, cudaFuncAttributeMaxDynamicSharedMemorySize, SMEM_BYTES);
    cudaFuncSetAttribute(tc_gemm_k<192, 3>, cudaFuncAttributeMaxDynamicSharedMemorySize, SMEM_BYTES);

    const int GB = V_ / 128;   // 2048 tiles

    split_w_k<<<(WT_TOTAL + 255) / 256, 256>>>(W_emb, W1, W2, W_mlp1);
    zero_small_k<<<(NG + 255) / 256, 256>>>();
    edge_embed_k<<<E_ / 128, 128>>>(eattr, W_edge, b_edge);

    tc_gemm_k<384, 0><<<GB, 288, SMEM_BYTES>>>(x_upd, Zc, Zb, n2g, b_emb,
                                               nullptr, nullptr, 0);
    for (int l = 0; l < 4; l++) {
        scatter_k<<<E_ / 8, 256>>>(eidx, eidx + E_);
        tc_gemm_k<128, 1><<<GB, 288, SMEM_BYTES>>>(nullptr, nullptr, nullptr, nullptr,
                                                   b1 + (size_t)l * 128, nullptr, nullptr,
                                                   49152 + l * 16384);
        tc_gemm_k<128, 2><<<GB, 288, SMEM_BYTES>>>(nullptr, nullptr, nullptr, nullptr,
                                                   b2 + (size_t)l * 128, nullptr, nullptr,
                                                   114688 + l * 16384);
    }
    tc_gemm_k<192, 3><<<GB, 288, SMEM_BYTES>>>(x_inp, nullptr, nullptr, nullptr,
                                               b_mlp1, W_mlp2, b_mlp2, 180224);

    seg_max_k<<<V_ / 256, 256>>>(n2g);
    seg_exp_k<<<V_ / 256, 256>>>(n2g, out);
    seg_div_k<<<V_ / 256, 256>>>(n2g, out);
}

// round 7
// speedup vs baseline: 2.3817x; 1.1431x over previous
#include <cuda_runtime.h>
#include <cuda_bf16.h>
#include <cstdint>

#define V_  262144
#define E_  524288
#define NG  8192
#define H_  128

// ---------------- tcgen05 feature gate ---------------------------------------------
#if defined(__CUDA_ARCH_FEAT_SM103_ALL) || defined(__CUDA_ARCH_FEAT_SM100_ALL) || defined(__CUDA_ARCH_FEAT_SM101_ALL)
#define HAS_TC 1
#endif
#if !defined(HAS_TC) && defined(__CUDA_ARCH_HAS_FEATURE__)
#if __CUDA_ARCH_HAS_FEATURE__(SM103_ALL)
#define HAS_TC 1
#endif
#endif
#ifndef HAS_TC
#define HAS_TC 0
#endif

// ---------------- scratch globals ------------------------------------------------
__device__ float    g_x[(size_t)V_ * H_];
__device__ float    g_e[(size_t)E_ * H_];
__device__ float    g_agg[(size_t)V_ * H_];   // stays zero between launches
__device__ float    g_logit[V_];
__device__ unsigned g_menc[NG];
__device__ float    g_den[NG];
// weights: transposed, bf16 hi/lo split, PRE-SWIZZLED (SW64) 32-K-chunk-contiguous
#define WT_TOTAL 204800
__device__ __align__(16) __nv_bfloat16 g_wbhi[WT_TOTAL];
__device__ __align__(16) __nv_bfloat16 g_wblo[WT_TOTAL];

// ---------------- PTX helpers -----------------------------------------------------
__device__ __forceinline__ uint32_t smem_u32(const void* p) {
    uint32_t a;
    asm("{ .reg .u64 t; cvta.to.shared.u64 t, %1; cvt.u32.u64 %0, t; }" : "=r"(a) : "l"(p));
    return a;
}
__device__ __forceinline__ void mbar_init(uint32_t mbar, uint32_t cnt) {
    asm volatile("mbarrier.init.shared.b64 [%0], %1;" :: "r"(mbar), "r"(cnt) : "memory");
}
__device__ __forceinline__ void mbar_arrive(uint32_t mbar) {
    asm volatile("mbarrier.arrive.shared.b64 _, [%0];" :: "r"(mbar) : "memory");
}
__device__ __forceinline__ void mbar_arrive_tx(uint32_t mbar, uint32_t tx) {
    asm volatile("mbarrier.arrive.expect_tx.shared.b64 _, [%0], %1;"
                 :: "r"(mbar), "r"(tx) : "memory");
}
__device__ __forceinline__ void mbar_wait(uint32_t mbar, uint32_t parity) {
    asm volatile(
        "{\n\t.reg .pred P;\n\tWL_%=:\n\t"
        "mbarrier.try_wait.parity.acquire.cta.shared::cta.b64 P, [%0], %1, 0x989680;\n\t"
        "@!P bra WL_%=;\n\t}" :: "r"(mbar), "r"(parity) : "memory");
}
__device__ __forceinline__ void fence_async_shared() {
    asm volatile("fence.proxy.async.shared::cta;" ::: "memory");
}
__device__ __forceinline__ void bulk_g2s(uint32_t dst, const void* src, uint32_t bytes,
                                         uint32_t mbar) {
    uint64_t gsrc;
    asm("cvta.to.global.u64 %0, %1;" : "=l"(gsrc) : "l"(src));
    asm volatile(
        "cp.async.bulk.shared::cta.global.mbarrier::complete_tx::bytes [%0], [%1], %2, [%3];"
        :: "r"(dst), "l"(gsrc), "r"(bytes), "r"(mbar) : "memory");
}

#if HAS_TC
__device__ __forceinline__ void mma_bf16(uint32_t d, uint64_t a, uint64_t b,
                                         uint32_t idesc, int acc) {
    asm volatile(
        "{\n\t.reg .pred p;\n\tsetp.ne.b32 p, %4, 0;\n\t"
        "tcgen05.mma.cta_group::1.kind::f16 [%0], %1, %2, %3, p;\n\t}"
        :: "r"(d), "l"(a), "l"(b), "r"(idesc), "r"(acc) : "memory");
}
__device__ __forceinline__ void tc_commit(uint32_t mbar) {
    asm volatile(
        "tcgen05.commit.cta_group::1.mbarrier::arrive::one.shared::cluster.b64 [%0];"
        :: "r"(mbar) : "memory");
}
__device__ __forceinline__ void tc_alloc(uint32_t smem_dst, uint32_t ncols) {
    asm volatile("tcgen05.alloc.cta_group::1.sync.aligned.shared::cta.b32 [%0], %1;"
                 :: "r"(smem_dst), "r"(ncols) : "memory");
}
__device__ __forceinline__ void tc_dealloc(uint32_t tmem, uint32_t ncols) {
    asm volatile("tcgen05.dealloc.cta_group::1.sync.aligned.b32 %0, %1;"
                 :: "r"(tmem), "r"(ncols));
}
__device__ __forceinline__ void tc_relinquish() {
    asm volatile("tcgen05.relinquish_alloc_permit.cta_group::1.sync.aligned;");
}
__device__ __forceinline__ void tc_fence_after() {
    asm volatile("tcgen05.fence::after_thread_sync;" ::: "memory");
}
__device__ __forceinline__ void tc_wait_ld() {
    asm volatile("tcgen05.wait::ld.sync.aligned;" ::: "memory");
}
__device__ __forceinline__ void ldtm32(uint32_t* r, uint32_t addr) {
    asm volatile(
        "tcgen05.ld.sync.aligned.32x32b.x32.b32 "
        "{%0, %1, %2, %3, %4, %5, %6, %7, %8, %9, %10, %11, %12, %13, %14, %15, "
        " %16, %17, %18, %19, %20, %21, %22, %23, %24, %25, %26, %27, %28, %29, %30, %31}, [%32];"
        : "=r"(r[0]), "=r"(r[1]), "=r"(r[2]), "=r"(r[3]), "=r"(r[4]), "=r"(r[5]),
          "=r"(r[6]), "=r"(r[7]), "=r"(r[8]), "=r"(r[9]), "=r"(r[10]), "=r"(r[11]),
          "=r"(r[12]), "=r"(r[13]), "=r"(r[14]), "=r"(r[15]), "=r"(r[16]), "=r"(r[17]),
          "=r"(r[18]), "=r"(r[19]), "=r"(r[20]), "=r"(r[21]), "=r"(r[22]), "=r"(r[23]),
          "=r"(r[24]), "=r"(r[25]), "=r"(r[26]), "=r"(r[27]), "=r"(r[28]), "=r"(r[29]),
          "=r"(r[30]), "=r"(r[31])
        : "r"(addr));
}
#endif  // HAS_TC

__device__ __forceinline__ unsigned encf(float f) {
    unsigned u = __float_as_uint(f);
    return (u & 0x80000000u) ? ~u : (u | 0x80000000u);
}
__device__ __forceinline__ float decf(unsigned u) {
    return (u & 0x80000000u) ? __uint_as_float(u & 0x7fffffffu) : __uint_as_float(~u);
}

// SW64 K-major descriptor: layout=4, version=1, SBO=32, LBO=1
static __device__ __forceinline__ uint64_t make_desc64(uint32_t addr) {
    const uint64_t base =
        (uint64_t(4) << 61) | (uint64_t(1) << 46) | (uint64_t(32) << 32) | (uint64_t(1) << 16);
    return base | ((uint64_t)(addr >> 4) & 0x3FFF);
}

// idesc kind::f16: cF32(1<<4) | aBF16(1<<7) | bBF16(1<<10) | N=128 (16<<17) | M=128 (8<<24)
#define IDESC_BF16 0x08200490u

// smem layout (bytes)
#define SM_TMEMP 0
#define SM_FULL0 16
#define SM_FULL1 24
#define SM_EMPT0 32
#define SM_EMPT1 40
#define SM_D1DN  48
#define SM_F2_0  56
#define SM_F2_1  64
#define SM_E2_0  72
#define SM_E2_1  80
#define SM_PART  256         // 512B: b1 copy (layer) / head partials
#define SM_TILES 2048
#define STG_SZ   32768
#define OFF_AHI  0
#define OFF_ALO  8192
#define OFF_BHI  16384
#define OFF_BLO  24576
#define SMEM_BYTES (SM_TILES + 2 * STG_SZ)

__device__ __forceinline__ uint32_t pack_bf2(float a, float b) {
    __nv_bfloat162 h = __float22bfloat162_rn(make_float2(a, b));
    return *(uint32_t*)&h;
}

// ---------------- weight transpose + bf16 split + SW64 pre-swizzle ----------------
__global__ void split_w_k(const float* __restrict__ We, const float* __restrict__ W1,
                          const float* __restrict__ W2, const float* __restrict__ Wm)
{
    int i = blockIdx.x * 256 + threadIdx.x;
    if (i >= WT_TOTAL) return;
    int base, n, k, K;
    if (i < 49152)       { base = 0;      int j = i;          K = 384; n = j / K; k = j % K; }
    else if (i < 114688) { int j = i - 49152;  int l = j >> 14; base = 49152 + l*16384;  j &= 16383; K = 128; n = j >> 7; k = j & 127; }
    else if (i < 180224) { int j = i - 114688; int l = j >> 14; base = 114688 + l*16384; j &= 16383; K = 128; n = j >> 7; k = j & 127; }
    else                 { base = 180224; int j = i - 180224;  K = 192; n = j / K; k = j % K; }
    float v;
    if (base == 0)           v = We[k * 128 + n];
    else if (base < 114688)  v = W1[(base - 49152) / 16384 * 16384 + k * 128 + n];
    else if (base < 180224)  v = W2[(base - 114688) / 16384 * 16384 + k * 128 + n];
    else                     v = Wm[k * 128 + n];

    __nv_bfloat16 hi = __float2bfloat16_rn(v);
    __nv_bfloat16 lo = __float2bfloat16_rn(v - __bfloat162float(hi));
    int chunk = k >> 5, kk = k & 31;
    uint32_t off = (uint32_t)n * 64u + (uint32_t)kk * 2u;
    off ^= ((off >> 3) & 0x30);               // SW64 swizzle
    int di = base + chunk * 4096 + (int)(off >> 1);
    g_wbhi[di] = hi;
    g_wblo[di] = lo;
}

// ---------------- edge embedding -------------------------------------------------
__global__ __launch_bounds__(128) void edge_embed_k(
    const float* __restrict__ attr, const float* __restrict__ Wedge,
    const float* __restrict__ bedge)
{
    __shared__ float Ws[16 * 128];
    __shared__ float Ae[128 * 16];
    __shared__ float bs[128];
    const int tid = threadIdx.x;
    const int e0 = blockIdx.x * 128;
    for (int i = tid; i < 16 * 128; i += 128) Ws[i] = Wedge[i];
    bs[tid] = bedge[tid];
    for (int i = tid; i < 128 * 16; i += 128) Ae[i] = attr[(size_t)e0 * 16 + i];
    __syncthreads();
    for (int ee = 0; ee < 128; ee++) {
        float s = bs[tid];
        #pragma unroll
        for (int k = 0; k < 16; k++) s = fmaf(Ae[ee * 16 + k], Ws[k * 128 + tid], s);
        g_e[(size_t)(e0 + ee) * 128 + tid] = fmaxf(s, 0.f);
    }
}

// ---------------- scatter --------------------------------------------------------
__global__ __launch_bounds__(256) void scatter_k(
    const int* __restrict__ src, const int* __restrict__ dst)
{
    const int warp = (blockIdx.x * blockDim.x + threadIdx.x) >> 5;
    const int lane = threadIdx.x & 31;
    if (warp >= E_) return;
    const int s = src[warp];
    const int d = dst[warp];
    float4 xv = *(const float4*)(g_x + (size_t)s * 128 + lane * 4);
    float4 ev = *(const float4*)(g_e + (size_t)warp * 128 + lane * 4);
    float4 m;
    m.x = fmaxf(xv.x + ev.x, 0.f);
    m.y = fmaxf(xv.y + ev.y, 0.f);
    m.z = fmaxf(xv.z + ev.z, 0.f);
    m.w = fmaxf(xv.w + ev.w, 0.f);
    atomicAdd((float4*)(g_agg + (size_t)d * 128 + lane * 4), m);
}

// ---------------- EMB / HEAD GEMM (pipeline, MODE 0 / 3) --------------------------
template <int K, int MODE>
__global__ __launch_bounds__(288, 2) void tc_gemm_k(
    const float* __restrict__ A0, const float* __restrict__ A1,
    const float* __restrict__ A2, const int* __restrict__ n2g,
    const float* __restrict__ bias, const float* __restrict__ w2,
    const float* __restrict__ b2s, int woff)
{
#if HAS_TC
    extern __shared__ __align__(1024) char smem[];
    const uint32_t sb = smem_u32(smem);
    const int tid  = threadIdx.x;
    const int wid  = tid >> 5;
    const int lane = tid & 31;
    const int rowBase = blockIdx.x * 128;
    const int NCH = K / 32;

    if (wid == 0) { tc_alloc(sb + SM_TMEMP, 128); tc_relinquish(); }
    if (tid == 0) {
        mbar_init(sb + SM_FULL0, 257); mbar_init(sb + SM_FULL1, 257);
        mbar_init(sb + SM_EMPT0, 1);   mbar_init(sb + SM_EMPT1, 1);
    }
    __syncthreads();
    uint32_t tmem;
    asm volatile("ld.shared.b32 %0, [%1];" : "=r"(tmem) : "r"(sb + SM_TMEMP));

    if (tid < 256) {
        const int row  = tid >> 1;
        const int r    = rowBase + row;
        const int half = tid & 1;
        uint32_t bo = (uint32_t)row * 64u + (uint32_t)half * 32u;
        const uint32_t sw0 = bo ^ ((bo >> 3) & 0x30);
        bo += 16u;
        const uint32_t sw1 = bo ^ ((bo >> 3) & 0x30);
        int gg = 0;
        if (MODE == 0) gg = __ldg(n2g + r);

        for (int c = 0; c < NCH; c++) {
            const int s = c & 1;
            const int kb = c * 32 + half * 16;
            float4 av[4];
            if (MODE == 0) {
                const float* p = (kb < 128) ? A0 + (size_t)r * 128 + kb
                               : (kb < 256) ? A1 + (size_t)gg * 128 + (kb - 128)
                                            : A2 + (size_t)gg * 128 + (kb - 256);
                #pragma unroll
                for (int q = 0; q < 4; q++) av[q] = *(const float4*)(p + q * 4);
            } else {
                const float* p = (kb < 128) ? g_x + (size_t)r * 128 + kb
                                            : A0 + (size_t)r * 64 + (kb - 128);
                #pragma unroll
                for (int q = 0; q < 4; q++) av[q] = *(const float4*)(p + q * 4);
            }

            if (c >= 2) mbar_wait(sb + SM_EMPT0 + s * 8, ((c >> 1) + 1) & 1);

            const float* f = (const float*)av;
            uint32_t hi[8], lo[8];
            #pragma unroll
            for (int q = 0; q < 8; q++) {
                float a = f[2 * q], b = f[2 * q + 1];
                __nv_bfloat162 h = __float22bfloat162_rn(make_float2(a, b));
                hi[q] = *(uint32_t*)&h;
                lo[q] = pack_bf2(a - __bfloat162float(h.x), b - __bfloat162float(h.y));
            }
            char* stg = smem + SM_TILES + s * STG_SZ;
            *(uint4*)(stg + OFF_AHI + sw0) = *(uint4*)&hi[0];
            *(uint4*)(stg + OFF_AHI + sw1) = *(uint4*)&hi[4];
            *(uint4*)(stg + OFF_ALO + sw0) = *(uint4*)&lo[0];
            *(uint4*)(stg + OFF_ALO + sw1) = *(uint4*)&lo[4];

            fence_async_shared();
            mbar_arrive(sb + SM_FULL0 + s * 8);
        }
    } else if (tid == 256) {
        uint64_t dAhi[2], dAlo[2], dBhi[2], dBlo[2];
        #pragma unroll
        for (int s = 0; s < 2; s++) {
            uint32_t st = sb + SM_TILES + s * STG_SZ;
            dAhi[s] = make_desc64(st + OFF_AHI);
            dAlo[s] = make_desc64(st + OFF_ALO);
            dBhi[s] = make_desc64(st + OFF_BHI);
            dBlo[s] = make_desc64(st + OFF_BLO);
        }
        for (int c = 0; c < NCH; c++) {
            const int s = c & 1;
            if (c >= 2) mbar_wait(sb + SM_EMPT0 + s * 8, ((c >> 1) + 1) & 1);
            const uint32_t full = sb + SM_FULL0 + s * 8;
            mbar_arrive_tx(full, 16384);
            const uint32_t st = sb + SM_TILES + s * STG_SZ;
            bulk_g2s(st + OFF_BHI, g_wbhi + woff + c * 4096, 8192, full);
            bulk_g2s(st + OFF_BLO, g_wblo + woff + c * 4096, 8192, full);
            mbar_wait(full, (c >> 1) & 1);
            #pragma unroll
            for (int ks = 0; ks < 2; ks++) {
                const uint64_t o = ks * 2;
                int first = (c == 0 && ks == 0);
                mma_bf16(tmem, dAhi[s] + o, dBhi[s] + o, IDESC_BF16, first ? 0 : 1);
                mma_bf16(tmem, dAhi[s] + o, dBlo[s] + o, IDESC_BF16, 1);
                mma_bf16(tmem, dAlo[s] + o, dBhi[s] + o, IDESC_BF16, 1);
            }
            tc_commit(sb + SM_EMPT0 + s * 8);
        }
    }

    {
        const int L = NCH - 1;
        mbar_wait(sb + SM_EMPT0 + (L & 1) * 8, (L >> 1) & 1);
        tc_fence_after();
    }
    if (tid < 256) {
        const int sp = wid & 3;
        const int h  = wid >> 2;
        const int r  = rowBase + sp * 32 + lane;
        const int cb = h * 64;
        uint32_t regs[64];
        ldtm32(regs,      tmem + cb);
        ldtm32(regs + 32, tmem + cb + 32);
        tc_wait_ld();

        if (MODE == 3) {
            float p = 0.f;
            #pragma unroll
            for (int j = 0; j < 64; j++) {
                float t = fmaxf(__uint_as_float(regs[j]) + __ldg(bias + cb + j), 0.f);
                p = fmaf(t, __ldg(w2 + cb + j), p);
            }
            ((float*)(smem + SM_PART))[h * 128 + sp * 32 + lane] = p;
        } else {
            size_t base = (size_t)r * 128 + cb;
            #pragma unroll
            for (int j = 0; j < 64; j += 4) {
                float4 o;
                o.x = fmaxf(__uint_as_float(regs[j + 0]) + __ldg(bias + cb + j + 0), 0.f);
                o.y = fmaxf(__uint_as_float(regs[j + 1]) + __ldg(bias + cb + j + 1), 0.f);
                o.z = fmaxf(__uint_as_float(regs[j + 2]) + __ldg(bias + cb + j + 2), 0.f);
                o.w = fmaxf(__uint_as_float(regs[j + 3]) + __ldg(bias + cb + j + 3), 0.f);
                *(float4*)(g_x + base + j) = o;
            }
        }
    }
    __syncthreads();
    if (MODE == 3 && tid < 128) {
        const float* part = (const float*)(smem + SM_PART);
        g_logit[rowBase + tid] = part[tid] + part[128 + tid] + b2s[0];
    }
    if (wid == 0) tc_dealloc(tmem, 128);

#else
    const int tid = threadIdx.x;
    const int rowBase = blockIdx.x * 128;
    if (tid >= 128) return;
    __shared__ float col[128];
    for (int m = 0; m < 128; m++) {
        const int r = rowBase + m;
        float acc = 0.f;
        for (int k = 0; k < K; k++) {
            float a;
            if (MODE == 0) {
                if (k < 128) a = A0[(size_t)r * 128 + k];
                else {
                    int gg = n2g[r];
                    a = (k < 256) ? A1[(size_t)gg * 128 + (k - 128)]
                                  : A2[(size_t)gg * 128 + (k - 256)];
                }
            } else {
                a = (k < 128) ? g_x[(size_t)r * 128 + k] : A0[(size_t)r * 64 + (k - 128)];
            }
            int chunk = k >> 5, kk = k & 31;
            uint32_t off = (uint32_t)tid * 64u + (uint32_t)kk * 2u;
            off ^= ((off >> 3) & 0x30);
            int di = woff + chunk * 4096 + (int)(off >> 1);
            float w = __bfloat162float(g_wbhi[di]) + __bfloat162float(g_wblo[di]);
            acc = fmaf(a, w, acc);
        }
        if (MODE == 3) {
            col[tid] = fmaxf(acc + bias[tid], 0.f) * w2[tid];
            __syncthreads();
            if (tid == 0) {
                float p = 0.f;
                for (int j = 0; j < 128; j++) p += col[j];
                g_logit[r] = p + b2s[0];
            }
            __syncthreads();
        } else {
            g_x[(size_t)r * 128 + tid] = fmaxf(acc + bias[tid], 0.f);
        }
    }
#endif
}

// ---------------- fused GINE layer: x += relu(relu((x+agg)W1+b1)W2+b2) ------------
__global__ __launch_bounds__(288, 2) void tc_layer_k(
    const float* __restrict__ b1, const float* __restrict__ b2,
    int woff1, int woff2)
{
#if HAS_TC
    extern __shared__ __align__(1024) char smem[];
    const uint32_t sb = smem_u32(smem);
    const int tid  = threadIdx.x;
    const int wid  = tid >> 5;
    const int lane = tid & 31;
    const int rowBase = blockIdx.x * 128;
    float* b1s = (float*)(smem + SM_PART);

    if (wid == 0) { tc_alloc(sb + SM_TMEMP, 256); tc_relinquish(); }
    if (tid == 0) {
        mbar_init(sb + SM_FULL0, 257); mbar_init(sb + SM_FULL1, 257);
        mbar_init(sb + SM_EMPT0, 1);   mbar_init(sb + SM_EMPT1, 1);
        mbar_init(sb + SM_D1DN, 1);
        mbar_init(sb + SM_F2_0, 129);  mbar_init(sb + SM_F2_1, 129);
        mbar_init(sb + SM_E2_0, 1);    mbar_init(sb + SM_E2_1, 1);
    }
    if (tid >= 128 && tid < 256) b1s[tid - 128] = b1[tid - 128];
    __syncthreads();
    uint32_t tmem;
    asm volatile("ld.shared.b32 %0, [%1];" : "=r"(tmem) : "r"(sb + SM_TMEMP));
    const uint32_t tmem2 = tmem + 128;

    // ================= phase 1: D1 = (x+agg) @ W1 =================
    if (tid < 256) {
        const int row  = tid >> 1;
        const int r    = rowBase + row;
        const int half = tid & 1;
        uint32_t bo = (uint32_t)row * 64u + (uint32_t)half * 32u;
        const uint32_t sw0 = bo ^ ((bo >> 3) & 0x30);
        bo += 16u;
        const uint32_t sw1 = bo ^ ((bo >> 3) & 0x30);

        for (int c = 0; c < 4; c++) {
            const int s = c & 1;
            const int kb = c * 32 + half * 16;
            size_t off = (size_t)r * 128 + kb;
            float4 av[4];
            #pragma unroll
            for (int q = 0; q < 4; q++) {
                float4 a = *(const float4*)(g_x + off + q * 4);
                float4 g = *(const float4*)(g_agg + off + q * 4);
                av[q] = make_float4(a.x + g.x, a.y + g.y, a.z + g.z, a.w + g.w);
            }
            #pragma unroll
            for (int q = 0; q < 4; q++)
                *(float4*)(g_agg + off + q * 4) = make_float4(0.f, 0.f, 0.f, 0.f);

            if (c >= 2) mbar_wait(sb + SM_EMPT0 + s * 8, 0);

            const float* f = (const float*)av;
            uint32_t hi[8], lo[8];
            #pragma unroll
            for (int q = 0; q < 8; q++) {
                float a = f[2 * q], b = f[2 * q + 1];
                __nv_bfloat162 h = __float22bfloat162_rn(make_float2(a, b));
                hi[q] = *(uint32_t*)&h;
                lo[q] = pack_bf2(a - __bfloat162float(h.x), b - __bfloat162float(h.y));
            }
            char* stg = smem + SM_TILES + s * STG_SZ;
            *(uint4*)(stg + OFF_AHI + sw0) = *(uint4*)&hi[0];
            *(uint4*)(stg + OFF_AHI + sw1) = *(uint4*)&hi[4];
            *(uint4*)(stg + OFF_ALO + sw0) = *(uint4*)&lo[0];
            *(uint4*)(stg + OFF_ALO + sw1) = *(uint4*)&lo[4];

            fence_async_shared();
            mbar_arrive(sb + SM_FULL0 + s * 8);
        }
    } else if (tid == 256) {
        uint64_t dAhi[2], dAlo[2], dBhi[2], dBlo[2];
        #pragma unroll
        for (int s = 0; s < 2; s++) {
            uint32_t st = sb + SM_TILES + s * STG_SZ;
            dAhi[s] = make_desc64(st + OFF_AHI);
            dAlo[s] = make_desc64(st + OFF_ALO);
            dBhi[s] = make_desc64(st + OFF_BHI);
            dBlo[s] = make_desc64(st + OFF_BLO);
        }
        for (int c = 0; c < 4; c++) {
            const int s = c & 1;
            if (c >= 2) mbar_wait(sb + SM_EMPT0 + s * 8, 0);
            const uint32_t full = sb + SM_FULL0 + s * 8;
            mbar_arrive_tx(full, 16384);
            const uint32_t st = sb + SM_TILES + s * STG_SZ;
            bulk_g2s(st + OFF_BHI, g_wbhi + woff1 + c * 4096, 8192, full);
            bulk_g2s(st + OFF_BLO, g_wblo + woff1 + c * 4096, 8192, full);
            mbar_wait(full, (c >> 1) & 1);
            #pragma unroll
            for (int ks = 0; ks < 2; ks++) {
                const uint64_t o = ks * 2;
                int first = (c == 0 && ks == 0);
                mma_bf16(tmem, dAhi[s] + o, dBhi[s] + o, IDESC_BF16, first ? 0 : 1);
                mma_bf16(tmem, dAhi[s] + o, dBlo[s] + o, IDESC_BF16, 1);
                mma_bf16(tmem, dAlo[s] + o, dBhi[s] + o, IDESC_BF16, 1);
            }
            tc_commit(sb + SM_EMPT0 + s * 8);
        }
        tc_commit(sb + SM_D1DN);
    }

    // ================= phase 2: D2 = relu(D1+b1) @ W2 =================
    mbar_wait(sb + SM_D1DN, 0);
    tc_fence_after();

    if (tid < 256) {
        // warp w: subpartition sp = w&3 (TMEM rows sp*32..), chunk group grp = w>>2
        const int sp  = wid & 3;
        const int grp = wid >> 2;
        const int r   = sp * 32 + lane;           // row within tile
        #pragma unroll
        for (int it = 0; it < 2; it++) {
            const int c = grp + it * 2;           // chunks: 0,2 (grp0) / 1,3 (grp1)
            const int s = c & 1;
            if (it == 1) mbar_wait(sb + SM_E2_0 + s * 8, 0);

            uint32_t regs[32];
            ldtm32(regs, tmem + c * 32);
            tc_wait_ld();

            // relu(D1 + b1) -> bf16 hi/lo, full 32 columns of this row
            uint32_t hi[16], lo[16];
            #pragma unroll
            for (int q = 0; q < 16; q++) {
                float a = fmaxf(__uint_as_float(regs[2 * q])     + b1s[c * 32 + 2 * q],     0.f);
                float b = fmaxf(__uint_as_float(regs[2 * q + 1]) + b1s[c * 32 + 2 * q + 1], 0.f);
                __nv_bfloat162 h = __float22bfloat162_rn(make_float2(a, b));
                hi[q] = *(uint32_t*)&h;
                lo[q] = pack_bf2(a - __bfloat162float(h.x), b - __bfloat162float(h.y));
            }
            char* stg = smem + SM_TILES + s * STG_SZ;
            const uint32_t bo0 = (uint32_t)r * 64u;
            #pragma unroll
            for (int q = 0; q < 4; q++) {
                uint32_t o = bo0 + q * 16u;
                o ^= ((o >> 3) & 0x30);
                *(uint4*)(stg + OFF_AHI + o) = *(uint4*)&hi[q * 4];
                *(uint4*)(stg + OFF_ALO + o) = *(uint4*)&lo[q * 4];
            }
            fence_async_shared();
            mbar_arrive(sb + SM_F2_0 + s * 8);
        }
    } else if (tid == 256) {
        uint64_t dAhi[2], dAlo[2], dBhi[2], dBlo[2];
        #pragma unroll
        for (int s = 0; s < 2; s++) {
            uint32_t st = sb + SM_TILES + s * STG_SZ;
            dAhi[s] = make_desc64(st + OFF_AHI);
            dAlo[s] = make_desc64(st + OFF_ALO);
            dBhi[s] = make_desc64(st + OFF_BHI);
            dBlo[s] = make_desc64(st + OFF_BLO);
        }
        for (int c = 0; c < 4; c++) {
            const int s = c & 1;
            if (c >= 2) mbar_wait(sb + SM_E2_0 + s * 8, 0);
            const uint32_t full = sb + SM_F2_0 + s * 8;
            mbar_arrive_tx(full, 16384);
            const uint32_t st = sb + SM_TILES + s * STG_SZ;
            bulk_g2s(st + OFF_BHI, g_wbhi + woff2 + c * 4096, 8192, full);
            bulk_g2s(st + OFF_BLO, g_wblo + woff2 + c * 4096, 8192, full);
            mbar_wait(full, (c >> 1) & 1);
            #pragma unroll
            for (int ks = 0; ks < 2; ks++) {
                const uint64_t o = ks * 2;
                int first = (c == 0 && ks == 0);
                mma_bf16(tmem2, dAhi[s] + o, dBhi[s] + o, IDESC_BF16, first ? 0 : 1);
                mma_bf16(tmem2, dAhi[s] + o, dBlo[s] + o, IDESC_BF16, 1);
                mma_bf16(tmem2, dAlo[s] + o, dBhi[s] + o, IDESC_BF16, 1);
            }
            tc_commit(sb + SM_E2_0 + s * 8);
        }
    }

    // ================= epilogue: g_x += relu(D2 + b2) =================
    mbar_wait(sb + SM_E2_0, 1);
    mbar_wait(sb + SM_E2_1, 1);
    tc_fence_after();
    if (tid < 256) {
        const int sp = wid & 3;
        const int h  = wid >> 2;
        const int r  = rowBase + sp * 32 + lane;
        const int cb = h * 64;
        uint32_t regs[64];
        ldtm32(regs,      tmem2 + cb);
        ldtm32(regs + 32, tmem2 + cb + 32);
        tc_wait_ld();
        size_t base = (size_t)r * 128 + cb;
        #pragma unroll
        for (int j = 0; j < 64; j += 4) {
            float4 o;
            o.x = fmaxf(__uint_as_float(regs[j + 0]) + __ldg(b2 + cb + j + 0), 0.f);
            o.y = fmaxf(__uint_as_float(regs[j + 1]) + __ldg(b2 + cb + j + 1), 0.f);
            o.z = fmaxf(__uint_as_float(regs[j + 2]) + __ldg(b2 + cb + j + 2), 0.f);
            o.w = fmaxf(__uint_as_float(regs[j + 3]) + __ldg(b2 + cb + j + 3), 0.f);
            float4 x0 = *(const float4*)(g_x + base + j);
            o.x += x0.x; o.y += x0.y; o.z += x0.z; o.w += x0.w;
            *(float4*)(g_x + base + j) = o;
        }
    }
    __syncthreads();
    if (wid == 0) tc_dealloc(tmem, 256);

#else  // ---------- naive fallback (family-PTX pass only; never executes) ----------
    const int tid = threadIdx.x;
    const int rowBase = blockIdx.x * 128;
    if (tid >= 128) return;
    __shared__ float hrow[128];
    for (int m = 0; m < 128; m++) {
        const int r = rowBase + m;
        float acc = 0.f;
        for (int k = 0; k < 128; k++) {
            float a = g_x[(size_t)r * 128 + k] + g_agg[(size_t)r * 128 + k];
            int chunk = k >> 5, kk = k & 31;
            uint32_t off = (uint32_t)tid * 64u + (uint32_t)kk * 2u;
            off ^= ((off >> 3) & 0x30);
            int di = woff1 + chunk * 4096 + (int)(off >> 1);
            acc = fmaf(a, __bfloat162float(g_wbhi[di]) + __bfloat162float(g_wblo[di]), acc);
        }
        hrow[tid] = fmaxf(acc + b1[tid], 0.f);
        __syncthreads();
        float acc2 = 0.f;
        for (int k = 0; k < 128; k++) {
            int chunk = k >> 5, kk = k & 31;
            uint32_t off = (uint32_t)tid * 64u + (uint32_t)kk * 2u;
            off ^= ((off >> 3) & 0x30);
            int di = woff2 + chunk * 4096 + (int)(off >> 1);
            acc2 = fmaf(hrow[k], __bfloat162float(g_wbhi[di]) + __bfloat162float(g_wblo[di]), acc2);
        }
        g_x[(size_t)r * 128 + tid] += fmaxf(acc2 + b2[tid], 0.f);
        __syncthreads();
    }
    for (int i = tid; i < 128 * 128; i += 128)
        g_agg[(size_t)rowBase * 128 + i] = 0.f;
#endif
}

// ---------------- segment softmax -------------------------------------------------
__global__ void zero_small_k() {
    int i = blockIdx.x * blockDim.x + threadIdx.x;
    if (i < NG) { g_menc[i] = 0u; g_den[i] = 0.f; }
}
__global__ void seg_max_k(const int* __restrict__ n2g) {
    int i = blockIdx.x * blockDim.x + threadIdx.x;
    if (i >= V_) return;
    atomicMax(&g_menc[n2g[i]], encf(g_logit[i]));
}
__global__ void seg_exp_k(const int* __restrict__ n2g, float* __restrict__ out) {
    int i = blockIdx.x * blockDim.x + threadIdx.x;
    if (i >= V_) return;
    int gg = n2g[i];
    float m = decf(g_menc[gg]);
    float ex = expf(g_logit[i] - m);
    out[i] = ex;
    atomicAdd(&g_den[gg], ex);
}
__global__ void seg_div_k(const int* __restrict__ n2g, float* __restrict__ out) {
    int i = blockIdx.x * blockDim.x + threadIdx.x;
    if (i >= V_) return;
    out[i] = out[i] / g_den[n2g[i]];
}

// ---------------- launch -----------------------------------------------------------
extern "C" void kernel_launch(void* const* d_in, const int* in_sizes, int n_in,
                              void* d_out, int out_size)
{
    const float* x_inp   = (const float*)d_in[0];
    const int*   eidx    = (const int*)  d_in[1];
    const float* eattr   = (const float*)d_in[2];
    const float* x_upd   = (const float*)d_in[3];
    const float* Zc      = (const float*)d_in[4];
    const float* Zb      = (const float*)d_in[5];
    const int*   n2g     = (const int*)  d_in[6];
    const float* W_emb   = (const float*)d_in[7];
    const float* b_emb   = (const float*)d_in[8];
    const float* W_edge  = (const float*)d_in[9];
    const float* b_edge  = (const float*)d_in[10];
    const float* W1      = (const float*)d_in[11];
    const float* b1      = (const float*)d_in[12];
    const float* W2      = (const float*)d_in[13];
    const float* b2      = (const float*)d_in[14];
    const float* W_mlp1  = (const float*)d_in[15];
    const float* b_mlp1  = (const float*)d_in[16];
    const float* W_mlp2  = (const float*)d_in[17];
    const float* b_mlp2  = (const float*)d_in[18];
    float* out = (float*)d_out;

    cudaFuncSetAttribute(tc_gemm_k<384, 0>, cudaFuncAttributeMaxDynamicSharedMemorySize, SMEM_BYTES);
    cudaFuncSetAttribute(tc_gemm_k<192, 3>, cudaFuncAttributeMaxDynamicSharedMemorySize, SMEM_BYTES);
    cudaFuncSetAttribute(tc_layer_k,        cudaFuncAttributeMaxDynamicSharedMemorySize, SMEM_BYTES);

    const int GB = V_ / 128;   // 2048 tiles

    split_w_k<<<(WT_TOTAL + 255) / 256, 256>>>(W_emb, W1, W2, W_mlp1);
    zero_small_k<<<(NG + 255) / 256, 256>>>();
    edge_embed_k<<<E_ / 128, 128>>>(eattr, W_edge, b_edge);

    tc_gemm_k<384, 0><<<GB, 288, SMEM_BYTES>>>(x_upd, Zc, Zb, n2g, b_emb,
                                               nullptr, nullptr, 0);
    for (int l = 0; l < 4; l++) {
        scatter_k<<<E_ / 8, 256>>>(eidx, eidx + E_);
        tc_layer_k<<<GB, 288, SMEM_BYTES>>>(b1 + (size_t)l * 128, b2 + (size_t)l * 128,
                                            49152 + l * 16384, 114688 + l * 16384);
    }
    tc_gemm_k<192, 3><<<GB, 288, SMEM_BYTES>>>(x_inp, nullptr, nullptr, nullptr,
                                               b_mlp1, W_mlp2, b_mlp2, 180224);

    seg_max_k<<<V_ / 256, 256>>>(n2g);
    seg_exp_k<<<V_ / 256, 256>>>(n2g, out);
    seg_div_k<<<V_ / 256, 256>>>(n2g, out);
}

// round 8
// speedup vs baseline: 3.5113x; 1.4742x over previous
#include <cuda_runtime.h>
#include <cuda_bf16.h>
#include <cstdint>

#define V_  262144
#define E_  524288
#define NG  8192
#define H_  128

// ---------------- tcgen05 feature gate ---------------------------------------------
#if defined(__CUDA_ARCH_FEAT_SM103_ALL) || defined(__CUDA_ARCH_FEAT_SM100_ALL) || defined(__CUDA_ARCH_FEAT_SM101_ALL)
#define HAS_TC 1
#endif
#if !defined(HAS_TC) && defined(__CUDA_ARCH_HAS_FEATURE__)
#if __CUDA_ARCH_HAS_FEATURE__(SM103_ALL)
#define HAS_TC 1
#endif
#endif
#ifndef HAS_TC
#define HAS_TC 0
#endif

// ---------------- scratch globals ------------------------------------------------
__device__ float    g_x[(size_t)V_ * H_];
__device__ float    g_e[(size_t)E_ * H_];
__device__ float    g_agg[(size_t)V_ * H_];   // stays zero between launches
__device__ float    g_logit[V_];
__device__ unsigned g_menc[NG];
__device__ float    g_den[NG];
// weights: transposed, bf16 hi/lo split, PRE-SWIZZLED (SW64) 32-K-chunk-contiguous
#define WT_TOTAL 204800
__device__ __align__(16) __nv_bfloat16 g_wbhi[WT_TOTAL];
__device__ __align__(16) __nv_bfloat16 g_wblo[WT_TOTAL];

// ---------------- PTX helpers -----------------------------------------------------
__device__ __forceinline__ uint32_t smem_u32(const void* p) {
    uint32_t a;
    asm("{ .reg .u64 t; cvta.to.shared.u64 t, %1; cvt.u32.u64 %0, t; }" : "=r"(a) : "l"(p));
    return a;
}
__device__ __forceinline__ void mbar_init(uint32_t mbar, uint32_t cnt) {
    asm volatile("mbarrier.init.shared.b64 [%0], %1;" :: "r"(mbar), "r"(cnt) : "memory");
}
__device__ __forceinline__ void mbar_arrive(uint32_t mbar) {
    asm volatile("mbarrier.arrive.shared.b64 _, [%0];" :: "r"(mbar) : "memory");
}
__device__ __forceinline__ void mbar_arrive_tx(uint32_t mbar, uint32_t tx) {
    asm volatile("mbarrier.arrive.expect_tx.shared.b64 _, [%0], %1;"
                 :: "r"(mbar), "r"(tx) : "memory");
}
__device__ __forceinline__ void mbar_wait(uint32_t mbar, uint32_t parity) {
    asm volatile(
        "{\n\t.reg .pred P;\n\tWL_%=:\n\t"
        "mbarrier.try_wait.parity.acquire.cta.shared::cta.b64 P, [%0], %1, 0x989680;\n\t"
        "@!P bra WL_%=;\n\t}" :: "r"(mbar), "r"(parity) : "memory");
}
__device__ __forceinline__ void fence_async_shared() {
    asm volatile("fence.proxy.async.shared::cta;" ::: "memory");
}
__device__ __forceinline__ void bulk_g2s(uint32_t dst, const void* src, uint32_t bytes,
                                         uint32_t mbar) {
    uint64_t gsrc;
    asm("cvta.to.global.u64 %0, %1;" : "=l"(gsrc) : "l"(src));
    asm volatile(
        "cp.async.bulk.shared::cta.global.mbarrier::complete_tx::bytes [%0], [%1], %2, [%3];"
        :: "r"(dst), "l"(gsrc), "r"(bytes), "r"(mbar) : "memory");
}

#if HAS_TC
__device__ __forceinline__ void mma_bf16(uint32_t d, uint64_t a, uint64_t b,
                                         uint32_t idesc, int acc) {
    asm volatile(
        "{\n\t.reg .pred p;\n\tsetp.ne.b32 p, %4, 0;\n\t"
        "tcgen05.mma.cta_group::1.kind::f16 [%0], %1, %2, %3, p;\n\t}"
        :: "r"(d), "l"(a), "l"(b), "r"(idesc), "r"(acc) : "memory");
}
__device__ __forceinline__ void tc_commit(uint32_t mbar) {
    asm volatile(
        "tcgen05.commit.cta_group::1.mbarrier::arrive::one.shared::cluster.b64 [%0];"
        :: "r"(mbar) : "memory");
}
__device__ __forceinline__ void tc_alloc(uint32_t smem_dst, uint32_t ncols) {
    asm volatile("tcgen05.alloc.cta_group::1.sync.aligned.shared::cta.b32 [%0], %1;"
                 :: "r"(smem_dst), "r"(ncols) : "memory");
}
__device__ __forceinline__ void tc_dealloc(uint32_t tmem, uint32_t ncols) {
    asm volatile("tcgen05.dealloc.cta_group::1.sync.aligned.b32 %0, %1;"
                 :: "r"(tmem), "r"(ncols));
}
__device__ __forceinline__ void tc_relinquish() {
    asm volatile("tcgen05.relinquish_alloc_permit.cta_group::1.sync.aligned;");
}
__device__ __forceinline__ void tc_fence_after() {
    asm volatile("tcgen05.fence::after_thread_sync;" ::: "memory");
}
__device__ __forceinline__ void tc_wait_ld() {
    asm volatile("tcgen05.wait::ld.sync.aligned;" ::: "memory");
}
__device__ __forceinline__ void ldtm32(uint32_t* r, uint32_t addr) {
    asm volatile(
        "tcgen05.ld.sync.aligned.32x32b.x32.b32 "
        "{%0, %1, %2, %3, %4, %5, %6, %7, %8, %9, %10, %11, %12, %13, %14, %15, "
        " %16, %17, %18, %19, %20, %21, %22, %23, %24, %25, %26, %27, %28, %29, %30, %31}, [%32];"
        : "=r"(r[0]), "=r"(r[1]), "=r"(r[2]), "=r"(r[3]), "=r"(r[4]), "=r"(r[5]),
          "=r"(r[6]), "=r"(r[7]), "=r"(r[8]), "=r"(r[9]), "=r"(r[10]), "=r"(r[11]),
          "=r"(r[12]), "=r"(r[13]), "=r"(r[14]), "=r"(r[15]), "=r"(r[16]), "=r"(r[17]),
          "=r"(r[18]), "=r"(r[19]), "=r"(r[20]), "=r"(r[21]), "=r"(r[22]), "=r"(r[23]),
          "=r"(r[24]), "=r"(r[25]), "=r"(r[26]), "=r"(r[27]), "=r"(r[28]), "=r"(r[29]),
          "=r"(r[30]), "=r"(r[31])
        : "r"(addr));
}
__device__ __forceinline__ void ldtm16(uint32_t* r, uint32_t addr) {
    asm volatile(
        "tcgen05.ld.sync.aligned.32x32b.x16.b32 "
        "{%0, %1, %2, %3, %4, %5, %6, %7, %8, %9, %10, %11, %12, %13, %14, %15}, [%16];"
        : "=r"(r[0]), "=r"(r[1]), "=r"(r[2]), "=r"(r[3]), "=r"(r[4]), "=r"(r[5]),
          "=r"(r[6]), "=r"(r[7]), "=r"(r[8]), "=r"(r[9]), "=r"(r[10]), "=r"(r[11]),
          "=r"(r[12]), "=r"(r[13]), "=r"(r[14]), "=r"(r[15])
        : "r"(addr));
}
#endif  // HAS_TC

__device__ __forceinline__ unsigned encf(float f) {
    unsigned u = __float_as_uint(f);
    return (u & 0x80000000u) ? ~u : (u | 0x80000000u);
}
__device__ __forceinline__ float decf(unsigned u) {
    return (u & 0x80000000u) ? __uint_as_float(u & 0x7fffffffu) : __uint_as_float(~u);
}

// SW64 K-major descriptor: layout=4, version=1, SBO=32, LBO=1
static __device__ __forceinline__ uint64_t make_desc64(uint32_t addr) {
    const uint64_t base =
        (uint64_t(4) << 61) | (uint64_t(1) << 46) | (uint64_t(32) << 32) | (uint64_t(1) << 16);
    return base | ((uint64_t)(addr >> 4) & 0x3FFF);
}

// idesc kind::f16: cF32(1<<4) | aBF16(1<<7) | bBF16(1<<10) | N=128 (16<<17) | M=128 (8<<24)
#define IDESC_BF16 0x08200490u

// ------- streaming GEMM smem layout (EMB / HEAD) -------
#define SM_TMEMP 0
#define SM_FULL0 16
#define SM_FULL1 24
#define SM_EMPT0 32
#define SM_EMPT1 40
#define SM_PART  256
#define SM_TILES 2048
#define STG_SZ   32768
#define OFF_AHI  0
#define OFF_ALO  8192
#define OFF_BHI  16384
#define OFF_BLO  24576
#define SMEM_GEMM (SM_TILES + 2 * STG_SZ)

// ------- fused layer smem layout (resident B) -------
#define L_FULL0 16
#define L_FULL1 24
#define L_EMPT0 32
#define L_EMPT1 40
#define L_D1DN  48
#define L_F2_0  56
#define L_F2_1  64
#define L_E2_0  72
#define L_E2_1  80
#define L_WBAR  88
#define L_B1S   128          // 512B
#define L_ASTG  1024         // + s*16384 : Ahi 8K | Alo 8K
#define L_WHI   33792        // 32KB resident W hi
#define L_WLO   66560        // 32KB resident W lo
#define SMEM_LAYER 99328

__device__ __forceinline__ uint32_t pack_bf2(float a, float b) {
    __nv_bfloat162 h = __float22bfloat162_rn(make_float2(a, b));
    return *(uint32_t*)&h;
}

// ---------------- weight split (+ softmax scratch zero) ---------------------------
__global__ void split_w_k(const float* __restrict__ We, const float* __restrict__ W1,
                          const float* __restrict__ W2, const float* __restrict__ Wm)
{
    int i = blockIdx.x * 256 + threadIdx.x;
    if (i >= WT_TOTAL) return;
    if (i < NG) { g_menc[i] = 0u; g_den[i] = 0.f; }
    int base, n, k, K;
    if (i < 49152)       { base = 0;      int j = i;          K = 384; n = j / K; k = j % K; }
    else if (i < 114688) { int j = i - 49152;  int l = j >> 14; base = 49152 + l*16384;  j &= 16383; K = 128; n = j >> 7; k = j & 127; }
    else if (i < 180224) { int j = i - 114688; int l = j >> 14; base = 114688 + l*16384; j &= 16383; K = 128; n = j >> 7; k = j & 127; }
    else                 { base = 180224; int j = i - 180224;  K = 192; n = j / K; k = j % K; }
    float v;
    if (base == 0)           v = We[k * 128 + n];
    else if (base < 114688)  v = W1[(base - 49152) / 16384 * 16384 + k * 128 + n];
    else if (base < 180224)  v = W2[(base - 114688) / 16384 * 16384 + k * 128 + n];
    else                     v = Wm[k * 128 + n];

    __nv_bfloat16 hi = __float2bfloat16_rn(v);
    __nv_bfloat16 lo = __float2bfloat16_rn(v - __bfloat162float(hi));
    int chunk = k >> 5, kk = k & 31;
    uint32_t off = (uint32_t)n * 64u + (uint32_t)kk * 2u;
    off ^= ((off >> 3) & 0x30);               // SW64 swizzle
    int di = base + chunk * 4096 + (int)(off >> 1);
    g_wbhi[di] = hi;
    g_wblo[di] = lo;
}

// ---------------- scatter --------------------------------------------------------
__global__ __launch_bounds__(256) void scatter_k(
    const int* __restrict__ src, const int* __restrict__ dst)
{
    const int warp = (blockIdx.x * blockDim.x + threadIdx.x) >> 5;
    const int lane = threadIdx.x & 31;
    if (warp >= E_) return;
    const int s = src[warp];
    const int d = dst[warp];
    float4 xv = *(const float4*)(g_x + (size_t)s * 128 + lane * 4);
    float4 ev = *(const float4*)(g_e + (size_t)warp * 128 + lane * 4);
    float4 m;
    m.x = fmaxf(xv.x + ev.x, 0.f);
    m.y = fmaxf(xv.y + ev.y, 0.f);
    m.z = fmaxf(xv.z + ev.z, 0.f);
    m.w = fmaxf(xv.w + ev.w, 0.f);
    atomicAdd((float4*)(g_agg + (size_t)d * 128 + lane * 4), m);
}

// ---------------- EMB(+edge blocks) / HEAD GEMM (streaming B pipeline) ------------
// MODE 0: grid = 2048 GEMM tiles + 2048 edge blocks (256 edges each).
//   edge blocks compute g_e = relu(attr @ W_edge + b_edge); Wedge passed via w2,
//   bedge via b2s, attr via eattr.
// MODE 3: head, grid 2048.
template <int K, int MODE>
__global__ __launch_bounds__(288, 2) void tc_gemm_k(
    const float* __restrict__ A0, const float* __restrict__ A1,
    const float* __restrict__ A2, const int* __restrict__ n2g,
    const float* __restrict__ bias, const float* __restrict__ w2,
    const float* __restrict__ b2s, const float* __restrict__ eattr, int woff)
{
    extern __shared__ __align__(1024) char smem[];
    const int tid  = threadIdx.x;

    // ---------------- edge-embedding blocks (MODE 0 only) ----------------
    if (MODE == 0 && blockIdx.x >= V_ / 128) {
        const int eb = blockIdx.x - V_ / 128;
        const int e0 = eb * 256;
        float* Ws = (float*)smem;                 // 2048 floats
        float* Ae = (float*)(smem + 8192);        // 4096 floats
        float* bs = (float*)(smem + 24576);       // 128 floats
        for (int i = tid; i < 2048; i += 288) Ws[i] = w2[i];
        for (int i = tid; i < 4096; i += 288) Ae[i] = eattr[(size_t)e0 * 16 + i];
        if (tid < 128) bs[tid] = b2s[tid];
        __syncthreads();
        if (tid < 256) {
            const int col = tid & 127, half = tid >> 7;
            float w[16];
            #pragma unroll
            for (int k = 0; k < 16; k++) w[k] = Ws[k * 128 + col];
            const float bb = bs[col];
            for (int ee = 0; ee < 128; ee++) {
                const int e = half * 128 + ee;
                const float4* a4 = (const float4*)&Ae[e * 16];
                float4 x0 = a4[0], x1 = a4[1], x2 = a4[2], x3 = a4[3];
                float s = bb;
                s = fmaf(x0.x, w[0],  s); s = fmaf(x0.y, w[1],  s);
                s = fmaf(x0.z, w[2],  s); s = fmaf(x0.w, w[3],  s);
                s = fmaf(x1.x, w[4],  s); s = fmaf(x1.y, w[5],  s);
                s = fmaf(x1.z, w[6],  s); s = fmaf(x1.w, w[7],  s);
                s = fmaf(x2.x, w[8],  s); s = fmaf(x2.y, w[9],  s);
                s = fmaf(x2.z, w[10], s); s = fmaf(x2.w, w[11], s);
                s = fmaf(x3.x, w[12], s); s = fmaf(x3.y, w[13], s);
                s = fmaf(x3.z, w[14], s); s = fmaf(x3.w, w[15], s);
                g_e[(size_t)(e0 + e) * 128 + col] = fmaxf(s, 0.f);
            }
        }
        return;
    }

#if HAS_TC
    const uint32_t sb = smem_u32(smem);
    const int wid  = tid >> 5;
    const int lane = tid & 31;
    const int rowBase = blockIdx.x * 128;
    const int NCH = K / 32;

    if (wid == 0) { tc_alloc(sb + SM_TMEMP, 128); tc_relinquish(); }
    if (tid == 0) {
        mbar_init(sb + SM_FULL0, 257); mbar_init(sb + SM_FULL1, 257);
        mbar_init(sb + SM_EMPT0, 1);   mbar_init(sb + SM_EMPT1, 1);
    }
    __syncthreads();
    uint32_t tmem;
    asm volatile("ld.shared.b32 %0, [%1];" : "=r"(tmem) : "r"(sb + SM_TMEMP));

    if (tid < 256) {
        const int row  = tid >> 1;
        const int r    = rowBase + row;
        const int half = tid & 1;
        uint32_t bo = (uint32_t)row * 64u + (uint32_t)half * 32u;
        const uint32_t sw0 = bo ^ ((bo >> 3) & 0x30);
        bo += 16u;
        const uint32_t sw1 = bo ^ ((bo >> 3) & 0x30);
        int gg = 0;
        if (MODE == 0) gg = __ldg(n2g + r);

        for (int c = 0; c < NCH; c++) {
            const int s = c & 1;
            const int kb = c * 32 + half * 16;
            float4 av[4];
            if (MODE == 0) {
                const float* p = (kb < 128) ? A0 + (size_t)r * 128 + kb
                               : (kb < 256) ? A1 + (size_t)gg * 128 + (kb - 128)
                                            : A2 + (size_t)gg * 128 + (kb - 256);
                #pragma unroll
                for (int q = 0; q < 4; q++) av[q] = *(const float4*)(p + q * 4);
            } else {
                const float* p = (kb < 128) ? g_x + (size_t)r * 128 + kb
                                            : A0 + (size_t)r * 64 + (kb - 128);
                #pragma unroll
                for (int q = 0; q < 4; q++) av[q] = *(const float4*)(p + q * 4);
            }

            if (c >= 2) mbar_wait(sb + SM_EMPT0 + s * 8, ((c >> 1) + 1) & 1);

            const float* f = (const float*)av;
            uint32_t hi[8], lo[8];
            #pragma unroll
            for (int q = 0; q < 8; q++) {
                float a = f[2 * q], b = f[2 * q + 1];
                __nv_bfloat162 h = __float22bfloat162_rn(make_float2(a, b));
                hi[q] = *(uint32_t*)&h;
                lo[q] = pack_bf2(a - __bfloat162float(h.x), b - __bfloat162float(h.y));
            }
            char* stg = smem + SM_TILES + s * STG_SZ;
            *(uint4*)(stg + OFF_AHI + sw0) = *(uint4*)&hi[0];
            *(uint4*)(stg + OFF_AHI + sw1) = *(uint4*)&hi[4];
            *(uint4*)(stg + OFF_ALO + sw0) = *(uint4*)&lo[0];
            *(uint4*)(stg + OFF_ALO + sw1) = *(uint4*)&lo[4];

            fence_async_shared();
            mbar_arrive(sb + SM_FULL0 + s * 8);
        }
    } else if (tid == 256) {
        uint64_t dAhi[2], dAlo[2], dBhi[2], dBlo[2];
        #pragma unroll
        for (int s = 0; s < 2; s++) {
            uint32_t st = sb + SM_TILES + s * STG_SZ;
            dAhi[s] = make_desc64(st + OFF_AHI);
            dAlo[s] = make_desc64(st + OFF_ALO);
            dBhi[s] = make_desc64(st + OFF_BHI);
            dBlo[s] = make_desc64(st + OFF_BLO);
        }
        for (int c = 0; c < NCH; c++) {
            const int s = c & 1;
            if (c >= 2) mbar_wait(sb + SM_EMPT0 + s * 8, ((c >> 1) + 1) & 1);
            const uint32_t full = sb + SM_FULL0 + s * 8;
            mbar_arrive_tx(full, 16384);
            const uint32_t st = sb + SM_TILES + s * STG_SZ;
            bulk_g2s(st + OFF_BHI, g_wbhi + woff + c * 4096, 8192, full);
            bulk_g2s(st + OFF_BLO, g_wblo + woff + c * 4096, 8192, full);
            mbar_wait(full, (c >> 1) & 1);
            #pragma unroll
            for (int ks = 0; ks < 2; ks++) {
                const uint64_t o = ks * 2;
                int first = (c == 0 && ks == 0);
                mma_bf16(tmem, dAhi[s] + o, dBhi[s] + o, IDESC_BF16, first ? 0 : 1);
                mma_bf16(tmem, dAhi[s] + o, dBlo[s] + o, IDESC_BF16, 1);
                mma_bf16(tmem, dAlo[s] + o, dBhi[s] + o, IDESC_BF16, 1);
            }
            tc_commit(sb + SM_EMPT0 + s * 8);
        }
    }

    {
        const int L = NCH - 1;
        mbar_wait(sb + SM_EMPT0 + (L & 1) * 8, (L >> 1) & 1);
        tc_fence_after();
    }
    if (tid < 256) {
        const int sp = wid & 3;
        const int h  = wid >> 2;
        const int r  = rowBase + sp * 32 + lane;
        const int cb = h * 64;
        uint32_t regs[64];
        ldtm32(regs,      tmem + cb);
        ldtm32(regs + 32, tmem + cb + 32);
        tc_wait_ld();

        if (MODE == 3) {
            float p = 0.f;
            #pragma unroll
            for (int j = 0; j < 64; j++) {
                float t = fmaxf(__uint_as_float(regs[j]) + __ldg(bias + cb + j), 0.f);
                p = fmaf(t, __ldg(w2 + cb + j), p);
            }
            ((float*)(smem + SM_PART))[h * 128 + sp * 32 + lane] = p;
        } else {
            size_t base = (size_t)r * 128 + cb;
            #pragma unroll
            for (int j = 0; j < 64; j += 4) {
                float4 o;
                o.x = fmaxf(__uint_as_float(regs[j + 0]) + __ldg(bias + cb + j + 0), 0.f);
                o.y = fmaxf(__uint_as_float(regs[j + 1]) + __ldg(bias + cb + j + 1), 0.f);
                o.z = fmaxf(__uint_as_float(regs[j + 2]) + __ldg(bias + cb + j + 2), 0.f);
                o.w = fmaxf(__uint_as_float(regs[j + 3]) + __ldg(bias + cb + j + 3), 0.f);
                *(float4*)(g_x + base + j) = o;
            }
        }
    }
    __syncthreads();
    if (MODE == 3 && tid < 128) {
        const float* part = (const float*)(smem + SM_PART);
        g_logit[rowBase + tid] = part[tid] + part[128 + tid] + b2s[0];
    }
    if (wid == 0) tc_dealloc(tmem, 128);

#else  // fallback (family-PTX pass only)
    const int rowBase = blockIdx.x * 128;
    if (tid >= 128) return;
    __shared__ float col[128];
    for (int m = 0; m < 128; m++) {
        const int r = rowBase + m;
        float acc = 0.f;
        for (int k = 0; k < K; k++) {
            float a;
            if (MODE == 0) {
                if (k < 128) a = A0[(size_t)r * 128 + k];
                else {
                    int gg = n2g[r];
                    a = (k < 256) ? A1[(size_t)gg * 128 + (k - 128)]
                                  : A2[(size_t)gg * 128 + (k - 256)];
                }
            } else {
                a = (k < 128) ? g_x[(size_t)r * 128 + k] : A0[(size_t)r * 64 + (k - 128)];
            }
            int chunk = k >> 5, kk = k & 31;
            uint32_t off = (uint32_t)tid * 64u + (uint32_t)kk * 2u;
            off ^= ((off >> 3) & 0x30);
            int di = woff + chunk * 4096 + (int)(off >> 1);
            float w = __bfloat162float(g_wbhi[di]) + __bfloat162float(g_wblo[di]);
            acc = fmaf(a, w, acc);
        }
        if (MODE == 3) {
            col[tid] = fmaxf(acc + bias[tid], 0.f) * w2[tid];
            __syncthreads();
            if (tid == 0) {
                float p = 0.f;
                for (int j = 0; j < 128; j++) p += col[j];
                g_logit[r] = p + b2s[0];
            }
            __syncthreads();
        } else {
            g_x[(size_t)r * 128 + tid] = fmaxf(acc + bias[tid], 0.f);
        }
    }
#endif
}

// ---------------- fused GINE layer (resident-B): x += relu(relu((x+agg)W1+b1)W2+b2)
__global__ __launch_bounds__(288, 2) void tc_layer_k(
    const float* __restrict__ b1, const float* __restrict__ b2,
    int woff1, int woff2)
{
#if HAS_TC
    extern __shared__ __align__(1024) char smem[];
    const uint32_t sb = smem_u32(smem);
    const int tid  = threadIdx.x;
    const int wid  = tid >> 5;
    const int lane = tid & 31;
    const int rowBase = blockIdx.x * 128;
    float* b1s = (float*)(smem + L_B1S);

    if (wid == 0) { tc_alloc(sb, 256); tc_relinquish(); }
    if (tid == 0) {
        mbar_init(sb + L_FULL0, 256); mbar_init(sb + L_FULL1, 256);
        mbar_init(sb + L_EMPT0, 1);   mbar_init(sb + L_EMPT1, 1);
        mbar_init(sb + L_D1DN, 1);
        mbar_init(sb + L_F2_0, 128);  mbar_init(sb + L_F2_1, 128);
        mbar_init(sb + L_E2_0, 1);    mbar_init(sb + L_E2_1, 1);
        mbar_init(sb + L_WBAR, 1);
    }
    if (tid >= 128 && tid < 256) b1s[tid - 128] = b1[tid - 128];
    __syncthreads();
    uint32_t tmem;
    asm volatile("ld.shared.b32 %0, [%1];" : "=r"(tmem) : "r"(sb));
    const uint32_t tmem2 = tmem + 128;

    // ============ phase 1: D1 = (x+agg) @ W1 ============
    if (tid < 256) {
        const int row  = tid >> 1;
        const int r    = rowBase + row;
        const int half = tid & 1;
        uint32_t bo = (uint32_t)row * 64u + (uint32_t)half * 32u;
        const uint32_t sw0 = bo ^ ((bo >> 3) & 0x30);
        bo += 16u;
        const uint32_t sw1 = bo ^ ((bo >> 3) & 0x30);

        for (int c = 0; c < 4; c++) {
            const int s = c & 1;
            const int kb = c * 32 + half * 16;
            size_t off = (size_t)r * 128 + kb;
            float4 av[4];
            #pragma unroll
            for (int q = 0; q < 4; q++) {
                float4 a = *(const float4*)(g_x + off + q * 4);
                float4 g = *(const float4*)(g_agg + off + q * 4);
                av[q] = make_float4(a.x + g.x, a.y + g.y, a.z + g.z, a.w + g.w);
            }
            if (c >= 2) mbar_wait(sb + L_EMPT0 + s * 8, 0);

            const float* f = (const float*)av;
            uint32_t hi[8], lo[8];
            #pragma unroll
            for (int q = 0; q < 8; q++) {
                float a = f[2 * q], b = f[2 * q + 1];
                __nv_bfloat162 h = __float22bfloat162_rn(make_float2(a, b));
                hi[q] = *(uint32_t*)&h;
                lo[q] = pack_bf2(a - __bfloat162float(h.x), b - __bfloat162float(h.y));
            }
            char* stg = smem + L_ASTG + s * 16384;
            *(uint4*)(stg + sw0)        = *(uint4*)&hi[0];
            *(uint4*)(stg + sw1)        = *(uint4*)&hi[4];
            *(uint4*)(stg + 8192 + sw0) = *(uint4*)&lo[0];
            *(uint4*)(stg + 8192 + sw1) = *(uint4*)&lo[4];

            fence_async_shared();
            mbar_arrive(sb + L_FULL0 + s * 8);
        }
    } else if (tid == 256) {
        // resident W1 load
        mbar_arrive_tx(sb + L_WBAR, 65536);
        bulk_g2s(sb + L_WHI, g_wbhi + woff1, 32768, sb + L_WBAR);
        bulk_g2s(sb + L_WLO, g_wblo + woff1, 32768, sb + L_WBAR);
        uint64_t dAhi[2], dAlo[2];
        #pragma unroll
        for (int s = 0; s < 2; s++) {
            dAhi[s] = make_desc64(sb + L_ASTG + s * 16384);
            dAlo[s] = make_desc64(sb + L_ASTG + s * 16384 + 8192);
        }
        mbar_wait(sb + L_WBAR, 0);
        for (int c = 0; c < 4; c++) {
            const int s = c & 1;
            mbar_wait(sb + L_FULL0 + s * 8, (c >> 1) & 1);
            uint64_t bh = make_desc64(sb + L_WHI + c * 8192);
            uint64_t bl = make_desc64(sb + L_WLO + c * 8192);
            #pragma unroll
            for (int ks = 0; ks < 2; ks++) {
                const uint64_t o = ks * 2;
                int first = (c == 0 && ks == 0);
                mma_bf16(tmem, dAhi[s] + o, bh + o, IDESC_BF16, first ? 0 : 1);
                mma_bf16(tmem, dAhi[s] + o, bl + o, IDESC_BF16, 1);
                mma_bf16(tmem, dAlo[s] + o, bh + o, IDESC_BF16, 1);
            }
            tc_commit(sb + L_EMPT0 + s * 8);
        }
        tc_commit(sb + L_D1DN);
    }

    // ============ phase 2: D2 = relu(D1+b1) @ W2 ============
    mbar_wait(sb + L_D1DN, 0);
    tc_fence_after();

    if (tid < 256) {
        const int sp  = wid & 3;
        const int grp = wid >> 2;
        const int r   = sp * 32 + lane;
        #pragma unroll
        for (int it = 0; it < 2; it++) {
            const int c = grp + it * 2;
            const int s = c & 1;
            if (it == 1) mbar_wait(sb + L_E2_0 + s * 8, 0);
            char* stg = smem + L_ASTG + s * 16384;
            #pragma unroll
            for (int hh = 0; hh < 2; hh++) {
                uint32_t regs[16];
                ldtm16(regs, tmem + c * 32 + hh * 16);
                tc_wait_ld();
                uint32_t hi[8], lo[8];
                #pragma unroll
                for (int q = 0; q < 8; q++) {
                    const int cb = c * 32 + hh * 16;
                    float a = fmaxf(__uint_as_float(regs[2 * q])     + b1s[cb + 2 * q],     0.f);
                    float b = fmaxf(__uint_as_float(regs[2 * q + 1]) + b1s[cb + 2 * q + 1], 0.f);
                    __nv_bfloat162 h = __float22bfloat162_rn(make_float2(a, b));
                    hi[q] = *(uint32_t*)&h;
                    lo[q] = pack_bf2(a - __bfloat162float(h.x), b - __bfloat162float(h.y));
                }
                uint32_t o0 = (uint32_t)r * 64u + hh * 32u;
                uint32_t o1 = o0 + 16u;
                o0 ^= ((o0 >> 3) & 0x30);
                o1 ^= ((o1 >> 3) & 0x30);
                *(uint4*)(stg + o0)        = *(uint4*)&hi[0];
                *(uint4*)(stg + o1)        = *(uint4*)&hi[4];
                *(uint4*)(stg + 8192 + o0) = *(uint4*)&lo[0];
                *(uint4*)(stg + 8192 + o1) = *(uint4*)&lo[4];
            }
            fence_async_shared();
            mbar_arrive(sb + L_F2_0 + s * 8);
        }
    } else if (tid == 256) {
        // resident W2 load (region free: phase-1 MMAs drained at D1DN)
        mbar_arrive_tx(sb + L_WBAR, 65536);
        bulk_g2s(sb + L_WHI, g_wbhi + woff2, 32768, sb + L_WBAR);
        bulk_g2s(sb + L_WLO, g_wblo + woff2, 32768, sb + L_WBAR);
        uint64_t dAhi[2], dAlo[2];
        #pragma unroll
        for (int s = 0; s < 2; s++) {
            dAhi[s] = make_desc64(sb + L_ASTG + s * 16384);
            dAlo[s] = make_desc64(sb + L_ASTG + s * 16384 + 8192);
        }
        mbar_wait(sb + L_WBAR, 1);
        for (int c = 0; c < 4; c++) {
            const int s = c & 1;
            if (c >= 2) mbar_wait(sb + L_E2_0 + s * 8, 0);
            mbar_wait(sb + L_F2_0 + s * 8, (c >> 1) & 1);
            uint64_t bh = make_desc64(sb + L_WHI + c * 8192);
            uint64_t bl = make_desc64(sb + L_WLO + c * 8192);
            #pragma unroll
            for (int ks = 0; ks < 2; ks++) {
                const uint64_t o = ks * 2;
                int first = (c == 0 && ks == 0);
                mma_bf16(tmem2, dAhi[s] + o, bh + o, IDESC_BF16, first ? 0 : 1);
                mma_bf16(tmem2, dAhi[s] + o, bl + o, IDESC_BF16, 1);
                mma_bf16(tmem2, dAlo[s] + o, bh + o, IDESC_BF16, 1);
            }
            tc_commit(sb + L_E2_0 + s * 8);
        }
    }

    // ============ epilogue: g_x += relu(D2 + b2); re-zero g_agg ============
    mbar_wait(sb + L_E2_0, 1);
    mbar_wait(sb + L_E2_1, 1);
    tc_fence_after();
    if (tid < 256) {
        const int sp = wid & 3;
        const int h  = wid >> 2;
        const int r  = rowBase + sp * 32 + lane;
        const int cb = h * 64;
        uint32_t regs[64];
        ldtm32(regs,      tmem2 + cb);
        ldtm32(regs + 32, tmem2 + cb + 32);
        tc_wait_ld();
        size_t base = (size_t)r * 128 + cb;
        #pragma unroll
        for (int j = 0; j < 64; j += 4) {
            float4 o;
            o.x = fmaxf(__uint_as_float(regs[j + 0]) + __ldg(b2 + cb + j + 0), 0.f);
            o.y = fmaxf(__uint_as_float(regs[j + 1]) + __ldg(b2 + cb + j + 1), 0.f);
            o.z = fmaxf(__uint_as_float(regs[j + 2]) + __ldg(b2 + cb + j + 2), 0.f);
            o.w = fmaxf(__uint_as_float(regs[j + 3]) + __ldg(b2 + cb + j + 3), 0.f);
            float4 x0 = *(const float4*)(g_x + base + j);
            o.x += x0.x; o.y += x0.y; o.z += x0.z; o.w += x0.w;
            *(float4*)(g_x + base + j) = o;
            *(float4*)(g_agg + base + j) = make_float4(0.f, 0.f, 0.f, 0.f);
        }
    }
    __syncthreads();
    if (wid == 0) tc_dealloc(tmem, 256);

#else  // fallback (family-PTX pass only)
    const int tid = threadIdx.x;
    const int rowBase = blockIdx.x * 128;
    if (tid >= 128) return;
    __shared__ float hrow[128];
    for (int m = 0; m < 128; m++) {
        const int r = rowBase + m;
        float acc = 0.f;
        for (int k = 0; k < 128; k++) {
            float a = g_x[(size_t)r * 128 + k] + g_agg[(size_t)r * 128 + k];
            int chunk = k >> 5, kk = k & 31;
            uint32_t off = (uint32_t)tid * 64u + (uint32_t)kk * 2u;
            off ^= ((off >> 3) & 0x30);
            int di = woff1 + chunk * 4096 + (int)(off >> 1);
            acc = fmaf(a, __bfloat162float(g_wbhi[di]) + __bfloat162float(g_wblo[di]), acc);
        }
        hrow[tid] = fmaxf(acc + b1[tid], 0.f);
        __syncthreads();
        float acc2 = 0.f;
        for (int k = 0; k < 128; k++) {
            int chunk = k >> 5, kk = k & 31;
            uint32_t off = (uint32_t)tid * 64u + (uint32_t)kk * 2u;
            off ^= ((off >> 3) & 0x30);
            int di = woff2 + chunk * 4096 + (int)(off >> 1);
            acc2 = fmaf(hrow[k], __bfloat162float(g_wbhi[di]) + __bfloat162float(g_wblo[di]), acc2);
        }
        g_x[(size_t)r * 128 + tid] += fmaxf(acc2 + b2[tid], 0.f);
        __syncthreads();
    }
    for (int i = tid; i < 128 * 128; i += 128)
        g_agg[(size_t)rowBase * 128 + i] = 0.f;
#endif
}

// ---------------- segment softmax -------------------------------------------------
__global__ void seg_max_k(const int* __restrict__ n2g) {
    int i = blockIdx.x * blockDim.x + threadIdx.x;
    if (i >= V_) return;
    atomicMax(&g_menc[n2g[i]], encf(g_logit[i]));
}
__global__ void seg_exp_k(const int* __restrict__ n2g, float* __restrict__ out) {
    int i = blockIdx.x * blockDim.x + threadIdx.x;
    if (i >= V_) return;
    int gg = n2g[i];
    float m = decf(g_menc[gg]);
    float ex = expf(g_logit[i] - m);
    out[i] = ex;
    atomicAdd(&g_den[gg], ex);
}
__global__ void seg_div_k(const int* __restrict__ n2g, float* __restrict__ out) {
    int i = blockIdx.x * blockDim.x + threadIdx.x;
    if (i >= V_) return;
    out[i] = out[i] / g_den[n2g[i]];
}

// ---------------- launch -----------------------------------------------------------
extern "C" void kernel_launch(void* const* d_in, const int* in_sizes, int n_in,
                              void* d_out, int out_size)
{
    const float* x_inp   = (const float*)d_in[0];
    const int*   eidx    = (const int*)  d_in[1];
    const float* eattr   = (const float*)d_in[2];
    const float* x_upd   = (const float*)d_in[3];
    const float* Zc      = (const float*)d_in[4];
    const float* Zb      = (const float*)d_in[5];
    const int*   n2g     = (const int*)  d_in[6];
    const float* W_emb   = (const float*)d_in[7];
    const float* b_emb   = (const float*)d_in[8];
    const float* W_edge  = (const float*)d_in[9];
    const float* b_edge  = (const float*)d_in[10];
    const float* W1      = (const float*)d_in[11];
    const float* b1      = (const float*)d_in[12];
    const float* W2      = (const float*)d_in[13];
    const float* b2      = (const float*)d_in[14];
    const float* W_mlp1  = (const float*)d_in[15];
    const float* b_mlp1  = (const float*)d_in[16];
    const float* W_mlp2  = (const float*)d_in[17];
    const float* b_mlp2  = (const float*)d_in[18];
    float* out = (float*)d_out;

    cudaFuncSetAttribute(tc_gemm_k<384, 0>, cudaFuncAttributeMaxDynamicSharedMemorySize, SMEM_GEMM);
    cudaFuncSetAttribute(tc_gemm_k<192, 3>, cudaFuncAttributeMaxDynamicSharedMemorySize, SMEM_GEMM);
    cudaFuncSetAttribute(tc_layer_k,        cudaFuncAttributeMaxDynamicSharedMemorySize, SMEM_LAYER);

    const int GB = V_ / 128;   // 2048 tiles

    // launch 1: weight split + softmax scratch zero
    split_w_k<<<(WT_TOTAL + 255) / 256, 256>>>(W_emb, W1, W2, W_mlp1);
    // launch 2: EMB GEMM (blocks 0..2047) + edge embedding (blocks 2048..4095)
    tc_gemm_k<384, 0><<<GB + 2048, 288, SMEM_GEMM>>>(x_upd, Zc, Zb, n2g, b_emb,
                                                     W_edge, b_edge, eattr, 0);
    for (int l = 0; l < 4; l++) {
        // launches 3,5,7,9: scatter ; 4,6,8,10: fused layer (launch 4 gets profiled)
        scatter_k<<<E_ / 8, 256>>>(eidx, eidx + E_);
        tc_layer_k<<<GB, 288, SMEM_LAYER>>>(b1 + (size_t)l * 128, b2 + (size_t)l * 128,
                                            49152 + l * 16384, 114688 + l * 16384);
    }
    tc_gemm_k<192, 3><<<GB, 288, SMEM_GEMM>>>(x_inp, nullptr, nullptr, nullptr,
                                              b_mlp1, W_mlp2, b_mlp2, nullptr, 180224);

    seg_max_k<<<V_ / 256, 256>>>(n2g);
    seg_exp_k<<<V_ / 256, 256>>>(n2g, out);
    seg_div_k<<<V_ / 256, 256>>>(n2g, out);
}

// round 9
// speedup vs baseline: 3.6313x; 1.0342x over previous
#include <cuda_runtime.h>
#include <cuda_bf16.h>
#include <cstdint>

#define V_  262144
#define E_  524288
#define NG  8192
#define H_  128

// ---------------- tcgen05 feature gate ---------------------------------------------
#if defined(__CUDA_ARCH_FEAT_SM103_ALL) || defined(__CUDA_ARCH_FEAT_SM100_ALL) || defined(__CUDA_ARCH_FEAT_SM101_ALL)
#define HAS_TC 1
#endif
#if !defined(HAS_TC) && defined(__CUDA_ARCH_HAS_FEATURE__)
#if __CUDA_ARCH_HAS_FEATURE__(SM103_ALL)
#define HAS_TC 1
#endif
#endif
#ifndef HAS_TC
#define HAS_TC 0
#endif

// ---------------- scratch globals ------------------------------------------------
__device__ float    g_x[(size_t)V_ * H_];     // current node features
__device__ float    g_xa[(size_t)V_ * H_];    // x + aggregated messages (seeded w/ x)
__device__ __align__(8) __nv_bfloat162 g_e2[(size_t)E_ * 64];  // edge emb, bf16x2
__device__ float    g_logit[V_];
__device__ unsigned g_menc[NG];
__device__ float    g_den[NG];
// weights: transposed, bf16 hi/lo split, PRE-SWIZZLED (SW64) 32-K-chunk-contiguous
#define WT_TOTAL 204800
__device__ __align__(16) __nv_bfloat16 g_wbhi[WT_TOTAL];
__device__ __align__(16) __nv_bfloat16 g_wblo[WT_TOTAL];

// ---------------- PTX helpers -----------------------------------------------------
__device__ __forceinline__ uint32_t smem_u32(const void* p) {
    uint32_t a;
    asm("{ .reg .u64 t; cvta.to.shared.u64 t, %1; cvt.u32.u64 %0, t; }" : "=r"(a) : "l"(p));
    return a;
}
__device__ __forceinline__ void mbar_init(uint32_t mbar, uint32_t cnt) {
    asm volatile("mbarrier.init.shared.b64 [%0], %1;" :: "r"(mbar), "r"(cnt) : "memory");
}
__device__ __forceinline__ void mbar_arrive(uint32_t mbar) {
    asm volatile("mbarrier.arrive.shared.b64 _, [%0];" :: "r"(mbar) : "memory");
}
__device__ __forceinline__ void mbar_arrive_tx(uint32_t mbar, uint32_t tx) {
    asm volatile("mbarrier.arrive.expect_tx.shared.b64 _, [%0], %1;"
                 :: "r"(mbar), "r"(tx) : "memory");
}
__device__ __forceinline__ void mbar_wait(uint32_t mbar, uint32_t parity) {
    asm volatile(
        "{\n\t.reg .pred P;\n\tWL_%=:\n\t"
        "mbarrier.try_wait.parity.acquire.cta.shared::cta.b64 P, [%0], %1, 0x989680;\n\t"
        "@!P bra WL_%=;\n\t}" :: "r"(mbar), "r"(parity) : "memory");
}
__device__ __forceinline__ void fence_async_shared() {
    asm volatile("fence.proxy.async.shared::cta;" ::: "memory");
}
__device__ __forceinline__ void bulk_g2s(uint32_t dst, const void* src, uint32_t bytes,
                                         uint32_t mbar) {
    uint64_t gsrc;
    asm("cvta.to.global.u64 %0, %1;" : "=l"(gsrc) : "l"(src));
    asm volatile(
        "cp.async.bulk.shared::cta.global.mbarrier::complete_tx::bytes [%0], [%1], %2, [%3];"
        :: "r"(dst), "l"(gsrc), "r"(bytes), "r"(mbar) : "memory");
}

#if HAS_TC
__device__ __forceinline__ void mma_bf16(uint32_t d, uint64_t a, uint64_t b,
                                         uint32_t idesc, int acc) {
    asm volatile(
        "{\n\t.reg .pred p;\n\tsetp.ne.b32 p, %4, 0;\n\t"
        "tcgen05.mma.cta_group::1.kind::f16 [%0], %1, %2, %3, p;\n\t}"
        :: "r"(d), "l"(a), "l"(b), "r"(idesc), "r"(acc) : "memory");
}
__device__ __forceinline__ void tc_commit(uint32_t mbar) {
    asm volatile(
        "tcgen05.commit.cta_group::1.mbarrier::arrive::one.shared::cluster.b64 [%0];"
        :: "r"(mbar) : "memory");
}
__device__ __forceinline__ void tc_alloc(uint32_t smem_dst, uint32_t ncols) {
    asm volatile("tcgen05.alloc.cta_group::1.sync.aligned.shared::cta.b32 [%0], %1;"
                 :: "r"(smem_dst), "r"(ncols) : "memory");
}
__device__ __forceinline__ void tc_dealloc(uint32_t tmem, uint32_t ncols) {
    asm volatile("tcgen05.dealloc.cta_group::1.sync.aligned.b32 %0, %1;"
                 :: "r"(tmem), "r"(ncols));
}
__device__ __forceinline__ void tc_relinquish() {
    asm volatile("tcgen05.relinquish_alloc_permit.cta_group::1.sync.aligned;");
}
__device__ __forceinline__ void tc_fence_after() {
    asm volatile("tcgen05.fence::after_thread_sync;" ::: "memory");
}
__device__ __forceinline__ void tc_wait_ld() {
    asm volatile("tcgen05.wait::ld.sync.aligned;" ::: "memory");
}
__device__ __forceinline__ void ldtm32(uint32_t* r, uint32_t addr) {
    asm volatile(
        "tcgen05.ld.sync.aligned.32x32b.x32.b32 "
        "{%0, %1, %2, %3, %4, %5, %6, %7, %8, %9, %10, %11, %12, %13, %14, %15, "
        " %16, %17, %18, %19, %20, %21, %22, %23, %24, %25, %26, %27, %28, %29, %30, %31}, [%32];"
        : "=r"(r[0]), "=r"(r[1]), "=r"(r[2]), "=r"(r[3]), "=r"(r[4]), "=r"(r[5]),
          "=r"(r[6]), "=r"(r[7]), "=r"(r[8]), "=r"(r[9]), "=r"(r[10]), "=r"(r[11]),
          "=r"(r[12]), "=r"(r[13]), "=r"(r[14]), "=r"(r[15]), "=r"(r[16]), "=r"(r[17]),
          "=r"(r[18]), "=r"(r[19]), "=r"(r[20]), "=r"(r[21]), "=r"(r[22]), "=r"(r[23]),
          "=r"(r[24]), "=r"(r[25]), "=r"(r[26]), "=r"(r[27]), "=r"(r[28]), "=r"(r[29]),
          "=r"(r[30]), "=r"(r[31])
        : "r"(addr));
}
__device__ __forceinline__ void ldtm16(uint32_t* r, uint32_t addr) {
    asm volatile(
        "tcgen05.ld.sync.aligned.32x32b.x16.b32 "
        "{%0, %1, %2, %3, %4, %5, %6, %7, %8, %9, %10, %11, %12, %13, %14, %15}, [%16];"
        : "=r"(r[0]), "=r"(r[1]), "=r"(r[2]), "=r"(r[3]), "=r"(r[4]), "=r"(r[5]),
          "=r"(r[6]), "=r"(r[7]), "=r"(r[8]), "=r"(r[9]), "=r"(r[10]), "=r"(r[11]),
          "=r"(r[12]), "=r"(r[13]), "=r"(r[14]), "=r"(r[15])
        : "r"(addr));
}
#endif  // HAS_TC

__device__ __forceinline__ unsigned encf(float f) {
    unsigned u = __float_as_uint(f);
    return (u & 0x80000000u) ? ~u : (u | 0x80000000u);
}
__device__ __forceinline__ float decf(unsigned u) {
    return (u & 0x80000000u) ? __uint_as_float(u & 0x7fffffffu) : __uint_as_float(~u);
}

// SW64 K-major descriptor: layout=4, version=1, SBO=32, LBO=1
static __device__ __forceinline__ uint64_t make_desc64(uint32_t addr) {
    const uint64_t base =
        (uint64_t(4) << 61) | (uint64_t(1) << 46) | (uint64_t(32) << 32) | (uint64_t(1) << 16);
    return base | ((uint64_t)(addr >> 4) & 0x3FFF);
}

// idesc kind::f16: cF32(1<<4) | aBF16(1<<7) | bBF16(1<<10) | N=128 (16<<17) | M=128 (8<<24)
#define IDESC_BF16 0x08200490u

// ------- streaming GEMM smem layout (EMB / HEAD) -------
#define SM_TMEMP 0
#define SM_FULL0 16
#define SM_FULL1 24
#define SM_EMPT0 32
#define SM_EMPT1 40
#define SM_PART  256
#define SM_TILES 2048
#define STG_SZ   32768
#define OFF_AHI  0
#define OFF_ALO  8192
#define OFF_BHI  16384
#define OFF_BLO  24576
#define SMEM_GEMM (SM_TILES + 2 * STG_SZ)

// ------- fused layer smem layout (resident B) -------
#define L_FULL0 16
#define L_FULL1 24
#define L_EMPT0 32
#define L_EMPT1 40
#define L_D1DN  48
#define L_F2_0  56
#define L_F2_1  64
#define L_E2_0  72
#define L_E2_1  80
#define L_WBAR  88
#define L_B1S   128          // 512B
#define L_ASTG  1024         // + s*16384 : Ahi 8K | Alo 8K
#define L_WHI   33792        // 32KB resident W hi
#define L_WLO   66560        // 32KB resident W lo
#define SMEM_LAYER 99328

__device__ __forceinline__ uint32_t pack_bf2(float a, float b) {
    __nv_bfloat162 h = __float22bfloat162_rn(make_float2(a, b));
    return *(uint32_t*)&h;
}

// ---------------- weight split (+ softmax scratch zero) ---------------------------
__global__ void split_w_k(const float* __restrict__ We, const float* __restrict__ W1,
                          const float* __restrict__ W2, const float* __restrict__ Wm)
{
    int i = blockIdx.x * 256 + threadIdx.x;
    if (i >= WT_TOTAL) return;
    if (i < NG) { g_menc[i] = 0u; g_den[i] = 0.f; }
    int base, n, k, K;
    if (i < 49152)       { base = 0;      int j = i;          K = 384; n = j / K; k = j % K; }
    else if (i < 114688) { int j = i - 49152;  int l = j >> 14; base = 49152 + l*16384;  j &= 16383; K = 128; n = j >> 7; k = j & 127; }
    else if (i < 180224) { int j = i - 114688; int l = j >> 14; base = 114688 + l*16384; j &= 16383; K = 128; n = j >> 7; k = j & 127; }
    else                 { base = 180224; int j = i - 180224;  K = 192; n = j / K; k = j % K; }
    float v;
    if (base == 0)           v = We[k * 128 + n];
    else if (base < 114688)  v = W1[(base - 49152) / 16384 * 16384 + k * 128 + n];
    else if (base < 180224)  v = W2[(base - 114688) / 16384 * 16384 + k * 128 + n];
    else                     v = Wm[k * 128 + n];

    __nv_bfloat16 hi = __float2bfloat16_rn(v);
    __nv_bfloat16 lo = __float2bfloat16_rn(v - __bfloat162float(hi));
    int chunk = k >> 5, kk = k & 31;
    uint32_t off = (uint32_t)n * 64u + (uint32_t)kk * 2u;
    off ^= ((off >> 3) & 0x30);               // SW64 swizzle
    int di = base + chunk * 4096 + (int)(off >> 1);
    g_wbhi[di] = hi;
    g_wblo[di] = lo;
}

// ---------------- scatter: g_xa[dst] += relu(x[src] + e) --------------------------
__global__ __launch_bounds__(256) void scatter_k(
    const int* __restrict__ src, const int* __restrict__ dst)
{
    const int warp = (blockIdx.x * blockDim.x + threadIdx.x) >> 5;
    const int lane = threadIdx.x & 31;
    if (warp >= E_) return;
    const int s = src[warp];
    const int d = dst[warp];
    float4 xv = *(const float4*)(g_x + (size_t)s * 128 + lane * 4);
    const __nv_bfloat162* ep = g_e2 + (size_t)warp * 64 + lane * 2;
    float2 e0 = __bfloat1622float2(ep[0]);
    float2 e1 = __bfloat1622float2(ep[1]);
    float4 m;
    m.x = fmaxf(xv.x + e0.x, 0.f);
    m.y = fmaxf(xv.y + e0.y, 0.f);
    m.z = fmaxf(xv.z + e1.x, 0.f);
    m.w = fmaxf(xv.w + e1.y, 0.f);
    atomicAdd((float4*)(g_xa + (size_t)d * 128 + lane * 4), m);
}

// ---------------- EMB(+edge blocks) / HEAD GEMM (streaming B pipeline) ------------
// MODE 0: grid = 2048 GEMM tiles + 2048 edge blocks (256 edges each).
// MODE 3: head, grid 2048.
template <int K, int MODE>
__global__ __launch_bounds__(288, 2) void tc_gemm_k(
    const float* __restrict__ A0, const float* __restrict__ A1,
    const float* __restrict__ A2, const int* __restrict__ n2g,
    const float* __restrict__ bias, const float* __restrict__ w2,
    const float* __restrict__ b2s, const float* __restrict__ eattr, int woff)
{
    extern __shared__ __align__(1024) char smem[];
    const int tid  = threadIdx.x;

    // ---------------- edge-embedding blocks (MODE 0 only) ----------------
    if (MODE == 0 && blockIdx.x >= V_ / 128) {
        const int eb = blockIdx.x - V_ / 128;
        const int e0 = eb * 256;
        float* Ws = (float*)smem;                 // 2048 floats
        float* Ae = (float*)(smem + 8192);        // 4096 floats
        float* bs = (float*)(smem + 24576);       // 128 floats
        for (int i = tid; i < 2048; i += 288) Ws[i] = w2[i];
        for (int i = tid; i < 4096; i += 288) Ae[i] = eattr[(size_t)e0 * 16 + i];
        if (tid < 128) bs[tid] = b2s[tid];
        __syncthreads();
        if (tid < 256) {
            const int col = tid & 127, half = tid >> 7;
            float w[16];
            #pragma unroll
            for (int k = 0; k < 16; k++) w[k] = Ws[k * 128 + col];
            const float bb = bs[col];
            for (int ee = 0; ee < 128; ee++) {
                const int e = half * 128 + ee;
                const float4* a4 = (const float4*)&Ae[e * 16];
                float4 x0 = a4[0], x1 = a4[1], x2 = a4[2], x3 = a4[3];
                float s = bb;
                s = fmaf(x0.x, w[0],  s); s = fmaf(x0.y, w[1],  s);
                s = fmaf(x0.z, w[2],  s); s = fmaf(x0.w, w[3],  s);
                s = fmaf(x1.x, w[4],  s); s = fmaf(x1.y, w[5],  s);
                s = fmaf(x1.z, w[6],  s); s = fmaf(x1.w, w[7],  s);
                s = fmaf(x2.x, w[8],  s); s = fmaf(x2.y, w[9],  s);
                s = fmaf(x2.z, w[10], s); s = fmaf(x2.w, w[11], s);
                s = fmaf(x3.x, w[12], s); s = fmaf(x3.y, w[13], s);
                s = fmaf(x3.z, w[14], s); s = fmaf(x3.w, w[15], s);
                s = fmaxf(s, 0.f);
                // pack adjacent columns into bf16x2 via shuffle (pairs in same warp)
                float snb = __shfl_down_sync(0xffffffffu, s, 1);
                if ((col & 1) == 0) {
                    uint32_t pk = pack_bf2(s, snb);
                    *(uint32_t*)&g_e2[(size_t)(e0 + e) * 64 + (col >> 1)] = pk;
                }
            }
        }
        return;
    }

#if HAS_TC
    const uint32_t sb = smem_u32(smem);
    const int wid  = tid >> 5;
    const int lane = tid & 31;
    const int rowBase = blockIdx.x * 128;
    const int NCH = K / 32;

    if (wid == 0) { tc_alloc(sb + SM_TMEMP, 128); tc_relinquish(); }
    if (tid == 0) {
        mbar_init(sb + SM_FULL0, 257); mbar_init(sb + SM_FULL1, 257);
        mbar_init(sb + SM_EMPT0, 1);   mbar_init(sb + SM_EMPT1, 1);
    }
    __syncthreads();
    uint32_t tmem;
    asm volatile("ld.shared.b32 %0, [%1];" : "=r"(tmem) : "r"(sb + SM_TMEMP));

    if (tid < 256) {
        const int row  = tid >> 1;
        const int r    = rowBase + row;
        const int half = tid & 1;
        uint32_t bo = (uint32_t)row * 64u + (uint32_t)half * 32u;
        const uint32_t sw0 = bo ^ ((bo >> 3) & 0x30);
        bo += 16u;
        const uint32_t sw1 = bo ^ ((bo >> 3) & 0x30);
        int gg = 0;
        if (MODE == 0) gg = __ldg(n2g + r);

        for (int c = 0; c < NCH; c++) {
            const int s = c & 1;
            const int kb = c * 32 + half * 16;
            float4 av[4];
            if (MODE == 0) {
                const float* p = (kb < 128) ? A0 + (size_t)r * 128 + kb
                               : (kb < 256) ? A1 + (size_t)gg * 128 + (kb - 128)
                                            : A2 + (size_t)gg * 128 + (kb - 256);
                #pragma unroll
                for (int q = 0; q < 4; q++) av[q] = *(const float4*)(p + q * 4);
            } else {
                const float* p = (kb < 128) ? g_x + (size_t)r * 128 + kb
                                            : A0 + (size_t)r * 64 + (kb - 128);
                #pragma unroll
                for (int q = 0; q < 4; q++) av[q] = *(const float4*)(p + q * 4);
            }

            if (c >= 2) mbar_wait(sb + SM_EMPT0 + s * 8, ((c >> 1) + 1) & 1);

            const float* f = (const float*)av;
            uint32_t hi[8], lo[8];
            #pragma unroll
            for (int q = 0; q < 8; q++) {
                float a = f[2 * q], b = f[2 * q + 1];
                __nv_bfloat162 h = __float22bfloat162_rn(make_float2(a, b));
                hi[q] = *(uint32_t*)&h;
                lo[q] = pack_bf2(a - __bfloat162float(h.x), b - __bfloat162float(h.y));
            }
            char* stg = smem + SM_TILES + s * STG_SZ;
            *(uint4*)(stg + OFF_AHI + sw0) = *(uint4*)&hi[0];
            *(uint4*)(stg + OFF_AHI + sw1) = *(uint4*)&hi[4];
            *(uint4*)(stg + OFF_ALO + sw0) = *(uint4*)&lo[0];
            *(uint4*)(stg + OFF_ALO + sw1) = *(uint4*)&lo[4];

            fence_async_shared();
            mbar_arrive(sb + SM_FULL0 + s * 8);
        }
    } else if (tid == 256) {
        uint64_t dAhi[2], dAlo[2], dBhi[2], dBlo[2];
        #pragma unroll
        for (int s = 0; s < 2; s++) {
            uint32_t st = sb + SM_TILES + s * STG_SZ;
            dAhi[s] = make_desc64(st + OFF_AHI);
            dAlo[s] = make_desc64(st + OFF_ALO);
            dBhi[s] = make_desc64(st + OFF_BHI);
            dBlo[s] = make_desc64(st + OFF_BLO);
        }
        for (int c = 0; c < NCH; c++) {
            const int s = c & 1;
            if (c >= 2) mbar_wait(sb + SM_EMPT0 + s * 8, ((c >> 1) + 1) & 1);
            const uint32_t full = sb + SM_FULL0 + s * 8;
            mbar_arrive_tx(full, 16384);
            const uint32_t st = sb + SM_TILES + s * STG_SZ;
            bulk_g2s(st + OFF_BHI, g_wbhi + woff + c * 4096, 8192, full);
            bulk_g2s(st + OFF_BLO, g_wblo + woff + c * 4096, 8192, full);
            mbar_wait(full, (c >> 1) & 1);
            #pragma unroll
            for (int ks = 0; ks < 2; ks++) {
                const uint64_t o = ks * 2;
                int first = (c == 0 && ks == 0);
                mma_bf16(tmem, dAhi[s] + o, dBhi[s] + o, IDESC_BF16, first ? 0 : 1);
                mma_bf16(tmem, dAhi[s] + o, dBlo[s] + o, IDESC_BF16, 1);
                mma_bf16(tmem, dAlo[s] + o, dBhi[s] + o, IDESC_BF16, 1);
            }
            tc_commit(sb + SM_EMPT0 + s * 8);
        }
    }

    {
        const int L = NCH - 1;
        mbar_wait(sb + SM_EMPT0 + (L & 1) * 8, (L >> 1) & 1);
        tc_fence_after();
    }
    if (tid < 256) {
        const int sp = wid & 3;
        const int h  = wid >> 2;
        const int r  = rowBase + sp * 32 + lane;
        const int cb = h * 64;
        uint32_t regs[64];
        ldtm32(regs,      tmem + cb);
        ldtm32(regs + 32, tmem + cb + 32);
        tc_wait_ld();

        if (MODE == 3) {
            float p = 0.f;
            #pragma unroll
            for (int j = 0; j < 64; j++) {
                float t = fmaxf(__uint_as_float(regs[j]) + __ldg(bias + cb + j), 0.f);
                p = fmaf(t, __ldg(w2 + cb + j), p);
            }
            ((float*)(smem + SM_PART))[h * 128 + sp * 32 + lane] = p;
        } else {
            size_t base = (size_t)r * 128 + cb;
            #pragma unroll
            for (int j = 0; j < 64; j += 4) {
                float4 o;
                o.x = fmaxf(__uint_as_float(regs[j + 0]) + __ldg(bias + cb + j + 0), 0.f);
                o.y = fmaxf(__uint_as_float(regs[j + 1]) + __ldg(bias + cb + j + 1), 0.f);
                o.z = fmaxf(__uint_as_float(regs[j + 2]) + __ldg(bias + cb + j + 2), 0.f);
                o.w = fmaxf(__uint_as_float(regs[j + 3]) + __ldg(bias + cb + j + 3), 0.f);
                *(float4*)(g_x + base + j) = o;
                *(float4*)(g_xa + base + j) = o;     // seed x+agg accumulator
            }
        }
    }
    __syncthreads();
    if (MODE == 3 && tid < 128) {
        const float* part = (const float*)(smem + SM_PART);
        g_logit[rowBase + tid] = part[tid] + part[128 + tid] + b2s[0];
    }
    if (wid == 0) tc_dealloc(tmem, 128);

#else  // fallback (family-PTX pass only)
    const int rowBase = blockIdx.x * 128;
    if (tid >= 128) return;
    __shared__ float col[128];
    for (int m = 0; m < 128; m++) {
        const int r = rowBase + m;
        float acc = 0.f;
        for (int k = 0; k < K; k++) {
            float a;
            if (MODE == 0) {
                if (k < 128) a = A0[(size_t)r * 128 + k];
                else {
                    int gg = n2g[r];
                    a = (k < 256) ? A1[(size_t)gg * 128 + (k - 128)]
                                  : A2[(size_t)gg * 128 + (k - 256)];
                }
            } else {
                a = (k < 128) ? g_x[(size_t)r * 128 + k] : A0[(size_t)r * 64 + (k - 128)];
            }
            int chunk = k >> 5, kk = k & 31;
            uint32_t off = (uint32_t)tid * 64u + (uint32_t)kk * 2u;
            off ^= ((off >> 3) & 0x30);
            int di = woff + chunk * 4096 + (int)(off >> 1);
            float w = __bfloat162float(g_wbhi[di]) + __bfloat162float(g_wblo[di]);
            acc = fmaf(a, w, acc);
        }
        if (MODE == 3) {
            col[tid] = fmaxf(acc + bias[tid], 0.f) * w2[tid];
            __syncthreads();
            if (tid == 0) {
                float p = 0.f;
                for (int j = 0; j < 128; j++) p += col[j];
                g_logit[r] = p + b2s[0];
            }
            __syncthreads();
        } else {
            float o = fmaxf(acc + bias[tid], 0.f);
            g_x[(size_t)r * 128 + tid] = o;
            g_xa[(size_t)r * 128 + tid] = o;
        }
    }
#endif
}

// ---------------- fused GINE layer (resident-B): x += relu(relu(xa@W1+b1)W2+b2) ---
__global__ __launch_bounds__(288, 2) void tc_layer_k(
    const float* __restrict__ b1, const float* __restrict__ b2,
    int woff1, int woff2, int seed)
{
#if HAS_TC
    extern __shared__ __align__(1024) char smem[];
    const uint32_t sb = smem_u32(smem);
    const int tid  = threadIdx.x;
    const int wid  = tid >> 5;
    const int lane = tid & 31;
    const int rowBase = blockIdx.x * 128;
    float* b1s = (float*)(smem + L_B1S);

    if (wid == 0) { tc_alloc(sb, 256); tc_relinquish(); }
    if (tid == 0) {
        mbar_init(sb + L_FULL0, 256); mbar_init(sb + L_FULL1, 256);
        mbar_init(sb + L_EMPT0, 1);   mbar_init(sb + L_EMPT1, 1);
        mbar_init(sb + L_D1DN, 1);
        mbar_init(sb + L_F2_0, 128);  mbar_init(sb + L_F2_1, 128);
        mbar_init(sb + L_E2_0, 1);    mbar_init(sb + L_E2_1, 1);
        mbar_init(sb + L_WBAR, 1);
    }
    if (tid >= 128 && tid < 256) b1s[tid - 128] = b1[tid - 128];
    __syncthreads();
    uint32_t tmem;
    asm volatile("ld.shared.b32 %0, [%1];" : "=r"(tmem) : "r"(sb));
    const uint32_t tmem2 = tmem + 128;

    // ============ phase 1: D1 = xa @ W1 ============
    if (tid < 256) {
        const int row  = tid >> 1;
        const int r    = rowBase + row;
        const int half = tid & 1;
        uint32_t bo = (uint32_t)row * 64u + (uint32_t)half * 32u;
        const uint32_t sw0 = bo ^ ((bo >> 3) & 0x30);
        bo += 16u;
        const uint32_t sw1 = bo ^ ((bo >> 3) & 0x30);

        for (int c = 0; c < 4; c++) {
            const int s = c & 1;
            const int kb = c * 32 + half * 16;
            size_t off = (size_t)r * 128 + kb;
            float4 av[4];
            #pragma unroll
            for (int q = 0; q < 4; q++) av[q] = *(const float4*)(g_xa + off + q * 4);

            if (c >= 2) mbar_wait(sb + L_EMPT0 + s * 8, 0);

            const float* f = (const float*)av;
            uint32_t hi[8], lo[8];
            #pragma unroll
            for (int q = 0; q < 8; q++) {
                float a = f[2 * q], b = f[2 * q + 1];
                __nv_bfloat162 h = __float22bfloat162_rn(make_float2(a, b));
                hi[q] = *(uint32_t*)&h;
                lo[q] = pack_bf2(a - __bfloat162float(h.x), b - __bfloat162float(h.y));
            }
            char* stg = smem + L_ASTG + s * 16384;
            *(uint4*)(stg + sw0)        = *(uint4*)&hi[0];
            *(uint4*)(stg + sw1)        = *(uint4*)&hi[4];
            *(uint4*)(stg + 8192 + sw0) = *(uint4*)&lo[0];
            *(uint4*)(stg + 8192 + sw1) = *(uint4*)&lo[4];

            fence_async_shared();
            mbar_arrive(sb + L_FULL0 + s * 8);
        }
    } else if (tid == 256) {
        mbar_arrive_tx(sb + L_WBAR, 65536);
        bulk_g2s(sb + L_WHI, g_wbhi + woff1, 32768, sb + L_WBAR);
        bulk_g2s(sb + L_WLO, g_wblo + woff1, 32768, sb + L_WBAR);
        uint64_t dAhi[2], dAlo[2];
        #pragma unroll
        for (int s = 0; s < 2; s++) {
            dAhi[s] = make_desc64(sb + L_ASTG + s * 16384);
            dAlo[s] = make_desc64(sb + L_ASTG + s * 16384 + 8192);
        }
        mbar_wait(sb + L_WBAR, 0);
        for (int c = 0; c < 4; c++) {
            const int s = c & 1;
            mbar_wait(sb + L_FULL0 + s * 8, (c >> 1) & 1);
            uint64_t bh = make_desc64(sb + L_WHI + c * 8192);
            uint64_t bl = make_desc64(sb + L_WLO + c * 8192);
            #pragma unroll
            for (int ks = 0; ks < 2; ks++) {
                const uint64_t o = ks * 2;
                int first = (c == 0 && ks == 0);
                mma_bf16(tmem, dAhi[s] + o, bh + o, IDESC_BF16, first ? 0 : 1);
                mma_bf16(tmem, dAhi[s] + o, bl + o, IDESC_BF16, 1);
                mma_bf16(tmem, dAlo[s] + o, bh + o, IDESC_BF16, 1);
            }
            tc_commit(sb + L_EMPT0 + s * 8);
        }
        tc_commit(sb + L_D1DN);
    }

    // ============ phase 2: D2 = relu(D1+b1) @ W2 ============
    mbar_wait(sb + L_D1DN, 0);
    tc_fence_after();

    if (tid < 256) {
        const int sp  = wid & 3;
        const int grp = wid >> 2;
        const int r   = sp * 32 + lane;
        #pragma unroll
        for (int it = 0; it < 2; it++) {
            const int c = grp + it * 2;
            const int s = c & 1;
            if (it == 1) mbar_wait(sb + L_E2_0 + s * 8, 0);
            char* stg = smem + L_ASTG + s * 16384;
            #pragma unroll
            for (int hh = 0; hh < 2; hh++) {
                uint32_t regs[16];
                ldtm16(regs, tmem + c * 32 + hh * 16);
                tc_wait_ld();
                uint32_t hi[8], lo[8];
                #pragma unroll
                for (int q = 0; q < 8; q++) {
                    const int cb = c * 32 + hh * 16;
                    float a = fmaxf(__uint_as_float(regs[2 * q])     + b1s[cb + 2 * q],     0.f);
                    float b = fmaxf(__uint_as_float(regs[2 * q + 1]) + b1s[cb + 2 * q + 1], 0.f);
                    __nv_bfloat162 h = __float22bfloat162_rn(make_float2(a, b));
                    hi[q] = *(uint32_t*)&h;
                    lo[q] = pack_bf2(a - __bfloat162float(h.x), b - __bfloat162float(h.y));
                }
                uint32_t o0 = (uint32_t)r * 64u + hh * 32u;
                uint32_t o1 = o0 + 16u;
                o0 ^= ((o0 >> 3) & 0x30);
                o1 ^= ((o1 >> 3) & 0x30);
                *(uint4*)(stg + o0)        = *(uint4*)&hi[0];
                *(uint4*)(stg + o1)        = *(uint4*)&hi[4];
                *(uint4*)(stg + 8192 + o0) = *(uint4*)&lo[0];
                *(uint4*)(stg + 8192 + o1) = *(uint4*)&lo[4];
            }
            fence_async_shared();
            mbar_arrive(sb + L_F2_0 + s * 8);
        }
    } else if (tid == 256) {
        mbar_arrive_tx(sb + L_WBAR, 65536);
        bulk_g2s(sb + L_WHI, g_wbhi + woff2, 32768, sb + L_WBAR);
        bulk_g2s(sb + L_WLO, g_wblo + woff2, 32768, sb + L_WBAR);
        uint64_t dAhi[2], dAlo[2];
        #pragma unroll
        for (int s = 0; s < 2; s++) {
            dAhi[s] = make_desc64(sb + L_ASTG + s * 16384);
            dAlo[s] = make_desc64(sb + L_ASTG + s * 16384 + 8192);
        }
        mbar_wait(sb + L_WBAR, 1);
        for (int c = 0; c < 4; c++) {
            const int s = c & 1;
            if (c >= 2) mbar_wait(sb + L_E2_0 + s * 8, 0);
            mbar_wait(sb + L_F2_0 + s * 8, (c >> 1) & 1);
            uint64_t bh = make_desc64(sb + L_WHI + c * 8192);
            uint64_t bl = make_desc64(sb + L_WLO + c * 8192);
            #pragma unroll
            for (int ks = 0; ks < 2; ks++) {
                const uint64_t o = ks * 2;
                int first = (c == 0 && ks == 0);
                mma_bf16(tmem2, dAhi[s] + o, bh + o, IDESC_BF16, first ? 0 : 1);
                mma_bf16(tmem2, dAhi[s] + o, bl + o, IDESC_BF16, 1);
                mma_bf16(tmem2, dAlo[s] + o, bh + o, IDESC_BF16, 1);
            }
            tc_commit(sb + L_E2_0 + s * 8);
        }
    }

    // ============ epilogue: xn = x + relu(D2 + b2); write g_x (+ seed g_xa) =======
    mbar_wait(sb + L_E2_0, 1);
    mbar_wait(sb + L_E2_1, 1);
    tc_fence_after();
    if (tid < 256) {
        const int sp = wid & 3;
        const int h  = wid >> 2;
        const int r  = rowBase + sp * 32 + lane;
        const int cb = h * 64;
        uint32_t regs[64];
        ldtm32(regs,      tmem2 + cb);
        ldtm32(regs + 32, tmem2 + cb + 32);
        tc_wait_ld();
        size_t base = (size_t)r * 128 + cb;
        #pragma unroll
        for (int j = 0; j < 64; j += 4) {
            float4 o;
            o.x = fmaxf(__uint_as_float(regs[j + 0]) + __ldg(b2 + cb + j + 0), 0.f);
            o.y = fmaxf(__uint_as_float(regs[j + 1]) + __ldg(b2 + cb + j + 1), 0.f);
            o.z = fmaxf(__uint_as_float(regs[j + 2]) + __ldg(b2 + cb + j + 2), 0.f);
            o.w = fmaxf(__uint_as_float(regs[j + 3]) + __ldg(b2 + cb + j + 3), 0.f);
            float4 x0 = *(const float4*)(g_x + base + j);
            o.x += x0.x; o.y += x0.y; o.z += x0.z; o.w += x0.w;
            *(float4*)(g_x + base + j) = o;
            if (seed) *(float4*)(g_xa + base + j) = o;
        }
    }
    __syncthreads();
    if (wid == 0) tc_dealloc(tmem, 256);

#else  // fallback (family-PTX pass only)
    const int tid = threadIdx.x;
    const int rowBase = blockIdx.x * 128;
    if (tid >= 128) return;
    __shared__ float hrow[128];
    for (int m = 0; m < 128; m++) {
        const int r = rowBase + m;
        float acc = 0.f;
        for (int k = 0; k < 128; k++) {
            float a = g_xa[(size_t)r * 128 + k];
            int chunk = k >> 5, kk = k & 31;
            uint32_t off = (uint32_t)tid * 64u + (uint32_t)kk * 2u;
            off ^= ((off >> 3) & 0x30);
            int di = woff1 + chunk * 4096 + (int)(off >> 1);
            acc = fmaf(a, __bfloat162float(g_wbhi[di]) + __bfloat162float(g_wblo[di]), acc);
        }
        hrow[tid] = fmaxf(acc + b1[tid], 0.f);
        __syncthreads();
        float acc2 = 0.f;
        for (int k = 0; k < 128; k++) {
            int chunk = k >> 5, kk = k & 31;
            uint32_t off = (uint32_t)tid * 64u + (uint32_t)kk * 2u;
            off ^= ((off >> 3) & 0x30);
            int di = woff2 + chunk * 4096 + (int)(off >> 1);
            acc2 = fmaf(hrow[k], __bfloat162float(g_wbhi[di]) + __bfloat162float(g_wblo[di]), acc2);
        }
        float xn = g_x[(size_t)r * 128 + tid] + fmaxf(acc2 + b2[tid], 0.f);
        g_x[(size_t)r * 128 + tid] = xn;
        if (seed) g_xa[(size_t)r * 128 + tid] = xn;
        __syncthreads();
    }
#endif
}

// ---------------- segment softmax -------------------------------------------------
__global__ void seg_max_k(const int* __restrict__ n2g) {
    int i = blockIdx.x * blockDim.x + threadIdx.x;
    if (i >= V_) return;
    atomicMax(&g_menc[n2g[i]], encf(g_logit[i]));
}
__global__ void seg_exp_k(const int* __restrict__ n2g, float* __restrict__ out) {
    int i = blockIdx.x * blockDim.x + threadIdx.x;
    if (i >= V_) return;
    int gg = n2g[i];
    float m = decf(g_menc[gg]);
    float ex = expf(g_logit[i] - m);
    out[i] = ex;
    atomicAdd(&g_den[gg], ex);
}
__global__ void seg_div_k(const int* __restrict__ n2g, float* __restrict__ out) {
    int i = blockIdx.x * blockDim.x + threadIdx.x;
    if (i >= V_) return;
    out[i] = out[i] / g_den[n2g[i]];
}

// ---------------- launch -----------------------------------------------------------
extern "C" void kernel_launch(void* const* d_in, const int* in_sizes, int n_in,
                              void* d_out, int out_size)
{
    const float* x_inp   = (const float*)d_in[0];
    const int*   eidx    = (const int*)  d_in[1];
    const float* eattr   = (const float*)d_in[2];
    const float* x_upd   = (const float*)d_in[3];
    const float* Zc      = (const float*)d_in[4];
    const float* Zb      = (const float*)d_in[5];
    const int*   n2g     = (const int*)  d_in[6];
    const float* W_emb   = (const float*)d_in[7];
    const float* b_emb   = (const float*)d_in[8];
    const float* W_edge  = (const float*)d_in[9];
    const float* b_edge  = (const float*)d_in[10];
    const float* W1      = (const float*)d_in[11];
    const float* b1      = (const float*)d_in[12];
    const float* W2      = (const float*)d_in[13];
    const float* b2      = (const float*)d_in[14];
    const float* W_mlp1  = (const float*)d_in[15];
    const float* b_mlp1  = (const float*)d_in[16];
    const float* W_mlp2  = (const float*)d_in[17];
    const float* b_mlp2  = (const float*)d_in[18];
    float* out = (float*)d_out;

    cudaFuncSetAttribute(tc_gemm_k<384, 0>, cudaFuncAttributeMaxDynamicSharedMemorySize, SMEM_GEMM);
    cudaFuncSetAttribute(tc_gemm_k<192, 3>, cudaFuncAttributeMaxDynamicSharedMemorySize, SMEM_GEMM);
    cudaFuncSetAttribute(tc_layer_k,        cudaFuncAttributeMaxDynamicSharedMemorySize, SMEM_LAYER);

    const int GB = V_ / 128;   // 2048 tiles

    // launch 1: weight split + softmax scratch zero
    split_w_k<<<(WT_TOTAL + 255) / 256, 256>>>(W_emb, W1, W2, W_mlp1);
    // launch 2: EMB GEMM (blocks 0..2047, seeds g_xa) + edge embedding (2048..4095)
    tc_gemm_k<384, 0><<<GB + 2048, 288, SMEM_GEMM>>>(x_upd, Zc, Zb, n2g, b_emb,
                                                     W_edge, b_edge, eattr, 0);
    for (int l = 0; l < 4; l++) {
        scatter_k<<<E_ / 8, 256>>>(eidx, eidx + E_);
        tc_layer_k<<<GB, 288, SMEM_LAYER>>>(b1 + (size_t)l * 128, b2 + (size_t)l * 128,
                                            49152 + l * 16384, 114688 + l * 16384,
                                            l < 3 ? 1 : 0);
    }
    tc_gemm_k<192, 3><<<GB, 288, SMEM_GEMM>>>(x_inp, nullptr, nullptr, nullptr,
                                              b_mlp1, W_mlp2, b_mlp2, nullptr, 180224);

    seg_max_k<<<V_ / 256, 256>>>(n2g);
    seg_exp_k<<<V_ / 256, 256>>>(n2g, out);
    seg_div_k<<<V_ / 256, 256>>>(n2g, out);
}

// round 10
// speedup vs baseline: 3.7185x; 1.0240x over previous
#include <cuda_runtime.h>
#include <cuda_bf16.h>
#include <cstdint>

#define V_  262144
#define E_  524288
#define NG  8192
#define H_  128

// ---------------- tcgen05 feature gate ---------------------------------------------
#if defined(__CUDA_ARCH_FEAT_SM103_ALL) || defined(__CUDA_ARCH_FEAT_SM100_ALL) || defined(__CUDA_ARCH_FEAT_SM101_ALL)
#define HAS_TC 1
#endif
#if !defined(HAS_TC) && defined(__CUDA_ARCH_HAS_FEATURE__)
#if __CUDA_ARCH_HAS_FEATURE__(SM103_ALL)
#define HAS_TC 1
#endif
#endif
#ifndef HAS_TC
#define HAS_TC 0
#endif

// ---------------- scratch globals ------------------------------------------------
__device__ float    g_x[(size_t)V_ * H_];     // current node features
__device__ float    g_xa[(size_t)V_ * H_];    // x + aggregated messages (seeded w/ x)
__device__ __align__(8) __nv_bfloat162 g_e2[(size_t)E_ * 64];  // edge emb, bf16x2
__device__ float    g_logit[V_];
__device__ unsigned g_menc[NG];
__device__ float    g_den[NG];
// weights: transposed, bf16 hi/lo split, PRE-SWIZZLED (SW64) 32-K-chunk-contiguous
#define WT_TOTAL 204800
__device__ __align__(16) __nv_bfloat16 g_wbhi[WT_TOTAL];
__device__ __align__(16) __nv_bfloat16 g_wblo[WT_TOTAL];

// ---------------- PTX helpers -----------------------------------------------------
__device__ __forceinline__ uint32_t smem_u32(const void* p) {
    uint32_t a;
    asm("{ .reg .u64 t; cvta.to.shared.u64 t, %1; cvt.u32.u64 %0, t; }" : "=r"(a) : "l"(p));
    return a;
}
__device__ __forceinline__ void mbar_init(uint32_t mbar, uint32_t cnt) {
    asm volatile("mbarrier.init.shared.b64 [%0], %1;" :: "r"(mbar), "r"(cnt) : "memory");
}
__device__ __forceinline__ void mbar_arrive(uint32_t mbar) {
    asm volatile("mbarrier.arrive.shared.b64 _, [%0];" :: "r"(mbar) : "memory");
}
__device__ __forceinline__ void mbar_arrive_tx(uint32_t mbar, uint32_t tx) {
    asm volatile("mbarrier.arrive.expect_tx.shared.b64 _, [%0], %1;"
                 :: "r"(mbar), "r"(tx) : "memory");
}
__device__ __forceinline__ void mbar_wait(uint32_t mbar, uint32_t parity) {
    asm volatile(
        "{\n\t.reg .pred P;\n\tWL_%=:\n\t"
        "mbarrier.try_wait.parity.acquire.cta.shared::cta.b64 P, [%0], %1, 0x989680;\n\t"
        "@!P bra WL_%=;\n\t}" :: "r"(mbar), "r"(parity) : "memory");
}
__device__ __forceinline__ void fence_async_shared() {
    asm volatile("fence.proxy.async.shared::cta;" ::: "memory");
}
__device__ __forceinline__ void bulk_g2s(uint32_t dst, const void* src, uint32_t bytes,
                                         uint32_t mbar) {
    uint64_t gsrc;
    asm("cvta.to.global.u64 %0, %1;" : "=l"(gsrc) : "l"(src));
    asm volatile(
        "cp.async.bulk.shared::cta.global.mbarrier::complete_tx::bytes [%0], [%1], %2, [%3];"
        :: "r"(dst), "l"(gsrc), "r"(bytes), "r"(mbar) : "memory");
}

#if HAS_TC
__device__ __forceinline__ void mma_bf16(uint32_t d, uint64_t a, uint64_t b,
                                         uint32_t idesc, int acc) {
    asm volatile(
        "{\n\t.reg .pred p;\n\tsetp.ne.b32 p, %4, 0;\n\t"
        "tcgen05.mma.cta_group::1.kind::f16 [%0], %1, %2, %3, p;\n\t}"
        :: "r"(d), "l"(a), "l"(b), "r"(idesc), "r"(acc) : "memory");
}
__device__ __forceinline__ void tc_commit(uint32_t mbar) {
    asm volatile(
        "tcgen05.commit.cta_group::1.mbarrier::arrive::one.shared::cluster.b64 [%0];"
        :: "r"(mbar) : "memory");
}
__device__ __forceinline__ void tc_alloc(uint32_t smem_dst, uint32_t ncols) {
    asm volatile("tcgen05.alloc.cta_group::1.sync.aligned.shared::cta.b32 [%0], %1;"
                 :: "r"(smem_dst), "r"(ncols) : "memory");
}
__device__ __forceinline__ void tc_dealloc(uint32_t tmem, uint32_t ncols) {
    asm volatile("tcgen05.dealloc.cta_group::1.sync.aligned.b32 %0, %1;"
                 :: "r"(tmem), "r"(ncols));
}
__device__ __forceinline__ void tc_relinquish() {
    asm volatile("tcgen05.relinquish_alloc_permit.cta_group::1.sync.aligned;");
}
__device__ __forceinline__ void tc_fence_after() {
    asm volatile("tcgen05.fence::after_thread_sync;" ::: "memory");
}
__device__ __forceinline__ void tc_wait_ld() {
    asm volatile("tcgen05.wait::ld.sync.aligned;" ::: "memory");
}
__device__ __forceinline__ void ldtm32(uint32_t* r, uint32_t addr) {
    asm volatile(
        "tcgen05.ld.sync.aligned.32x32b.x32.b32 "
        "{%0, %1, %2, %3, %4, %5, %6, %7, %8, %9, %10, %11, %12, %13, %14, %15, "
        " %16, %17, %18, %19, %20, %21, %22, %23, %24, %25, %26, %27, %28, %29, %30, %31}, [%32];"
        : "=r"(r[0]), "=r"(r[1]), "=r"(r[2]), "=r"(r[3]), "=r"(r[4]), "=r"(r[5]),
          "=r"(r[6]), "=r"(r[7]), "=r"(r[8]), "=r"(r[9]), "=r"(r[10]), "=r"(r[11]),
          "=r"(r[12]), "=r"(r[13]), "=r"(r[14]), "=r"(r[15]), "=r"(r[16]), "=r"(r[17]),
          "=r"(r[18]), "=r"(r[19]), "=r"(r[20]), "=r"(r[21]), "=r"(r[22]), "=r"(r[23]),
          "=r"(r[24]), "=r"(r[25]), "=r"(r[26]), "=r"(r[27]), "=r"(r[28]), "=r"(r[29]),
          "=r"(r[30]), "=r"(r[31])
        : "r"(addr));
}
__device__ __forceinline__ void ldtm16(uint32_t* r, uint32_t addr) {
    asm volatile(
        "tcgen05.ld.sync.aligned.32x32b.x16.b32 "
        "{%0, %1, %2, %3, %4, %5, %6, %7, %8, %9, %10, %11, %12, %13, %14, %15}, [%16];"
        : "=r"(r[0]), "=r"(r[1]), "=r"(r[2]), "=r"(r[3]), "=r"(r[4]), "=r"(r[5]),
          "=r"(r[6]), "=r"(r[7]), "=r"(r[8]), "=r"(r[9]), "=r"(r[10]), "=r"(r[11]),
          "=r"(r[12]), "=r"(r[13]), "=r"(r[14]), "=r"(r[15])
        : "r"(addr));
}
#endif  // HAS_TC

__device__ __forceinline__ unsigned encf(float f) {
    unsigned u = __float_as_uint(f);
    return (u & 0x80000000u) ? ~u : (u | 0x80000000u);
}
__device__ __forceinline__ float decf(unsigned u) {
    return (u & 0x80000000u) ? __uint_as_float(u & 0x7fffffffu) : __uint_as_float(~u);
}

// SW64 K-major descriptor: layout=4, version=1, SBO=32, LBO=1
static __device__ __forceinline__ uint64_t make_desc64(uint32_t addr) {
    const uint64_t base =
        (uint64_t(4) << 61) | (uint64_t(1) << 46) | (uint64_t(32) << 32) | (uint64_t(1) << 16);
    return base | ((uint64_t)(addr >> 4) & 0x3FFF);
}

// idesc kind::f16: cF32(1<<4) | aBF16(1<<7) | bBF16(1<<10) | N=128 (16<<17) | M=128 (8<<24)
#define IDESC_BF16 0x08200490u

// ------- streaming GEMM smem layout (EMB / HEAD) -------
#define SM_TMEMP 0
#define SM_FULL0 16
#define SM_FULL1 24
#define SM_EMPT0 32
#define SM_EMPT1 40
#define SM_PART  256
#define SM_TILES 2048
#define STG_SZ   32768
#define OFF_AHI  0
#define OFF_ALO  8192
#define OFF_BHI  16384
#define OFF_BLO  24576
#define SMEM_GEMM (SM_TILES + 2 * STG_SZ)

// ------- fused layer smem layout (resident B, 4 hi-only A stages) -------
#define L_F1    16           // + c*8, c in 0..3
#define L_F2    48           // + c*8
#define L_D1DN  80
#define L_E2DN  88
#define L_WBAR  96
#define L_B1S   128          // 512B
#define L_ASTG  1024         // + c*8192 : Ahi stage per chunk (4 x 8KB)
#define L_WHI   33792        // 32KB resident W hi
#define L_WLO   66560        // 32KB resident W lo
#define SMEM_LAYER 99328

__device__ __forceinline__ uint32_t pack_bf2(float a, float b) {
    __nv_bfloat162 h = __float22bfloat162_rn(make_float2(a, b));
    return *(uint32_t*)&h;
}

// ---------------- weight split (+ softmax scratch zero) ---------------------------
__global__ void split_w_k(const float* __restrict__ We, const float* __restrict__ W1,
                          const float* __restrict__ W2, const float* __restrict__ Wm)
{
    int i = blockIdx.x * 256 + threadIdx.x;
    if (i >= WT_TOTAL) return;
    if (i < NG) { g_menc[i] = 0u; g_den[i] = 0.f; }
    int base, n, k, K;
    if (i < 49152)       { base = 0;      int j = i;          K = 384; n = j / K; k = j % K; }
    else if (i < 114688) { int j = i - 49152;  int l = j >> 14; base = 49152 + l*16384;  j &= 16383; K = 128; n = j >> 7; k = j & 127; }
    else if (i < 180224) { int j = i - 114688; int l = j >> 14; base = 114688 + l*16384; j &= 16383; K = 128; n = j >> 7; k = j & 127; }
    else                 { base = 180224; int j = i - 180224;  K = 192; n = j / K; k = j % K; }
    float v;
    if (base == 0)           v = We[k * 128 + n];
    else if (base < 114688)  v = W1[(base - 49152) / 16384 * 16384 + k * 128 + n];
    else if (base < 180224)  v = W2[(base - 114688) / 16384 * 16384 + k * 128 + n];
    else                     v = Wm[k * 128 + n];

    __nv_bfloat16 hi = __float2bfloat16_rn(v);
    __nv_bfloat16 lo = __float2bfloat16_rn(v - __bfloat162float(hi));
    int chunk = k >> 5, kk = k & 31;
    uint32_t off = (uint32_t)n * 64u + (uint32_t)kk * 2u;
    off ^= ((off >> 3) & 0x30);               // SW64 swizzle
    int di = base + chunk * 4096 + (int)(off >> 1);
    g_wbhi[di] = hi;
    g_wblo[di] = lo;
}

// ---------------- scatter: g_xa[dst] += relu(x[src] + e) --------------------------
__global__ __launch_bounds__(256) void scatter_k(
    const int* __restrict__ src, const int* __restrict__ dst)
{
    const int warp = (blockIdx.x * blockDim.x + threadIdx.x) >> 5;
    const int lane = threadIdx.x & 31;
    if (warp >= E_) return;
    const int s = src[warp];
    const int d = dst[warp];
    float4 xv = *(const float4*)(g_x + (size_t)s * 128 + lane * 4);
    const __nv_bfloat162* ep = g_e2 + (size_t)warp * 64 + lane * 2;
    float2 e0 = __bfloat1622float2(ep[0]);
    float2 e1 = __bfloat1622float2(ep[1]);
    float4 m;
    m.x = fmaxf(xv.x + e0.x, 0.f);
    m.y = fmaxf(xv.y + e0.y, 0.f);
    m.z = fmaxf(xv.z + e1.x, 0.f);
    m.w = fmaxf(xv.w + e1.y, 0.f);
    atomicAdd((float4*)(g_xa + (size_t)d * 128 + lane * 4), m);
}

// ---------------- EMB(+edge blocks) / HEAD GEMM (streaming B pipeline) ------------
template <int K, int MODE>
__global__ __launch_bounds__(288, 2) void tc_gemm_k(
    const float* __restrict__ A0, const float* __restrict__ A1,
    const float* __restrict__ A2, const int* __restrict__ n2g,
    const float* __restrict__ bias, const float* __restrict__ w2,
    const float* __restrict__ b2s, const float* __restrict__ eattr, int woff)
{
    extern __shared__ __align__(1024) char smem[];
    const int tid  = threadIdx.x;

    // ---------------- edge-embedding blocks (MODE 0 only) ----------------
    if (MODE == 0 && blockIdx.x >= V_ / 128) {
        const int eb = blockIdx.x - V_ / 128;
        const int e0 = eb * 256;
        float* Ws = (float*)smem;
        float* Ae = (float*)(smem + 8192);
        float* bs = (float*)(smem + 24576);
        for (int i = tid; i < 2048; i += 288) Ws[i] = w2[i];
        for (int i = tid; i < 4096; i += 288) Ae[i] = eattr[(size_t)e0 * 16 + i];
        if (tid < 128) bs[tid] = b2s[tid];
        __syncthreads();
        if (tid < 256) {
            const int col = tid & 127, half = tid >> 7;
            float w[16];
            #pragma unroll
            for (int k = 0; k < 16; k++) w[k] = Ws[k * 128 + col];
            const float bb = bs[col];
            for (int ee = 0; ee < 128; ee++) {
                const int e = half * 128 + ee;
                const float4* a4 = (const float4*)&Ae[e * 16];
                float4 x0 = a4[0], x1 = a4[1], x2 = a4[2], x3 = a4[3];
                float s = bb;
                s = fmaf(x0.x, w[0],  s); s = fmaf(x0.y, w[1],  s);
                s = fmaf(x0.z, w[2],  s); s = fmaf(x0.w, w[3],  s);
                s = fmaf(x1.x, w[4],  s); s = fmaf(x1.y, w[5],  s);
                s = fmaf(x1.z, w[6],  s); s = fmaf(x1.w, w[7],  s);
                s = fmaf(x2.x, w[8],  s); s = fmaf(x2.y, w[9],  s);
                s = fmaf(x2.z, w[10], s); s = fmaf(x2.w, w[11], s);
                s = fmaf(x3.x, w[12], s); s = fmaf(x3.y, w[13], s);
                s = fmaf(x3.z, w[14], s); s = fmaf(x3.w, w[15], s);
                s = fmaxf(s, 0.f);
                float snb = __shfl_down_sync(0xffffffffu, s, 1);
                if ((col & 1) == 0) {
                    uint32_t pk = pack_bf2(s, snb);
                    *(uint32_t*)&g_e2[(size_t)(e0 + e) * 64 + (col >> 1)] = pk;
                }
            }
        }
        return;
    }

#if HAS_TC
    const uint32_t sb = smem_u32(smem);
    const int wid  = tid >> 5;
    const int lane = tid & 31;
    const int rowBase = blockIdx.x * 128;
    const int NCH = K / 32;

    if (wid == 0) { tc_alloc(sb + SM_TMEMP, 128); tc_relinquish(); }
    if (tid == 0) {
        mbar_init(sb + SM_FULL0, 257); mbar_init(sb + SM_FULL1, 257);
        mbar_init(sb + SM_EMPT0, 1);   mbar_init(sb + SM_EMPT1, 1);
    }
    __syncthreads();
    uint32_t tmem;
    asm volatile("ld.shared.b32 %0, [%1];" : "=r"(tmem) : "r"(sb + SM_TMEMP));

    if (tid < 256) {
        const int row  = tid >> 1;
        const int r    = rowBase + row;
        const int half = tid & 1;
        uint32_t bo = (uint32_t)row * 64u + (uint32_t)half * 32u;
        const uint32_t sw0 = bo ^ ((bo >> 3) & 0x30);
        bo += 16u;
        const uint32_t sw1 = bo ^ ((bo >> 3) & 0x30);
        int gg = 0;
        if (MODE == 0) gg = __ldg(n2g + r);

        for (int c = 0; c < NCH; c++) {
            const int s = c & 1;
            const int kb = c * 32 + half * 16;
            float4 av[4];
            if (MODE == 0) {
                const float* p = (kb < 128) ? A0 + (size_t)r * 128 + kb
                               : (kb < 256) ? A1 + (size_t)gg * 128 + (kb - 128)
                                            : A2 + (size_t)gg * 128 + (kb - 256);
                #pragma unroll
                for (int q = 0; q < 4; q++) av[q] = *(const float4*)(p + q * 4);
            } else {
                const float* p = (kb < 128) ? g_x + (size_t)r * 128 + kb
                                            : A0 + (size_t)r * 64 + (kb - 128);
                #pragma unroll
                for (int q = 0; q < 4; q++) av[q] = *(const float4*)(p + q * 4);
            }

            if (c >= 2) mbar_wait(sb + SM_EMPT0 + s * 8, ((c >> 1) + 1) & 1);

            const float* f = (const float*)av;
            uint32_t hi[8], lo[8];
            #pragma unroll
            for (int q = 0; q < 8; q++) {
                float a = f[2 * q], b = f[2 * q + 1];
                __nv_bfloat162 h = __float22bfloat162_rn(make_float2(a, b));
                hi[q] = *(uint32_t*)&h;
                lo[q] = pack_bf2(a - __bfloat162float(h.x), b - __bfloat162float(h.y));
            }
            char* stg = smem + SM_TILES + s * STG_SZ;
            *(uint4*)(stg + OFF_AHI + sw0) = *(uint4*)&hi[0];
            *(uint4*)(stg + OFF_AHI + sw1) = *(uint4*)&hi[4];
            *(uint4*)(stg + OFF_ALO + sw0) = *(uint4*)&lo[0];
            *(uint4*)(stg + OFF_ALO + sw1) = *(uint4*)&lo[4];

            fence_async_shared();
            mbar_arrive(sb + SM_FULL0 + s * 8);
        }
    } else if (tid == 256) {
        uint64_t dAhi[2], dAlo[2], dBhi[2], dBlo[2];
        #pragma unroll
        for (int s = 0; s < 2; s++) {
            uint32_t st = sb + SM_TILES + s * STG_SZ;
            dAhi[s] = make_desc64(st + OFF_AHI);
            dAlo[s] = make_desc64(st + OFF_ALO);
            dBhi[s] = make_desc64(st + OFF_BHI);
            dBlo[s] = make_desc64(st + OFF_BLO);
        }
        for (int c = 0; c < NCH; c++) {
            const int s = c & 1;
            if (c >= 2) mbar_wait(sb + SM_EMPT0 + s * 8, ((c >> 1) + 1) & 1);
            const uint32_t full = sb + SM_FULL0 + s * 8;
            mbar_arrive_tx(full, 16384);
            const uint32_t st = sb + SM_TILES + s * STG_SZ;
            bulk_g2s(st + OFF_BHI, g_wbhi + woff + c * 4096, 8192, full);
            bulk_g2s(st + OFF_BLO, g_wblo + woff + c * 4096, 8192, full);
            mbar_wait(full, (c >> 1) & 1);
            #pragma unroll
            for (int ks = 0; ks < 2; ks++) {
                const uint64_t o = ks * 2;
                int first = (c == 0 && ks == 0);
                mma_bf16(tmem, dAhi[s] + o, dBhi[s] + o, IDESC_BF16, first ? 0 : 1);
                mma_bf16(tmem, dAhi[s] + o, dBlo[s] + o, IDESC_BF16, 1);
                mma_bf16(tmem, dAlo[s] + o, dBhi[s] + o, IDESC_BF16, 1);
            }
            tc_commit(sb + SM_EMPT0 + s * 8);
        }
    }

    {
        const int L = NCH - 1;
        mbar_wait(sb + SM_EMPT0 + (L & 1) * 8, (L >> 1) & 1);
        tc_fence_after();
    }
    if (tid < 256) {
        const int sp = wid & 3;
        const int h  = wid >> 2;
        const int r  = rowBase + sp * 32 + lane;
        const int cb = h * 64;
        uint32_t regs[64];
        ldtm32(regs,      tmem + cb);
        ldtm32(regs + 32, tmem + cb + 32);
        tc_wait_ld();

        if (MODE == 3) {
            float p = 0.f;
            #pragma unroll
            for (int j = 0; j < 64; j++) {
                float t = fmaxf(__uint_as_float(regs[j]) + __ldg(bias + cb + j), 0.f);
                p = fmaf(t, __ldg(w2 + cb + j), p);
            }
            ((float*)(smem + SM_PART))[h * 128 + sp * 32 + lane] = p;
        } else {
            size_t base = (size_t)r * 128 + cb;
            #pragma unroll
            for (int j = 0; j < 64; j += 4) {
                float4 o;
                o.x = fmaxf(__uint_as_float(regs[j + 0]) + __ldg(bias + cb + j + 0), 0.f);
                o.y = fmaxf(__uint_as_float(regs[j + 1]) + __ldg(bias + cb + j + 1), 0.f);
                o.z = fmaxf(__uint_as_float(regs[j + 2]) + __ldg(bias + cb + j + 2), 0.f);
                o.w = fmaxf(__uint_as_float(regs[j + 3]) + __ldg(bias + cb + j + 3), 0.f);
                *(float4*)(g_x + base + j) = o;
                *(float4*)(g_xa + base + j) = o;     // seed x+agg accumulator
            }
        }
    }
    __syncthreads();
    if (MODE == 3 && tid < 128) {
        const float* part = (const float*)(smem + SM_PART);
        g_logit[rowBase + tid] = part[tid] + part[128 + tid] + b2s[0];
    }
    if (wid == 0) tc_dealloc(tmem, 128);

#else  // fallback (family-PTX pass only)
    const int rowBase = blockIdx.x * 128;
    if (tid >= 128) return;
    __shared__ float col[128];
    for (int m = 0; m < 128; m++) {
        const int r = rowBase + m;
        float acc = 0.f;
        for (int k = 0; k < K; k++) {
            float a;
            if (MODE == 0) {
                if (k < 128) a = A0[(size_t)r * 128 + k];
                else {
                    int gg = n2g[r];
                    a = (k < 256) ? A1[(size_t)gg * 128 + (k - 128)]
                                  : A2[(size_t)gg * 128 + (k - 256)];
                }
            } else {
                a = (k < 128) ? g_x[(size_t)r * 128 + k] : A0[(size_t)r * 64 + (k - 128)];
            }
            int chunk = k >> 5, kk = k & 31;
            uint32_t off = (uint32_t)tid * 64u + (uint32_t)kk * 2u;
            off ^= ((off >> 3) & 0x30);
            int di = woff + chunk * 4096 + (int)(off >> 1);
            float w = __bfloat162float(g_wbhi[di]) + __bfloat162float(g_wblo[di]);
            acc = fmaf(a, w, acc);
        }
        if (MODE == 3) {
            col[tid] = fmaxf(acc + bias[tid], 0.f) * w2[tid];
            __syncthreads();
            if (tid == 0) {
                float p = 0.f;
                for (int j = 0; j < 128; j++) p += col[j];
                g_logit[r] = p + b2s[0];
            }
            __syncthreads();
        } else {
            float o = fmaxf(acc + bias[tid], 0.f);
            g_x[(size_t)r * 128 + tid] = o;
            g_xa[(size_t)r * 128 + tid] = o;
        }
    }
#endif
}

// ---------------- fused GINE layer (resident-B, 4 hi-only A stages) ---------------
// x += relu(relu(xa@W1+b1)@W2+b2) ; A = bf16(activation), B = Whi+Wlo (2-term MMA)
__global__ __launch_bounds__(288, 2) void tc_layer_k(
    const float* __restrict__ b1, const float* __restrict__ b2,
    int woff1, int woff2, int seed)
{
#if HAS_TC
    extern __shared__ __align__(1024) char smem[];
    const uint32_t sb = smem_u32(smem);
    const int tid  = threadIdx.x;
    const int wid  = tid >> 5;
    const int lane = tid & 31;
    const int rowBase = blockIdx.x * 128;
    float* b1s = (float*)(smem + L_B1S);

    if (wid == 0) { tc_alloc(sb, 256); tc_relinquish(); }
    if (tid == 0) {
        #pragma unroll
        for (int c = 0; c < 4; c++) {
            mbar_init(sb + L_F1 + c * 8, 256);
            mbar_init(sb + L_F2 + c * 8, 256);
        }
        mbar_init(sb + L_D1DN, 1);
        mbar_init(sb + L_E2DN, 1);
        mbar_init(sb + L_WBAR, 1);
    }
    if (tid >= 128 && tid < 256) b1s[tid - 128] = b1[tid - 128];
    __syncthreads();
    uint32_t tmem;
    asm volatile("ld.shared.b32 %0, [%1];" : "=r"(tmem) : "r"(sb));
    const uint32_t tmem2 = tmem + 128;

    // ============ phase 1: D1 = bf16(xa) @ W1 (4 chunks, no backpressure) ============
    if (tid < 256) {
        const int row  = tid >> 1;
        const int r    = rowBase + row;
        const int half = tid & 1;
        uint32_t bo = (uint32_t)row * 64u + (uint32_t)half * 32u;
        const uint32_t sw0 = bo ^ ((bo >> 3) & 0x30);
        bo += 16u;
        const uint32_t sw1 = bo ^ ((bo >> 3) & 0x30);

        #pragma unroll
        for (int c = 0; c < 4; c++) {
            size_t off = (size_t)r * 128 + c * 32 + half * 16;
            float4 av[4];
            #pragma unroll
            for (int q = 0; q < 4; q++) av[q] = *(const float4*)(g_xa + off + q * 4);
            const float* f = (const float*)av;
            uint32_t hi[8];
            #pragma unroll
            for (int q = 0; q < 8; q++) hi[q] = pack_bf2(f[2 * q], f[2 * q + 1]);
            char* stg = smem + L_ASTG + c * 8192;
            *(uint4*)(stg + sw0) = *(uint4*)&hi[0];
            *(uint4*)(stg + sw1) = *(uint4*)&hi[4];
            fence_async_shared();
            mbar_arrive(sb + L_F1 + c * 8);
        }
    } else if (tid == 256) {
        mbar_arrive_tx(sb + L_WBAR, 65536);
        bulk_g2s(sb + L_WHI, g_wbhi + woff1, 32768, sb + L_WBAR);
        bulk_g2s(sb + L_WLO, g_wblo + woff1, 32768, sb + L_WBAR);
        uint64_t dA[4];
        #pragma unroll
        for (int c = 0; c < 4; c++) dA[c] = make_desc64(sb + L_ASTG + c * 8192);
        mbar_wait(sb + L_WBAR, 0);
        for (int c = 0; c < 4; c++) {
            mbar_wait(sb + L_F1 + c * 8, 0);
            uint64_t bh = make_desc64(sb + L_WHI + c * 8192);
            uint64_t bl = make_desc64(sb + L_WLO + c * 8192);
            #pragma unroll
            for (int ks = 0; ks < 2; ks++) {
                const uint64_t o = ks * 2;
                int first = (c == 0 && ks == 0);
                mma_bf16(tmem, dA[c] + o, bh + o, IDESC_BF16, first ? 0 : 1);
                mma_bf16(tmem, dA[c] + o, bl + o, IDESC_BF16, 1);
            }
        }
        tc_commit(sb + L_D1DN);
        // W2 load: safe only after phase-1 MMAs drain (they read W1 region)
        mbar_wait(sb + L_D1DN, 0);
        mbar_arrive_tx(sb + L_WBAR, 65536);
        bulk_g2s(sb + L_WHI, g_wbhi + woff2, 32768, sb + L_WBAR);
        bulk_g2s(sb + L_WLO, g_wblo + woff2, 32768, sb + L_WBAR);
        mbar_wait(sb + L_WBAR, 1);
        for (int c = 0; c < 4; c++) {
            mbar_wait(sb + L_F2 + c * 8, 0);
            uint64_t bh = make_desc64(sb + L_WHI + c * 8192);
            uint64_t bl = make_desc64(sb + L_WLO + c * 8192);
            #pragma unroll
            for (int ks = 0; ks < 2; ks++) {
                const uint64_t o = ks * 2;
                int first = (c == 0 && ks == 0);
                mma_bf16(tmem2, dA[c] + o, bh + o, IDESC_BF16, first ? 0 : 1);
                mma_bf16(tmem2, dA[c] + o, bl + o, IDESC_BF16, 1);
            }
        }
        tc_commit(sb + L_E2DN);
    }

    // ============ phase 2 producers: A2 = bf16(relu(D1 + b1)) ============
    if (tid < 256) {
        mbar_wait(sb + L_D1DN, 0);
        tc_fence_after();
        const int sp = wid & 3;
        const int hh = wid >> 2;
        const int r  = sp * 32 + lane;
        uint32_t o0 = (uint32_t)r * 64u + (uint32_t)hh * 32u;
        const uint32_t so0 = o0 ^ ((o0 >> 3) & 0x30);
        o0 += 16u;
        const uint32_t so1 = o0 ^ ((o0 >> 3) & 0x30);
        #pragma unroll
        for (int c = 0; c < 4; c++) {
            uint32_t regs[16];
            ldtm16(regs, tmem + c * 32 + hh * 16);
            tc_wait_ld();
            const int cb = c * 32 + hh * 16;
            uint32_t hi[8];
            #pragma unroll
            for (int q = 0; q < 8; q++) {
                float a = fmaxf(__uint_as_float(regs[2 * q])     + b1s[cb + 2 * q],     0.f);
                float b = fmaxf(__uint_as_float(regs[2 * q + 1]) + b1s[cb + 2 * q + 1], 0.f);
                hi[q] = pack_bf2(a, b);
            }
            char* stg = smem + L_ASTG + c * 8192;
            *(uint4*)(stg + so0) = *(uint4*)&hi[0];
            *(uint4*)(stg + so1) = *(uint4*)&hi[4];
            fence_async_shared();
            mbar_arrive(sb + L_F2 + c * 8);
        }
    }

    // ============ epilogue: g_x += relu(D2 + b2); seed g_xa ============
    mbar_wait(sb + L_E2DN, 0);
    tc_fence_after();
    if (tid < 256) {
        const int sp = wid & 3;
        const int h  = wid >> 2;
        const int r  = rowBase + sp * 32 + lane;
        const int cb = h * 64;
        uint32_t regs[64];
        ldtm32(regs,      tmem2 + cb);
        ldtm32(regs + 32, tmem2 + cb + 32);
        tc_wait_ld();
        size_t base = (size_t)r * 128 + cb;
        #pragma unroll
        for (int j = 0; j < 64; j += 4) {
            float4 o;
            o.x = fmaxf(__uint_as_float(regs[j + 0]) + __ldg(b2 + cb + j + 0), 0.f);
            o.y = fmaxf(__uint_as_float(regs[j + 1]) + __ldg(b2 + cb + j + 1), 0.f);
            o.z = fmaxf(__uint_as_float(regs[j + 2]) + __ldg(b2 + cb + j + 2), 0.f);
            o.w = fmaxf(__uint_as_float(regs[j + 3]) + __ldg(b2 + cb + j + 3), 0.f);
            float4 x0 = *(const float4*)(g_x + base + j);
            o.x += x0.x; o.y += x0.y; o.z += x0.z; o.w += x0.w;
            *(float4*)(g_x + base + j) = o;
            if (seed) *(float4*)(g_xa + base + j) = o;
        }
    }
    __syncthreads();
    if (wid == 0) tc_dealloc(tmem, 256);

#else  // fallback (family-PTX pass only)
    const int tid = threadIdx.x;
    const int rowBase = blockIdx.x * 128;
    if (tid >= 128) return;
    __shared__ float hrow[128];
    for (int m = 0; m < 128; m++) {
        const int r = rowBase + m;
        float acc = 0.f;
        for (int k = 0; k < 128; k++) {
            float a = g_xa[(size_t)r * 128 + k];
            int chunk = k >> 5, kk = k & 31;
            uint32_t off = (uint32_t)tid * 64u + (uint32_t)kk * 2u;
            off ^= ((off >> 3) & 0x30);
            int di = woff1 + chunk * 4096 + (int)(off >> 1);
            acc = fmaf(a, __bfloat162float(g_wbhi[di]) + __bfloat162float(g_wblo[di]), acc);
        }
        hrow[tid] = fmaxf(acc + b1[tid], 0.f);
        __syncthreads();
        float acc2 = 0.f;
        for (int k = 0; k < 128; k++) {
            int chunk = k >> 5, kk = k & 31;
            uint32_t off = (uint32_t)tid * 64u + (uint32_t)kk * 2u;
            off ^= ((off >> 3) & 0x30);
            int di = woff2 + chunk * 4096 + (int)(off >> 1);
            acc2 = fmaf(hrow[k], __bfloat162float(g_wbhi[di]) + __bfloat162float(g_wblo[di]), acc2);
        }
        float xn = g_x[(size_t)r * 128 + tid] + fmaxf(acc2 + b2[tid], 0.f);
        g_x[(size_t)r * 128 + tid] = xn;
        if (seed) g_xa[(size_t)r * 128 + tid] = xn;
        __syncthreads();
    }
#endif
}

// ---------------- segment softmax -------------------------------------------------
__global__ void seg_max_k(const int* __restrict__ n2g) {
    int i = blockIdx.x * blockDim.x + threadIdx.x;
    if (i >= V_) return;
    atomicMax(&g_menc[n2g[i]], encf(g_logit[i]));
}
__global__ void seg_exp_k(const int* __restrict__ n2g, float* __restrict__ out) {
    int i = blockIdx.x * blockDim.x + threadIdx.x;
    if (i >= V_) return;
    int gg = n2g[i];
    float m = decf(g_menc[gg]);
    float ex = expf(g_logit[i] - m);
    out[i] = ex;
    atomicAdd(&g_den[gg], ex);
}
__global__ void seg_div_k(const int* __restrict__ n2g, float* __restrict__ out) {
    int i = blockIdx.x * blockDim.x + threadIdx.x;
    if (i >= V_) return;
    out[i] = out[i] / g_den[n2g[i]];
}

// ---------------- launch -----------------------------------------------------------
extern "C" void kernel_launch(void* const* d_in, const int* in_sizes, int n_in,
                              void* d_out, int out_size)
{
    const float* x_inp   = (const float*)d_in[0];
    const int*   eidx    = (const int*)  d_in[1];
    const float* eattr   = (const float*)d_in[2];
    const float* x_upd   = (const float*)d_in[3];
    const float* Zc      = (const float*)d_in[4];
    const float* Zb      = (const float*)d_in[5];
    const int*   n2g     = (const int*)  d_in[6];
    const float* W_emb   = (const float*)d_in[7];
    const float* b_emb   = (const float*)d_in[8];
    const float* W_edge  = (const float*)d_in[9];
    const float* b_edge  = (const float*)d_in[10];
    const float* W1      = (const float*)d_in[11];
    const float* b1      = (const float*)d_in[12];
    const float* W2      = (const float*)d_in[13];
    const float* b2      = (const float*)d_in[14];
    const float* W_mlp1  = (const float*)d_in[15];
    const float* b_mlp1  = (const float*)d_in[16];
    const float* W_mlp2  = (const float*)d_in[17];
    const float* b_mlp2  = (const float*)d_in[18];
    float* out = (float*)d_out;

    cudaFuncSetAttribute(tc_gemm_k<384, 0>, cudaFuncAttributeMaxDynamicSharedMemorySize, SMEM_GEMM);
    cudaFuncSetAttribute(tc_gemm_k<192, 3>, cudaFuncAttributeMaxDynamicSharedMemorySize, SMEM_GEMM);
    cudaFuncSetAttribute(tc_layer_k,        cudaFuncAttributeMaxDynamicSharedMemorySize, SMEM_LAYER);

    const int GB = V_ / 128;   // 2048 tiles

    split_w_k<<<(WT_TOTAL + 255) / 256, 256>>>(W_emb, W1, W2, W_mlp1);
    tc_gemm_k<384, 0><<<GB + 2048, 288, SMEM_GEMM>>>(x_upd, Zc, Zb, n2g, b_emb,
                                                     W_edge, b_edge, eattr, 0);
    for (int l = 0; l < 4; l++) {
        scatter_k<<<E_ / 8, 256>>>(eidx, eidx + E_);
        tc_layer_k<<<GB, 288, SMEM_LAYER>>>(b1 + (size_t)l * 128, b2 + (size_t)l * 128,
                                            49152 + l * 16384, 114688 + l * 16384,
                                            l < 3 ? 1 : 0);
    }
    tc_gemm_k<192, 3><<<GB, 288, SMEM_GEMM>>>(x_inp, nullptr, nullptr, nullptr,
                                              b_mlp1, W_mlp2, b_mlp2, nullptr, 180224);

    seg_max_k<<<V_ / 256, 256>>>(n2g);
    seg_exp_k<<<V_ / 256, 256>>>(n2g, out);
    seg_div_k<<<V_ / 256, 256>>>(n2g, out);
}